// round 1
// baseline (speedup 1.0000x reference)
#include <cuda_runtime.h>
#include <cuda_bf16.h>
#include <mma.h>
#include <math.h>

using namespace nvcuda;

// Problem dims (fixed)
#define BATCH 16384
#define DIN   2048
#define HEADS 16
#define DHEAD 128
#define DOUT  512

// ---------------- scratch buffers (static device memory, no allocs) ----------
__device__ float g_q   [BATCH * DIN];
__device__ float g_k   [BATCH * DIN];
__device__ float g_v   [BATCH * DIN];
__device__ float g_att [BATCH * DIN];
__device__ float g_op  [BATCH * DIN];
__device__ float g_gt  [BATCH * DIN];
__device__ float g_kv  [HEADS * DHEAD * DHEAD];
__device__ float g_ksum[HEADS * DHEAD];
#define KV_SPLIT 64
__device__ float g_kvpart[KV_SPLIT * HEADS * DHEAD * DHEAD];   // 64 MB
#define KS_SPLIT 32
__device__ float g_ksumpart[KS_SPLIT * DIN];

// ---------------- tf32 wmma GEMM: C[M,N] = A[M,Ktot] @ B[Ktot,N] (+epilogue) --
// A columns < K0 come from A0, >= K0 from A1 (for the concat-gate GEMM).
// MODE 0: C = acc
// MODE 1: C = relu(acc) + 1e-4           (feature map for q,k)
// MODE 2: C = acc + bias[n]
// MODE 3: g = sigmoid(acc + bias[n]); C = g*ep + (1-g)*ex
#define BM 128
#define BN 128
#define BK 32
#define LDA_S 36
#define LDB_S 136
#define LDST  20

template <int MODE>
__global__ void __launch_bounds__(256) gemm_tf32(
    const float* __restrict__ A0, const float* __restrict__ A1,
    int K0, int Ktot,
    const float* __restrict__ B, const float* __restrict__ bias,
    const float* __restrict__ ep, const float* __restrict__ ex,
    float* __restrict__ C, int N)
{
    __shared__ float As[BM][LDA_S];            // 18.4 KB
    __shared__ float Bs[BK][LDB_S];            // 17.4 KB
    __shared__ float stage[8][16][LDST];       // 10.2 KB  (total 46 KB)

    const int bm  = blockIdx.y * BM;
    const int bn  = blockIdx.x * BN;
    const int tid = threadIdx.x;
    const int warp = tid >> 5;
    const int lane = tid & 31;
    const int wm = (warp >> 1) * 32;   // 4 warps along M
    const int wn = (warp & 1) * 64;    // 2 warps along N

    wmma::fragment<wmma::accumulator, 16, 16, 8, float> cfrag[2][4];
#pragma unroll
    for (int i = 0; i < 2; i++)
#pragma unroll
        for (int j = 0; j < 4; j++) wmma::fill_fragment(cfrag[i][j], 0.0f);

    const int nkt = Ktot / BK;
    for (int kt = 0; kt < nkt; kt++) {
        const int kbase = kt * BK;
        const float* Asrc;
        int kcol, lda_g;
        if (kbase < K0) { Asrc = A0; kcol = kbase;      lda_g = K0; }
        else            { Asrc = A1; kcol = kbase - K0; lda_g = Ktot - K0; }

        // load A tile 128x32 (1024 float4)
#pragma unroll
        for (int i = 0; i < 4; i++) {
            int t = tid + i * 256;
            int r = t >> 3;
            int c4 = (t & 7) << 2;
            float4 val = *reinterpret_cast<const float4*>(
                Asrc + (size_t)(bm + r) * lda_g + kcol + c4);
            *reinterpret_cast<float4*>(&As[r][c4]) = val;
        }
        // load B tile 32x128 (1024 float4)
#pragma unroll
        for (int i = 0; i < 4; i++) {
            int t = tid + i * 256;
            int r = t >> 5;
            int c4 = (t & 31) << 2;
            float4 val = *reinterpret_cast<const float4*>(
                B + (size_t)(kbase + r) * N + bn + c4);
            *reinterpret_cast<float4*>(&Bs[r][c4]) = val;
        }
        __syncthreads();

#pragma unroll
        for (int k0 = 0; k0 < BK; k0 += 8) {
            wmma::fragment<wmma::matrix_a, 16, 16, 8, wmma::precision::tf32, wmma::row_major> afrag[2];
            wmma::fragment<wmma::matrix_b, 16, 16, 8, wmma::precision::tf32, wmma::row_major> bfrag[4];
#pragma unroll
            for (int i = 0; i < 2; i++) {
                wmma::load_matrix_sync(afrag[i], &As[wm + 16 * i][k0], LDA_S);
#pragma unroll
                for (int e = 0; e < afrag[i].num_elements; e++)
                    afrag[i].x[e] = wmma::__float_to_tf32(afrag[i].x[e]);
            }
#pragma unroll
            for (int j = 0; j < 4; j++) {
                wmma::load_matrix_sync(bfrag[j], &Bs[k0][wn + 16 * j], LDB_S);
#pragma unroll
                for (int e = 0; e < bfrag[j].num_elements; e++)
                    bfrag[j].x[e] = wmma::__float_to_tf32(bfrag[j].x[e]);
            }
#pragma unroll
            for (int i = 0; i < 2; i++)
#pragma unroll
                for (int j = 0; j < 4; j++)
                    wmma::mma_sync(cfrag[i][j], afrag[i], bfrag[j], cfrag[i][j]);
        }
        __syncthreads();
    }

    // epilogue: stage each 16x16 fragment through smem, apply op, write out
#pragma unroll
    for (int i = 0; i < 2; i++) {
#pragma unroll
        for (int j = 0; j < 4; j++) {
            wmma::store_matrix_sync(&stage[warp][0][0], cfrag[i][j], LDST, wmma::mem_row_major);
            __syncwarp();
            const int gr0 = bm + wm + 16 * i;
            const int gc0 = bn + wn + 16 * j;
#pragma unroll
            for (int qq = 0; qq < 8; qq++) {
                int idx = lane + qq * 32;      // 0..255
                int rr = idx >> 4;
                int cc = idx & 15;
                float acc = stage[warp][rr][cc];
                size_t gi = (size_t)(gr0 + rr) * N + gc0 + cc;
                float o;
                if constexpr (MODE == 0) {
                    o = acc;
                } else if constexpr (MODE == 1) {
                    o = fmaxf(acc, 0.0f) + 1e-4f;
                } else if constexpr (MODE == 2) {
                    o = acc + bias[gc0 + cc];
                } else {
                    float t = acc + bias[gc0 + cc];
                    float g = 1.0f / (1.0f + expf(-t));
                    o = g * ep[gi] + (1.0f - g) * ex[gi];
                }
                C[gi] = o;
            }
            __syncwarp();
        }
    }
}

// ---------------- KV partial reduction: per (head, chunk) block --------------
// kvpart[c][h][d][e] = sum over 256 rows of k[b,h*128+d]*v[b,h*128+e]
__global__ void __launch_bounds__(256) kv_reduce(const float* __restrict__ k,
                                                 const float* __restrict__ v)
{
    const int h = blockIdx.x;
    const int chunk = blockIdx.y;
    const int b0 = chunk * (BATCH / KV_SPLIT);   // 256 rows per chunk
    __shared__ float ks[8][128];
    __shared__ float vs[8][128];
    const int tid = threadIdx.x;
    const int d0 = (tid >> 4) * 8;
    const int e0 = (tid & 15) * 8;
    float acc[8][8] = {};

    for (int bb = 0; bb < (BATCH / KV_SPLIT); bb += 8) {
        {
            int r = tid >> 5;
            int c4 = (tid & 31) << 2;
            *reinterpret_cast<float4*>(&ks[r][c4]) = *reinterpret_cast<const float4*>(
                k + (size_t)(b0 + bb + r) * DIN + h * DHEAD + c4);
            *reinterpret_cast<float4*>(&vs[r][c4]) = *reinterpret_cast<const float4*>(
                v + (size_t)(b0 + bb + r) * DIN + h * DHEAD + c4);
        }
        __syncthreads();
#pragma unroll
        for (int r = 0; r < 8; r++) {
            float kr[8], vr[8];
#pragma unroll
            for (int i = 0; i < 8; i++) { kr[i] = ks[r][d0 + i]; vr[i] = vs[r][e0 + i]; }
#pragma unroll
            for (int i = 0; i < 8; i++)
#pragma unroll
                for (int j = 0; j < 8; j++) acc[i][j] += kr[i] * vr[j];
        }
        __syncthreads();
    }
    float* dst = g_kvpart + (size_t)chunk * (HEADS * DHEAD * DHEAD) + h * DHEAD * DHEAD;
#pragma unroll
    for (int i = 0; i < 8; i++)
#pragma unroll
        for (int j = 0; j < 8; j++) dst[(d0 + i) * DHEAD + e0 + j] = acc[i][j];
}

// ---------------- ksum partials -----------------------------------------------
__global__ void ksum_part(const float* __restrict__ k)
{
    int c = blockIdx.x * 256 + threadIdx.x;         // column 0..2047
    int r0 = blockIdx.y * (BATCH / KS_SPLIT);       // 512 rows
    float s = 0.0f;
    for (int r = 0; r < BATCH / KS_SPLIT; r++) s += k[(size_t)(r0 + r) * DIN + c];
    g_ksumpart[blockIdx.y * DIN + c] = s;
}

// ---------------- final reductions (deterministic) -----------------------------
__global__ void kv_final()
{
    int i = blockIdx.x * 256 + threadIdx.x;         // 0..262143
    float s = 0.0f;
    for (int c = 0; c < KV_SPLIT; c++) s += g_kvpart[(size_t)c * (HEADS * DHEAD * DHEAD) + i];
    g_kv[i] = s;
    if (i < DIN) {
        float t = 0.0f;
        for (int c = 0; c < KS_SPLIT; c++) t += g_ksumpart[c * DIN + i];
        g_ksum[i] = t;
    }
}

// ---------------- attention: att[b,h,:] = (q[b,h,:] @ kv[h]) * z -----------------
// block: 128 b-rows for one head; kv[h] + q rows in smem.
__global__ void __launch_bounds__(256) attn_kernel(const float* __restrict__ q,
                                                   float* __restrict__ att)
{
    extern __shared__ float sm[];
    float* kv_s   = sm;                 // 128*132
    float* q_s    = sm + 128 * 132;     // 128*132
    float* ksum_s = q_s + 128 * 132;    // 128
    float* z_s    = ksum_s + 128;       // 128

    const int h  = blockIdx.y;
    const int b0 = blockIdx.x * 128;
    const int tid = threadIdx.x;

    const float* kvh = g_kv + h * DHEAD * DHEAD;
    for (int i = tid; i < DHEAD * DHEAD; i += 256) {
        int d = i >> 7, e = i & 127;
        kv_s[d * 132 + e] = kvh[i];
    }
    for (int i = tid; i < 128 * 32; i += 256) {   // 128 rows * 32 float4
        int r = i >> 5;
        int c4 = (i & 31) << 2;
        *reinterpret_cast<float4*>(&q_s[r * 132 + c4]) =
            *reinterpret_cast<const float4*>(q + (size_t)(b0 + r) * DIN + h * DHEAD + c4);
    }
    if (tid < 128) ksum_s[tid] = g_ksum[h * DHEAD + tid];
    __syncthreads();

    // z per row (2 threads/row, 64 d each, shfl-pair reduce)
    {
        int r = tid >> 1, half = tid & 1;
        float s = 0.0f;
        int dbase = half * 64;
        for (int d = 0; d < 64; d++) s += q_s[r * 132 + dbase + d] * ksum_s[dbase + d];
        s += __shfl_xor_sync(0xffffffffu, s, 1);
        if (half == 0) z_s[r] = 1.0f / (s + 1e-6f);
    }
    __syncthreads();

    // main: each thread computes 4 rows x 16 cols
    const int rg = tid >> 3;            // 0..31
    const int e0 = (tid & 7) * 16;
    float acc[4][16] = {};
    for (int d = 0; d < 128; d++) {
        float kvrow[16];
#pragma unroll
        for (int j = 0; j < 16; j += 4) {
            float4 f = *reinterpret_cast<float4*>(&kv_s[d * 132 + e0 + j]);
            kvrow[j] = f.x; kvrow[j + 1] = f.y; kvrow[j + 2] = f.z; kvrow[j + 3] = f.w;
        }
#pragma unroll
        for (int rr = 0; rr < 4; rr++) {
            float qd = q_s[(rg + rr * 32) * 132 + d];
#pragma unroll
            for (int j = 0; j < 16; j++) acc[rr][j] += qd * kvrow[j];
        }
    }
#pragma unroll
    for (int rr = 0; rr < 4; rr++) {
        int r = rg + rr * 32;
        float z = z_s[r];
#pragma unroll
        for (int j = 0; j < 16; j++)
            att[(size_t)(b0 + r) * DIN + h * DHEAD + e0 + j] = acc[rr][j] * z;
    }
}

// ---------------- launch ------------------------------------------------------
extern "C" void kernel_launch(void* const* d_in, const int* in_sizes, int n_in,
                              void* d_out, int out_size)
{
    const float* x    = (const float*)d_in[0];
    const float* Wq   = (const float*)d_in[1];
    const float* Wk   = (const float*)d_in[2];
    const float* Wv   = (const float*)d_in[3];
    const float* Wo   = (const float*)d_in[4];
    const float* bo   = (const float*)d_in[5];
    const float* Wg   = (const float*)d_in[6];
    const float* bg   = (const float*)d_in[7];
    const float* Wout = (const float*)d_in[8];
    const float* bout = (const float*)d_in[9];
    float* out = (float*)d_out;

    float *q_, *k_, *v_, *att_, *op_, *gt_;
    cudaGetSymbolAddress((void**)&q_,   g_q);
    cudaGetSymbolAddress((void**)&k_,   g_k);
    cudaGetSymbolAddress((void**)&v_,   g_v);
    cudaGetSymbolAddress((void**)&att_, g_att);
    cudaGetSymbolAddress((void**)&op_,  g_op);
    cudaGetSymbolAddress((void**)&gt_,  g_gt);

    const dim3 blk(256);
    const dim3 grid2048(DIN / BN, BATCH / BM);   // (16, 128)
    const dim3 grid512(DOUT / BN, BATCH / BM);   // (4, 128)

    // 1-3: Q = feat(x@Wq), K = feat(x@Wk), V = x@Wv
    gemm_tf32<1><<<grid2048, blk>>>(x, x, DIN, DIN, Wq, nullptr, nullptr, nullptr, q_, DIN);
    gemm_tf32<1><<<grid2048, blk>>>(x, x, DIN, DIN, Wk, nullptr, nullptr, nullptr, k_, DIN);
    gemm_tf32<0><<<grid2048, blk>>>(x, x, DIN, DIN, Wv, nullptr, nullptr, nullptr, v_, DIN);

    // 4-6: kv = sum_b k^T v per head; ksum = sum_b k (two-stage, deterministic)
    kv_reduce<<<dim3(HEADS, KV_SPLIT), blk>>>(k_, v_);
    ksum_part<<<dim3(DIN / 256, KS_SPLIT), blk>>>(k_);
    kv_final<<<dim3((HEADS * DHEAD * DHEAD) / 256), blk>>>();

    // 7: attention
    size_t attn_smem = (size_t)(128 * 132 * 2 + 256) * sizeof(float);
    cudaFuncSetAttribute(attn_kernel, cudaFuncAttributeMaxDynamicSharedMemorySize,
                         (int)attn_smem);
    attn_kernel<<<dim3(BATCH / 128, HEADS), blk, attn_smem>>>(q_, att_);

    // 8: out_proj = att @ Wo + bo
    gemm_tf32<2><<<grid2048, blk>>>(att_, att_, DIN, DIN, Wo, bo, nullptr, nullptr, op_, DIN);

    // 9: gated = sigmoid([op|x] @ Wg + bg) blend of op and x  (split-K concat)
    gemm_tf32<3><<<grid2048, blk>>>(op_, x, DIN, 2 * DIN, Wg, bg, op_, x, gt_, DIN);

    // 10: out = gated @ Wout + bout
    gemm_tf32<2><<<grid512, blk>>>(gt_, gt_, DIN, DIN, Wout, bout, nullptr, nullptr, out, DOUT);
}

// round 3
// speedup vs baseline: 2.1528x; 2.1528x over previous
#include <cuda_runtime.h>
#include <cuda_bf16.h>
#include <math.h>
#include <stdint.h>

// ---------------- problem dims (fixed) ----------------------------------------
#define BATCH 16384
#define DIN   2048
#define HEADS 16
#define DHEAD 128
#define DOUT  512

// ---------------- scratch (static device memory) ------------------------------
__device__ float g_xr   [BATCH * DIN];          // tf32-rounded x
__device__ float g_q    [BATCH * DIN];
__device__ float g_k    [BATCH * DIN];
__device__ float g_v    [BATCH * DIN];
__device__ float g_att  [BATCH * DIN];          // tf32-rounded at write
__device__ float g_op   [BATCH * DIN];          // exact
__device__ float g_opr  [BATCH * DIN];          // tf32-rounded copy
__device__ float g_gt   [BATCH * DIN];          // tf32-rounded at write
__device__ float g_kv   [HEADS * DHEAD * DHEAD];
__device__ float g_ksum [HEADS * DHEAD];
#define KV_SPLIT 64
__device__ float g_kvpart[KV_SPLIT * HEADS * DHEAD * DHEAD];
#define KS_SPLIT 32
__device__ float g_ksumpart[KS_SPLIT * DIN];
// tf32-rounded weights (same layout as inputs; B[k][n] row-major)
__device__ float g_wq  [DIN * DIN];
__device__ float g_wk  [DIN * DIN];
__device__ float g_wv  [DIN * DIN];
__device__ float g_wo  [DIN * DIN];
__device__ float g_wg  [2 * DIN * DIN];
__device__ float g_wout[DIN * DOUT];

// ---------------- helpers -------------------------------------------------------
__device__ __forceinline__ uint32_t smem_u32(const void* p) {
    uint32_t a;
    asm("{ .reg .u64 t; cvta.to.shared.u64 t, %1; cvt.u32.u64 %0, t; }" : "=r"(a) : "l"(p));
    return a;
}
__device__ __forceinline__ float rtf32(float x) {
    float r; asm("cvt.rna.tf32.f32 %0, %1;" : "=f"(r) : "f"(x)); return r;
}
__device__ __forceinline__ void cp16(uint32_t dst, const void* src) {
    asm volatile("cp.async.cg.shared.global [%0], [%1], 16;" :: "r"(dst), "l"(src));
}
#define CP_COMMIT() asm volatile("cp.async.commit_group;" ::: "memory")
#define CP_WAIT(n)  asm volatile("cp.async.wait_group %0;" :: "n"(n) : "memory")

#define MMA_TF32(d, A4, B2) \
    asm volatile("mma.sync.aligned.m16n8k8.row.col.f32.tf32.tf32.f32 " \
        "{%0,%1,%2,%3},{%4,%5,%6,%7},{%8,%9},{%0,%1,%2,%3};" \
        : "+f"((d)[0]), "+f"((d)[1]), "+f"((d)[2]), "+f"((d)[3]) \
        : "r"((A4)[0]), "r"((A4)[1]), "r"((A4)[2]), "r"((A4)[3]), \
          "r"((B2)[0]), "r"((B2)[1]))

// ---------------- GEMM config ----------------------------------------------------
#define BM 128
#define BN 128
#define BK 32
#define STAGES 4
#define AP 36        // A smem row pad (floats): bank = (m*4+k)%32, conflict-free
#define BP 136       // B smem row pad (floats): bank = (k*8+n)%32, conflict-free
#define ASTG (BM * AP)             // 4608 floats / stage
#define BSTG (BK * BP)             // 4352 floats / stage
#define GEMM_SMEM (STAGES * (ASTG + BSTG) * 4)   // 143360 bytes

// MODE 0: C=acc   1: C=relu(acc)+1e-4   2: C=acc+bias
// MODE 3: g=sigmoid(acc+bias); C=rtf32(g*ep+(1-g)*ex)
// MODE 4: o=acc+bias; C=o; C2=rtf32(o)
template <int MODE>
__global__ void __launch_bounds__(256, 1) gemm_mma(
    const float* __restrict__ A0, const float* __restrict__ A1, int K0, int nkt,
    const float* __restrict__ B, const float* __restrict__ bias,
    const float* __restrict__ ep, const float* __restrict__ ex,
    float* __restrict__ C, float* __restrict__ C2, int N)
{
    extern __shared__ float sm[];
    float* As = sm;
    float* Bs = sm + STAGES * ASTG;
    const uint32_t asu = smem_u32(As);
    const uint32_t bsu = smem_u32(Bs);

    const int tid  = threadIdx.x;
    const int bm   = blockIdx.y * BM;
    const int bn   = blockIdx.x * BN;
    const int wid  = tid >> 5, lane = tid & 31;
    const int wm   = (wid >> 2) * 64;      // warp grid 2 (M) x 4 (N)
    const int wn   = (wid & 3) * 32;
    const int lr   = lane >> 2;            // 0..7
    const int lc   = lane & 3;             // 0..3

    float acc[4][4][4];
#pragma unroll
    for (int mt = 0; mt < 4; mt++)
#pragma unroll
        for (int nt = 0; nt < 4; nt++)
#pragma unroll
            for (int e = 0; e < 4; e++) acc[mt][nt][e] = 0.0f;

    auto issue = [&](int kt) {
        const int s = kt % STAGES;
        const int kbase = kt * BK;
        const float* Aptr;
        int kc;
        if (kbase < K0) { Aptr = A0; kc = kbase; }
        else            { Aptr = A1; kc = kbase - K0; }
#pragma unroll
        for (int i = 0; i < 4; i++) {            // A tile 128x32
            int idx = tid + i * 256;
            int r = idx >> 3, c4 = (idx & 7) << 2;
            uint32_t dst = asu + (uint32_t)(s * ASTG + r * AP + c4) * 4u;
            cp16(dst, Aptr + (size_t)(bm + r) * DIN + kc + c4);
        }
#pragma unroll
        for (int i = 0; i < 4; i++) {            // B tile 32x128
            int idx = tid + i * 256;
            int r = idx >> 5, c4 = (idx & 31) << 2;
            uint32_t dst = bsu + (uint32_t)(s * BSTG + r * BP + c4) * 4u;
            cp16(dst, B + (size_t)(kbase + r) * N + bn + c4);
        }
    };

    // prologue: STAGES-1 stages in flight
#pragma unroll
    for (int kt = 0; kt < STAGES - 1; kt++) {
        if (kt < nkt) issue(kt);
        CP_COMMIT();
    }

    uint32_t a[2][4][4], b[2][4][2];

    for (int kt = 0; kt < nkt; kt++) {
        CP_WAIT(STAGES - 2);
        __syncthreads();

        if (kt + STAGES - 1 < nkt) issue(kt + STAGES - 1);
        CP_COMMIT();

        const int s = kt % STAGES;
        const float* as = As + s * ASTG;
        const float* bs = Bs + s * BSTG;

        // load kk=0 fragments
#pragma unroll
        for (int mt = 0; mt < 4; mt++) {
            const int r = wm + mt * 16 + lr;
            a[0][mt][0] = __float_as_uint(as[r * AP + lc]);
            a[0][mt][1] = __float_as_uint(as[(r + 8) * AP + lc]);
            a[0][mt][2] = __float_as_uint(as[r * AP + lc + 4]);
            a[0][mt][3] = __float_as_uint(as[(r + 8) * AP + lc + 4]);
        }
#pragma unroll
        for (int nt = 0; nt < 4; nt++) {
            const int c = wn + nt * 8 + lr;
            b[0][nt][0] = __float_as_uint(bs[lc * BP + c]);
            b[0][nt][1] = __float_as_uint(bs[(lc + 4) * BP + c]);
        }

#pragma unroll
        for (int kk = 0; kk < 4; kk++) {
            const int cur = kk & 1, nxt = cur ^ 1;
            if (kk < 3) {
                const int kcol = (kk + 1) * 8 + lc;
#pragma unroll
                for (int mt = 0; mt < 4; mt++) {
                    const int r = wm + mt * 16 + lr;
                    a[nxt][mt][0] = __float_as_uint(as[r * AP + kcol]);
                    a[nxt][mt][1] = __float_as_uint(as[(r + 8) * AP + kcol]);
                    a[nxt][mt][2] = __float_as_uint(as[r * AP + kcol + 4]);
                    a[nxt][mt][3] = __float_as_uint(as[(r + 8) * AP + kcol + 4]);
                }
#pragma unroll
                for (int nt = 0; nt < 4; nt++) {
                    const int c = wn + nt * 8 + lr;
                    b[nxt][nt][0] = __float_as_uint(bs[kcol * BP + c]);
                    b[nxt][nt][1] = __float_as_uint(bs[(kcol + 4) * BP + c]);
                }
            }
#pragma unroll
            for (int mt = 0; mt < 4; mt++)
#pragma unroll
                for (int nt = 0; nt < 4; nt++)
                    MMA_TF32(acc[mt][nt], a[cur][mt], b[cur][nt]);
        }
    }

    // ---- epilogue: direct register writes ----
#pragma unroll
    for (int mt = 0; mt < 4; mt++) {
#pragma unroll
        for (int nt = 0; nt < 4; nt++) {
#pragma unroll
            for (int h = 0; h < 2; h++) {
                const int gr = bm + wm + mt * 16 + lr + h * 8;
                const int gc = bn + wn + nt * 8 + 2 * lc;
                const size_t gi = (size_t)gr * N + gc;
                float v0 = acc[mt][nt][h * 2 + 0];
                float v1 = acc[mt][nt][h * 2 + 1];
                if constexpr (MODE == 1) {
                    v0 = fmaxf(v0, 0.f) + 1e-4f;
                    v1 = fmaxf(v1, 0.f) + 1e-4f;
                } else if constexpr (MODE == 2 || MODE == 4) {
                    v0 += bias[gc]; v1 += bias[gc + 1];
                } else if constexpr (MODE == 3) {
                    v0 += bias[gc]; v1 += bias[gc + 1];
                    const float g0 = 1.f / (1.f + expf(-v0));
                    const float g1 = 1.f / (1.f + expf(-v1));
                    const float2 e2 = *(const float2*)&ep[gi];
                    const float2 x2 = *(const float2*)&ex[gi];
                    v0 = rtf32(g0 * e2.x + (1.f - g0) * x2.x);
                    v1 = rtf32(g1 * e2.y + (1.f - g1) * x2.y);
                }
                *(float2*)&C[gi] = make_float2(v0, v1);
                if constexpr (MODE == 4)
                    *(float2*)&C2[gi] = make_float2(rtf32(v0), rtf32(v1));
            }
        }
    }
}

// ---------------- round-to-tf32 copy ---------------------------------------------
__global__ void round_copy(const float4* __restrict__ s, float4* __restrict__ d)
{
    const int i = blockIdx.x * 256 + threadIdx.x;
    float4 v = s[i];
    v.x = rtf32(v.x); v.y = rtf32(v.y); v.z = rtf32(v.z); v.w = rtf32(v.w);
    d[i] = v;
}

// ---------------- KV partial reduction (fp32, near roofline) ---------------------
__global__ void __launch_bounds__(256) kv_reduce(const float* __restrict__ k,
                                                 const float* __restrict__ v)
{
    const int h = blockIdx.x;
    const int chunk = blockIdx.y;
    const int b0 = chunk * (BATCH / KV_SPLIT);
    __shared__ float ks[8][128];
    __shared__ float vs[8][128];
    const int tid = threadIdx.x;
    const int d0 = (tid >> 4) * 8;
    const int e0 = (tid & 15) * 8;
    float acc[8][8] = {};

    for (int bb = 0; bb < (BATCH / KV_SPLIT); bb += 8) {
        {
            int r = tid >> 5;
            int c4 = (tid & 31) << 2;
            *reinterpret_cast<float4*>(&ks[r][c4]) = *reinterpret_cast<const float4*>(
                k + (size_t)(b0 + bb + r) * DIN + h * DHEAD + c4);
            *reinterpret_cast<float4*>(&vs[r][c4]) = *reinterpret_cast<const float4*>(
                v + (size_t)(b0 + bb + r) * DIN + h * DHEAD + c4);
        }
        __syncthreads();
#pragma unroll
        for (int r = 0; r < 8; r++) {
            float kr[8], vr[8];
#pragma unroll
            for (int i = 0; i < 8; i++) { kr[i] = ks[r][d0 + i]; vr[i] = vs[r][e0 + i]; }
#pragma unroll
            for (int i = 0; i < 8; i++)
#pragma unroll
                for (int j = 0; j < 8; j++) acc[i][j] += kr[i] * vr[j];
        }
        __syncthreads();
    }
    float* dst = g_kvpart + (size_t)chunk * (HEADS * DHEAD * DHEAD) + h * DHEAD * DHEAD;
#pragma unroll
    for (int i = 0; i < 8; i++)
#pragma unroll
        for (int j = 0; j < 8; j++) dst[(d0 + i) * DHEAD + e0 + j] = acc[i][j];
}

__global__ void ksum_part(const float* __restrict__ k)
{
    int c = blockIdx.x * 256 + threadIdx.x;
    int r0 = blockIdx.y * (BATCH / KS_SPLIT);
    float s = 0.0f;
    for (int r = 0; r < BATCH / KS_SPLIT; r++) s += k[(size_t)(r0 + r) * DIN + c];
    g_ksumpart[blockIdx.y * DIN + c] = s;
}

__global__ void kv_final()
{
    int i = blockIdx.x * 256 + threadIdx.x;
    float s = 0.0f;
    for (int c = 0; c < KV_SPLIT; c++) s += g_kvpart[(size_t)c * (HEADS * DHEAD * DHEAD) + i];
    g_kv[i] = s;
    if (i < DIN) {
        float t = 0.0f;
        for (int c = 0; c < KS_SPLIT; c++) t += g_ksumpart[c * DIN + i];
        g_ksum[i] = t;
    }
}

// ---------------- attention (fp32 compute; tf32-rounded output) ------------------
__global__ void __launch_bounds__(256) attn_kernel(const float* __restrict__ q,
                                                   float* __restrict__ att)
{
    extern __shared__ float smx[];
    float* kv_s   = smx;
    float* q_s    = smx + 128 * 132;
    float* ksum_s = q_s + 128 * 132;
    float* z_s    = ksum_s + 128;

    const int h  = blockIdx.y;
    const int b0 = blockIdx.x * 128;
    const int tid = threadIdx.x;

    const float* kvh = g_kv + h * DHEAD * DHEAD;
    for (int i = tid; i < DHEAD * DHEAD; i += 256) {
        int d = i >> 7, e = i & 127;
        kv_s[d * 132 + e] = kvh[i];
    }
    for (int i = tid; i < 128 * 32; i += 256) {
        int r = i >> 5;
        int c4 = (i & 31) << 2;
        *reinterpret_cast<float4*>(&q_s[r * 132 + c4]) =
            *reinterpret_cast<const float4*>(q + (size_t)(b0 + r) * DIN + h * DHEAD + c4);
    }
    if (tid < 128) ksum_s[tid] = g_ksum[h * DHEAD + tid];
    __syncthreads();

    {
        int r = tid >> 1, half = tid & 1;
        float s = 0.0f;
        int dbase = half * 64;
        for (int d = 0; d < 64; d++) s += q_s[r * 132 + dbase + d] * ksum_s[dbase + d];
        s += __shfl_xor_sync(0xffffffffu, s, 1);
        if (half == 0) z_s[r] = 1.0f / (s + 1e-6f);
    }
    __syncthreads();

    const int rg = tid >> 3;
    const int e0 = (tid & 7) * 16;
    float acc[4][16] = {};
    for (int d = 0; d < 128; d++) {
        float kvrow[16];
#pragma unroll
        for (int j = 0; j < 16; j += 4) {
            float4 f = *reinterpret_cast<float4*>(&kv_s[d * 132 + e0 + j]);
            kvrow[j] = f.x; kvrow[j + 1] = f.y; kvrow[j + 2] = f.z; kvrow[j + 3] = f.w;
        }
#pragma unroll
        for (int rr = 0; rr < 4; rr++) {
            float qd = q_s[(rg + rr * 32) * 132 + d];
#pragma unroll
            for (int j = 0; j < 16; j++) acc[rr][j] += qd * kvrow[j];
        }
    }
#pragma unroll
    for (int rr = 0; rr < 4; rr++) {
        int r = rg + rr * 32;
        float z = z_s[r];
#pragma unroll
        for (int j = 0; j < 16; j++)
            att[(size_t)(b0 + r) * DIN + h * DHEAD + e0 + j] = rtf32(acc[rr][j] * z);
    }
}

// ---------------- launch -----------------------------------------------------------
extern "C" void kernel_launch(void* const* d_in, const int* in_sizes, int n_in,
                              void* d_out, int out_size)
{
    const float* x    = (const float*)d_in[0];
    const float* Wq   = (const float*)d_in[1];
    const float* Wk   = (const float*)d_in[2];
    const float* Wv   = (const float*)d_in[3];
    const float* Wo   = (const float*)d_in[4];
    const float* bo   = (const float*)d_in[5];
    const float* Wg   = (const float*)d_in[6];
    const float* bg   = (const float*)d_in[7];
    const float* Wout = (const float*)d_in[8];
    const float* bout = (const float*)d_in[9];
    float* out = (float*)d_out;

    float *xr_, *q_, *k_, *v_, *att_, *op_, *opr_, *gt_;
    float *wq_, *wk_, *wv_, *wo_, *wg_, *wout_;
    cudaGetSymbolAddress((void**)&xr_,  g_xr);
    cudaGetSymbolAddress((void**)&q_,   g_q);
    cudaGetSymbolAddress((void**)&k_,   g_k);
    cudaGetSymbolAddress((void**)&v_,   g_v);
    cudaGetSymbolAddress((void**)&att_, g_att);
    cudaGetSymbolAddress((void**)&op_,  g_op);
    cudaGetSymbolAddress((void**)&opr_, g_opr);
    cudaGetSymbolAddress((void**)&gt_,  g_gt);
    cudaGetSymbolAddress((void**)&wq_,  g_wq);
    cudaGetSymbolAddress((void**)&wk_,  g_wk);
    cudaGetSymbolAddress((void**)&wv_,  g_wv);
    cudaGetSymbolAddress((void**)&wo_,  g_wo);
    cudaGetSymbolAddress((void**)&wg_,  g_wg);
    cudaGetSymbolAddress((void**)&wout_,g_wout);

    cudaFuncSetAttribute(gemm_mma<0>, cudaFuncAttributeMaxDynamicSharedMemorySize, GEMM_SMEM);
    cudaFuncSetAttribute(gemm_mma<1>, cudaFuncAttributeMaxDynamicSharedMemorySize, GEMM_SMEM);
    cudaFuncSetAttribute(gemm_mma<2>, cudaFuncAttributeMaxDynamicSharedMemorySize, GEMM_SMEM);
    cudaFuncSetAttribute(gemm_mma<3>, cudaFuncAttributeMaxDynamicSharedMemorySize, GEMM_SMEM);
    cudaFuncSetAttribute(gemm_mma<4>, cudaFuncAttributeMaxDynamicSharedMemorySize, GEMM_SMEM);

    const dim3 blk(256);
    const dim3 gN2048(DIN / BN, BATCH / BM);   // (16, 128)
    const dim3 gN512(DOUT / BN, BATCH / BM);   // (4, 128)

    // 0) tf32-RN-rounded operand copies (removes HMMA truncation bias)
    round_copy<<<(BATCH * DIN) / 1024, 256>>>((const float4*)x, (float4*)xr_);
    round_copy<<<(DIN * DIN) / 1024, 256>>>((const float4*)Wq, (float4*)wq_);
    round_copy<<<(DIN * DIN) / 1024, 256>>>((const float4*)Wk, (float4*)wk_);
    round_copy<<<(DIN * DIN) / 1024, 256>>>((const float4*)Wv, (float4*)wv_);
    round_copy<<<(DIN * DIN) / 1024, 256>>>((const float4*)Wo, (float4*)wo_);
    round_copy<<<(2 * DIN * DIN) / 1024, 256>>>((const float4*)Wg, (float4*)wg_);
    round_copy<<<(DIN * DOUT) / 1024, 256>>>((const float4*)Wout, (float4*)wout_);

    // 1-3) Q = feat(xr@Wq), K = feat(xr@Wk), V = xr@Wv
    gemm_mma<1><<<gN2048, blk, GEMM_SMEM>>>(xr_, xr_, DIN, DIN / BK, wq_,
                                            nullptr, nullptr, nullptr, q_, nullptr, DIN);
    gemm_mma<1><<<gN2048, blk, GEMM_SMEM>>>(xr_, xr_, DIN, DIN / BK, wk_,
                                            nullptr, nullptr, nullptr, k_, nullptr, DIN);
    gemm_mma<0><<<gN2048, blk, GEMM_SMEM>>>(xr_, xr_, DIN, DIN / BK, wv_,
                                            nullptr, nullptr, nullptr, v_, nullptr, DIN);

    // 4-6) kv / ksum reductions (deterministic two-stage, fp32)
    kv_reduce<<<dim3(HEADS, KV_SPLIT), 256>>>(k_, v_);
    ksum_part<<<dim3(DIN / 256, KS_SPLIT), 256>>>(k_);
    kv_final<<<dim3((HEADS * DHEAD * DHEAD) / 256), 256>>>();

    // 7) attention (tf32-rounded output feeds Wo GEMM)
    size_t attn_smem = (size_t)(128 * 132 * 2 + 256) * sizeof(float);
    cudaFuncSetAttribute(attn_kernel, cudaFuncAttributeMaxDynamicSharedMemorySize,
                         (int)attn_smem);
    attn_kernel<<<dim3(BATCH / 128, HEADS), 256, attn_smem>>>(q_, att_);

    // 8) out_proj = att @ Wo + bo  (exact -> op, tf32-rounded -> opr)
    gemm_mma<4><<<gN2048, blk, GEMM_SMEM>>>(att_, att_, DIN, DIN / BK, wo_,
                                            bo, nullptr, nullptr, op_, opr_, DIN);

    // 9) gate GEMM over concat [opr | xr]; blend with exact op / x
    gemm_mma<3><<<gN2048, blk, GEMM_SMEM>>>(opr_, xr_, DIN, (2 * DIN) / BK, wg_,
                                            bg, op_, x, gt_, nullptr, DIN);

    // 10) out = gt @ Wout + bout
    gemm_mma<2><<<gN512, blk, GEMM_SMEM>>>(gt_, gt_, DIN, DIN / BK, wout_,
                                           bout, nullptr, nullptr, out, nullptr, DOUT);
}

// round 4
// speedup vs baseline: 2.4923x; 1.1577x over previous
#include <cuda_runtime.h>
#include <cuda_bf16.h>
#include <math.h>
#include <stdint.h>

// ---------------- problem dims (fixed) ----------------------------------------
#define BATCH 16384
#define DIN   2048
#define HEADS 16
#define DHEAD 128
#define DOUT  512

// ---------------- scratch (static device memory) ------------------------------
__device__ float g_xr   [BATCH * DIN];          // tf32-rounded x
__device__ float g_q    [BATCH * DIN];
__device__ float g_k    [BATCH * DIN];
__device__ float g_v    [BATCH * DIN];
__device__ float g_att  [BATCH * DIN];          // tf32-rounded at write
__device__ float g_op   [BATCH * DIN];          // exact
__device__ float g_opr  [BATCH * DIN];          // tf32-rounded copy
__device__ float g_gt   [BATCH * DIN];          // tf32-rounded at write
__device__ float g_kv   [HEADS * DHEAD * DHEAD];
__device__ float g_ksum [HEADS * DHEAD];
#define KV_SPLIT 64
__device__ float g_kvpart[KV_SPLIT * HEADS * DHEAD * DHEAD];
#define KS_SPLIT 32
__device__ float g_ksumpart[KS_SPLIT * DIN];
// tf32-rounded weights (same layout as inputs; B[k][n] row-major)
__device__ float g_wq  [DIN * DIN];
__device__ float g_wk  [DIN * DIN];
__device__ float g_wv  [DIN * DIN];
__device__ float g_wo  [DIN * DIN];
__device__ float g_wg  [2 * DIN * DIN];
__device__ float g_wout[DIN * DOUT];

// ---------------- helpers -------------------------------------------------------
__device__ __forceinline__ uint32_t smem_u32(const void* p) {
    uint32_t a;
    asm("{ .reg .u64 t; cvta.to.shared.u64 t, %1; cvt.u32.u64 %0, t; }" : "=r"(a) : "l"(p));
    return a;
}
__device__ __forceinline__ float rtf32(float x) {
    float r; asm("cvt.rna.tf32.f32 %0, %1;" : "=f"(r) : "f"(x)); return r;
}
__device__ __forceinline__ void cp16(uint32_t dst, const void* src) {
    asm volatile("cp.async.cg.shared.global [%0], [%1], 16;" :: "r"(dst), "l"(src));
}
#define CP_COMMIT() asm volatile("cp.async.commit_group;" ::: "memory")
#define CP_WAIT(n)  asm volatile("cp.async.wait_group %0;" :: "n"(n) : "memory")

#define MMA_TF32(d, A4, B2) \
    asm volatile("mma.sync.aligned.m16n8k8.row.col.f32.tf32.tf32.f32 " \
        "{%0,%1,%2,%3},{%4,%5,%6,%7},{%8,%9},{%0,%1,%2,%3};" \
        : "+f"((d)[0]), "+f"((d)[1]), "+f"((d)[2]), "+f"((d)[3]) \
        : "r"((A4)[0]), "r"((A4)[1]), "r"((A4)[2]), "r"((A4)[3]), \
          "r"((B2)[0]), "r"((B2)[1]))

// ---------------- GEMM config ----------------------------------------------------
// block 128x256, 8 warps (2 M x 4 N), warp tile 64x64 -> LDS:MMA = 1:1
#define BM 128
#define BN 256
#define BK 32
#define STAGES 4
#define AP 36        // A smem row pad: bank = (r*4+k)%32 conflict-free
#define BP 264       // B smem row pad: 264%32=8 -> bank = (k*8+n)%32 conflict-free
#define ASTG (BM * AP)             // 4608 floats / stage
#define BSTG (BK * BP)             // 8448 floats / stage
#define GEMM_SMEM (STAGES * (ASTG + BSTG) * 4)   // 208896 bytes

// MODE 0: C=acc   1: C=relu(acc)+1e-4   2: C=acc+bias
// MODE 3: g=sigmoid(acc+bias); C=rtf32(g*ep+(1-g)*ex)
// MODE 4: o=acc+bias; C=o; C2=rtf32(o)
template <int MODE>
__global__ void __launch_bounds__(256, 1) gemm_mma(
    const float* __restrict__ A0, const float* __restrict__ A1, int K0, int nkt,
    const float* __restrict__ B, const float* __restrict__ bias,
    const float* __restrict__ ep, const float* __restrict__ ex,
    float* __restrict__ C, float* __restrict__ C2, int N)
{
    extern __shared__ float sm[];
    float* As = sm;
    float* Bs = sm + STAGES * ASTG;
    const uint32_t asu = smem_u32(As);
    const uint32_t bsu = smem_u32(Bs);

    const int tid  = threadIdx.x;
    const int bm   = blockIdx.y * BM;
    const int bn   = blockIdx.x * BN;
    const int wid  = tid >> 5, lane = tid & 31;
    const int wm   = (wid >> 2) * 64;      // warp grid 2 (M) x 4 (N)
    const int wn   = (wid & 3) * 64;
    const int lr   = lane >> 2;            // 0..7
    const int lc   = lane & 3;             // 0..3

    float acc[4][8][4];
#pragma unroll
    for (int mt = 0; mt < 4; mt++)
#pragma unroll
        for (int nt = 0; nt < 8; nt++)
#pragma unroll
            for (int e = 0; e < 4; e++) acc[mt][nt][e] = 0.0f;

    auto issue = [&](int kt) {
        const int s = kt % STAGES;
        const int kbase = kt * BK;
        const float* Aptr;
        int kc;
        if (kbase < K0) { Aptr = A0; kc = kbase; }
        else            { Aptr = A1; kc = kbase - K0; }
#pragma unroll
        for (int i = 0; i < 4; i++) {            // A tile 128x32 (1024 float4)
            int idx = tid + i * 256;
            int r = idx >> 3, c4 = (idx & 7) << 2;
            uint32_t dst = asu + (uint32_t)(s * ASTG + r * AP + c4) * 4u;
            cp16(dst, Aptr + (size_t)(bm + r) * DIN + kc + c4);
        }
#pragma unroll
        for (int i = 0; i < 8; i++) {            // B tile 32x256 (2048 float4)
            int idx = tid + i * 256;
            int r = idx >> 6, c4 = (idx & 63) << 2;
            uint32_t dst = bsu + (uint32_t)(s * BSTG + r * BP + c4) * 4u;
            cp16(dst, B + (size_t)(kbase + r) * N + bn + c4);
        }
    };

    // prologue: STAGES-1 stages in flight
#pragma unroll
    for (int kt = 0; kt < STAGES - 1; kt++) {
        if (kt < nkt) issue(kt);
        CP_COMMIT();
    }

    uint32_t a[2][4][4], b[2][8][2];

    for (int kt = 0; kt < nkt; kt++) {
        CP_WAIT(STAGES - 2);
        __syncthreads();

        if (kt + STAGES - 1 < nkt) issue(kt + STAGES - 1);
        CP_COMMIT();

        const int s = kt % STAGES;
        const float* as = As + s * ASTG;
        const float* bs = Bs + s * BSTG;

        // load kk=0 fragments
#pragma unroll
        for (int mt = 0; mt < 4; mt++) {
            const int r = wm + mt * 16 + lr;
            a[0][mt][0] = __float_as_uint(as[r * AP + lc]);
            a[0][mt][1] = __float_as_uint(as[(r + 8) * AP + lc]);
            a[0][mt][2] = __float_as_uint(as[r * AP + lc + 4]);
            a[0][mt][3] = __float_as_uint(as[(r + 8) * AP + lc + 4]);
        }
#pragma unroll
        for (int nt = 0; nt < 8; nt++) {
            const int c = wn + nt * 8 + lr;
            b[0][nt][0] = __float_as_uint(bs[lc * BP + c]);
            b[0][nt][1] = __float_as_uint(bs[(lc + 4) * BP + c]);
        }

#pragma unroll
        for (int kk = 0; kk < 4; kk++) {
            const int cur = kk & 1, nxt = cur ^ 1;
            if (kk < 3) {
                const int kcol = (kk + 1) * 8 + lc;
#pragma unroll
                for (int mt = 0; mt < 4; mt++) {
                    const int r = wm + mt * 16 + lr;
                    a[nxt][mt][0] = __float_as_uint(as[r * AP + kcol]);
                    a[nxt][mt][1] = __float_as_uint(as[(r + 8) * AP + kcol]);
                    a[nxt][mt][2] = __float_as_uint(as[r * AP + kcol + 4]);
                    a[nxt][mt][3] = __float_as_uint(as[(r + 8) * AP + kcol + 4]);
                }
#pragma unroll
                for (int nt = 0; nt < 8; nt++) {
                    const int c = wn + nt * 8 + lr;
                    b[nxt][nt][0] = __float_as_uint(bs[kcol * BP + c]);
                    b[nxt][nt][1] = __float_as_uint(bs[(kcol + 4) * BP + c]);
                }
            }
#pragma unroll
            for (int mt = 0; mt < 4; mt++)
#pragma unroll
                for (int nt = 0; nt < 8; nt++)
                    MMA_TF32(acc[mt][nt], a[cur][mt], b[cur][nt]);
        }
    }

    // ---- epilogue: direct register writes ----
#pragma unroll
    for (int mt = 0; mt < 4; mt++) {
#pragma unroll
        for (int nt = 0; nt < 8; nt++) {
#pragma unroll
            for (int h = 0; h < 2; h++) {
                const int gr = bm + wm + mt * 16 + lr + h * 8;
                const int gc = bn + wn + nt * 8 + 2 * lc;
                const size_t gi = (size_t)gr * N + gc;
                float v0 = acc[mt][nt][h * 2 + 0];
                float v1 = acc[mt][nt][h * 2 + 1];
                if constexpr (MODE == 1) {
                    v0 = fmaxf(v0, 0.f) + 1e-4f;
                    v1 = fmaxf(v1, 0.f) + 1e-4f;
                } else if constexpr (MODE == 2 || MODE == 4) {
                    v0 += bias[gc]; v1 += bias[gc + 1];
                } else if constexpr (MODE == 3) {
                    v0 += bias[gc]; v1 += bias[gc + 1];
                    const float g0 = 1.f / (1.f + expf(-v0));
                    const float g1 = 1.f / (1.f + expf(-v1));
                    const float2 e2 = *(const float2*)&ep[gi];
                    const float2 x2 = *(const float2*)&ex[gi];
                    v0 = rtf32(g0 * e2.x + (1.f - g0) * x2.x);
                    v1 = rtf32(g1 * e2.y + (1.f - g1) * x2.y);
                }
                *(float2*)&C[gi] = make_float2(v0, v1);
                if constexpr (MODE == 4)
                    *(float2*)&C2[gi] = make_float2(rtf32(v0), rtf32(v1));
            }
        }
    }
}

// ---------------- round-to-tf32 copy ---------------------------------------------
__global__ void round_copy(const float4* __restrict__ s, float4* __restrict__ d)
{
    const int i = blockIdx.x * 256 + threadIdx.x;
    float4 v = s[i];
    v.x = rtf32(v.x); v.y = rtf32(v.y); v.z = rtf32(v.z); v.w = rtf32(v.w);
    d[i] = v;
}

// ---------------- KV partial reduction (fp32, near roofline) ---------------------
__global__ void __launch_bounds__(256) kv_reduce(const float* __restrict__ k,
                                                 const float* __restrict__ v)
{
    const int h = blockIdx.x;
    const int chunk = blockIdx.y;
    const int b0 = chunk * (BATCH / KV_SPLIT);
    __shared__ float ks[8][128];
    __shared__ float vs[8][128];
    const int tid = threadIdx.x;
    const int d0 = (tid >> 4) * 8;
    const int e0 = (tid & 15) * 8;
    float acc[8][8] = {};

    for (int bb = 0; bb < (BATCH / KV_SPLIT); bb += 8) {
        {
            int r = tid >> 5;
            int c4 = (tid & 31) << 2;
            *reinterpret_cast<float4*>(&ks[r][c4]) = *reinterpret_cast<const float4*>(
                k + (size_t)(b0 + bb + r) * DIN + h * DHEAD + c4);
            *reinterpret_cast<float4*>(&vs[r][c4]) = *reinterpret_cast<const float4*>(
                v + (size_t)(b0 + bb + r) * DIN + h * DHEAD + c4);
        }
        __syncthreads();
#pragma unroll
        for (int r = 0; r < 8; r++) {
            float kr[8], vr[8];
#pragma unroll
            for (int i = 0; i < 8; i++) { kr[i] = ks[r][d0 + i]; vr[i] = vs[r][e0 + i]; }
#pragma unroll
            for (int i = 0; i < 8; i++)
#pragma unroll
                for (int j = 0; j < 8; j++) acc[i][j] += kr[i] * vr[j];
        }
        __syncthreads();
    }
    float* dst = g_kvpart + (size_t)chunk * (HEADS * DHEAD * DHEAD) + h * DHEAD * DHEAD;
#pragma unroll
    for (int i = 0; i < 8; i++)
#pragma unroll
        for (int j = 0; j < 8; j++) dst[(d0 + i) * DHEAD + e0 + j] = acc[i][j];
}

__global__ void ksum_part(const float* __restrict__ k)
{
    int c = blockIdx.x * 256 + threadIdx.x;
    int r0 = blockIdx.y * (BATCH / KS_SPLIT);
    float s = 0.0f;
    for (int r = 0; r < BATCH / KS_SPLIT; r++) s += k[(size_t)(r0 + r) * DIN + c];
    g_ksumpart[blockIdx.y * DIN + c] = s;
}

__global__ void kv_final()
{
    int i = blockIdx.x * 256 + threadIdx.x;
    float s = 0.0f;
    for (int c = 0; c < KV_SPLIT; c++) s += g_kvpart[(size_t)c * (HEADS * DHEAD * DHEAD) + i];
    g_kv[i] = s;
    if (i < DIN) {
        float t = 0.0f;
        for (int c = 0; c < KS_SPLIT; c++) t += g_ksumpart[c * DIN + i];
        g_ksum[i] = t;
    }
}

// ---------------- attention (fp32 compute; tf32-rounded output) ------------------
__global__ void __launch_bounds__(256) attn_kernel(const float* __restrict__ q,
                                                   float* __restrict__ att)
{
    extern __shared__ float smx[];
    float* kv_s   = smx;
    float* q_s    = smx + 128 * 132;
    float* ksum_s = q_s + 128 * 132;
    float* z_s    = ksum_s + 128;

    const int h  = blockIdx.y;
    const int b0 = blockIdx.x * 128;
    const int tid = threadIdx.x;

    const float* kvh = g_kv + h * DHEAD * DHEAD;
    for (int i = tid; i < DHEAD * DHEAD; i += 256) {
        int d = i >> 7, e = i & 127;
        kv_s[d * 132 + e] = kvh[i];
    }
    for (int i = tid; i < 128 * 32; i += 256) {
        int r = i >> 5;
        int c4 = (i & 31) << 2;
        *reinterpret_cast<float4*>(&q_s[r * 132 + c4]) =
            *reinterpret_cast<const float4*>(q + (size_t)(b0 + r) * DIN + h * DHEAD + c4);
    }
    if (tid < 128) ksum_s[tid] = g_ksum[h * DHEAD + tid];
    __syncthreads();

    {
        int r = tid >> 1, half = tid & 1;
        float s = 0.0f;
        int dbase = half * 64;
        for (int d = 0; d < 64; d++) s += q_s[r * 132 + dbase + d] * ksum_s[dbase + d];
        s += __shfl_xor_sync(0xffffffffu, s, 1);
        if (half == 0) z_s[r] = 1.0f / (s + 1e-6f);
    }
    __syncthreads();

    const int rg = tid >> 3;
    const int e0 = (tid & 7) * 16;
    float acc[4][16] = {};
    for (int d = 0; d < 128; d++) {
        float kvrow[16];
#pragma unroll
        for (int j = 0; j < 16; j += 4) {
            float4 f = *reinterpret_cast<float4*>(&kv_s[d * 132 + e0 + j]);
            kvrow[j] = f.x; kvrow[j + 1] = f.y; kvrow[j + 2] = f.z; kvrow[j + 3] = f.w;
        }
#pragma unroll
        for (int rr = 0; rr < 4; rr++) {
            float qd = q_s[(rg + rr * 32) * 132 + d];
#pragma unroll
            for (int j = 0; j < 16; j++) acc[rr][j] += qd * kvrow[j];
        }
    }
#pragma unroll
    for (int rr = 0; rr < 4; rr++) {
        int r = rg + rr * 32;
        float z = z_s[r];
#pragma unroll
        for (int j = 0; j < 16; j++)
            att[(size_t)(b0 + r) * DIN + h * DHEAD + e0 + j] = rtf32(acc[rr][j] * z);
    }
}

// ---------------- launch -----------------------------------------------------------
extern "C" void kernel_launch(void* const* d_in, const int* in_sizes, int n_in,
                              void* d_out, int out_size)
{
    const float* x    = (const float*)d_in[0];
    const float* Wq   = (const float*)d_in[1];
    const float* Wk   = (const float*)d_in[2];
    const float* Wv   = (const float*)d_in[3];
    const float* Wo   = (const float*)d_in[4];
    const float* bo   = (const float*)d_in[5];
    const float* Wg   = (const float*)d_in[6];
    const float* bg   = (const float*)d_in[7];
    const float* Wout = (const float*)d_in[8];
    const float* bout = (const float*)d_in[9];
    float* out = (float*)d_out;

    float *xr_, *q_, *k_, *v_, *att_, *op_, *opr_, *gt_;
    float *wq_, *wk_, *wv_, *wo_, *wg_, *wout_;
    cudaGetSymbolAddress((void**)&xr_,  g_xr);
    cudaGetSymbolAddress((void**)&q_,   g_q);
    cudaGetSymbolAddress((void**)&k_,   g_k);
    cudaGetSymbolAddress((void**)&v_,   g_v);
    cudaGetSymbolAddress((void**)&att_, g_att);
    cudaGetSymbolAddress((void**)&op_,  g_op);
    cudaGetSymbolAddress((void**)&opr_, g_opr);
    cudaGetSymbolAddress((void**)&gt_,  g_gt);
    cudaGetSymbolAddress((void**)&wq_,  g_wq);
    cudaGetSymbolAddress((void**)&wk_,  g_wk);
    cudaGetSymbolAddress((void**)&wv_,  g_wv);
    cudaGetSymbolAddress((void**)&wo_,  g_wo);
    cudaGetSymbolAddress((void**)&wg_,  g_wg);
    cudaGetSymbolAddress((void**)&wout_,g_wout);

    cudaFuncSetAttribute(gemm_mma<0>, cudaFuncAttributeMaxDynamicSharedMemorySize, GEMM_SMEM);
    cudaFuncSetAttribute(gemm_mma<1>, cudaFuncAttributeMaxDynamicSharedMemorySize, GEMM_SMEM);
    cudaFuncSetAttribute(gemm_mma<2>, cudaFuncAttributeMaxDynamicSharedMemorySize, GEMM_SMEM);
    cudaFuncSetAttribute(gemm_mma<3>, cudaFuncAttributeMaxDynamicSharedMemorySize, GEMM_SMEM);
    cudaFuncSetAttribute(gemm_mma<4>, cudaFuncAttributeMaxDynamicSharedMemorySize, GEMM_SMEM);

    const dim3 blk(256);
    const dim3 gN2048(DIN / BN, BATCH / BM);   // (8, 128)
    const dim3 gN512(DOUT / BN, BATCH / BM);   // (2, 128)

    // 0) tf32-RN-rounded operand copies (removes HMMA truncation bias)
    round_copy<<<(BATCH * DIN) / 1024, 256>>>((const float4*)x, (float4*)xr_);
    round_copy<<<(DIN * DIN) / 1024, 256>>>((const float4*)Wq, (float4*)wq_);
    round_copy<<<(DIN * DIN) / 1024, 256>>>((const float4*)Wk, (float4*)wk_);
    round_copy<<<(DIN * DIN) / 1024, 256>>>((const float4*)Wv, (float4*)wv_);
    round_copy<<<(DIN * DIN) / 1024, 256>>>((const float4*)Wo, (float4*)wo_);
    round_copy<<<(2 * DIN * DIN) / 1024, 256>>>((const float4*)Wg, (float4*)wg_);
    round_copy<<<(DIN * DOUT) / 1024, 256>>>((const float4*)Wout, (float4*)wout_);

    // 1-3) Q = feat(xr@Wq), K = feat(xr@Wk), V = xr@Wv
    gemm_mma<1><<<gN2048, blk, GEMM_SMEM>>>(xr_, xr_, DIN, DIN / BK, wq_,
                                            nullptr, nullptr, nullptr, q_, nullptr, DIN);
    gemm_mma<1><<<gN2048, blk, GEMM_SMEM>>>(xr_, xr_, DIN, DIN / BK, wk_,
                                            nullptr, nullptr, nullptr, k_, nullptr, DIN);
    gemm_mma<0><<<gN2048, blk, GEMM_SMEM>>>(xr_, xr_, DIN, DIN / BK, wv_,
                                            nullptr, nullptr, nullptr, v_, nullptr, DIN);

    // 4-6) kv / ksum reductions (deterministic two-stage, fp32)
    kv_reduce<<<dim3(HEADS, KV_SPLIT), 256>>>(k_, v_);
    ksum_part<<<dim3(DIN / 256, KS_SPLIT), 256>>>(k_);
    kv_final<<<dim3((HEADS * DHEAD * DHEAD) / 256), 256>>>();

    // 7) attention (tf32-rounded output feeds Wo GEMM)
    size_t attn_smem = (size_t)(128 * 132 * 2 + 256) * sizeof(float);
    cudaFuncSetAttribute(attn_kernel, cudaFuncAttributeMaxDynamicSharedMemorySize,
                         (int)attn_smem);
    attn_kernel<<<dim3(BATCH / 128, HEADS), 256, attn_smem>>>(q_, att_);

    // 8) out_proj = att @ Wo + bo  (exact -> op, tf32-rounded -> opr)
    gemm_mma<4><<<gN2048, blk, GEMM_SMEM>>>(att_, att_, DIN, DIN / BK, wo_,
                                            bo, nullptr, nullptr, op_, opr_, DIN);

    // 9) gate GEMM over concat [opr | xr]; blend with exact op / x
    gemm_mma<3><<<gN2048, blk, GEMM_SMEM>>>(opr_, xr_, DIN, (2 * DIN) / BK, wg_,
                                            bg, op_, x, gt_, nullptr, DIN);

    // 10) out = gt @ Wout + bout
    gemm_mma<2><<<gN512, blk, GEMM_SMEM>>>(gt_, gt_, DIN, DIN / BK, wout_,
                                           bout, nullptr, nullptr, out, nullptr, DOUT);
}

// round 5
// speedup vs baseline: 3.5490x; 1.4240x over previous
#include <cuda_runtime.h>
#include <cuda_fp16.h>
#include <math.h>
#include <stdint.h>

// ---------------- problem dims (fixed) ----------------------------------------
#define BATCH 16384
#define DIN   2048
#define HEADS 16
#define DHEAD 128
#define DOUT  512

// ---------------- scratch (static device memory) ------------------------------
__device__ __half g_xh  [BATCH * DIN];          // half copy of x
__device__ float  g_q   [BATCH * DIN];
__device__ float  g_k   [BATCH * DIN];
__device__ float  g_v   [BATCH * DIN];
__device__ __half g_att [BATCH * DIN];          // half at write
__device__ float  g_op  [BATCH * DIN];          // exact fp32 (for blend)
__device__ __half g_opr [BATCH * DIN];          // half copy (gate GEMM A)
__device__ __half g_gt  [BATCH * DIN];          // half at write
__device__ float  g_kv  [HEADS * DHEAD * DHEAD];
__device__ float  g_ksum[HEADS * DHEAD];
#define KV_SPLIT 64
__device__ float g_kvpart[KV_SPLIT * HEADS * DHEAD * DHEAD];
#define KS_SPLIT 32
__device__ float g_ksumpart[KS_SPLIT * DIN];
// transposed half weights [N][K]
__device__ __half g_wqT  [DIN * DIN];
__device__ __half g_wkT  [DIN * DIN];
__device__ __half g_wvT  [DIN * DIN];
__device__ __half g_woT  [DIN * DIN];
__device__ __half g_wgT  [DIN * 2 * DIN];
__device__ __half g_woutT[DOUT * DIN];

// ---------------- helpers -------------------------------------------------------
__device__ __forceinline__ uint32_t smem_u32(const void* p) {
    uint32_t a;
    asm("{ .reg .u64 t; cvta.to.shared.u64 t, %1; cvt.u32.u64 %0, t; }" : "=r"(a) : "l"(p));
    return a;
}
__device__ __forceinline__ void cp16(uint32_t dst, const void* src) {
    asm volatile("cp.async.cg.shared.global [%0], [%1], 16;" :: "r"(dst), "l"(src));
}
#define CP_COMMIT() asm volatile("cp.async.commit_group;" ::: "memory")
#define CP_WAIT(n)  asm volatile("cp.async.wait_group %0;" :: "n"(n) : "memory")

#define MMA_F16(d, A4, B2) \
    asm volatile("mma.sync.aligned.m16n8k16.row.col.f32.f16.f16.f32 " \
        "{%0,%1,%2,%3},{%4,%5,%6,%7},{%8,%9},{%0,%1,%2,%3};" \
        : "+f"((d)[0]), "+f"((d)[1]), "+f"((d)[2]), "+f"((d)[3]) \
        : "r"((A4)[0]), "r"((A4)[1]), "r"((A4)[2]), "r"((A4)[3]), \
          "r"((B2)[0]), "r"((B2)[1]))

// ---------------- GEMM config ----------------------------------------------------
// block 128x256, 8 warps (2M x 4N), warp tile 64x64. BK = 32 halves.
// smem rows: 40 halves (20 words, stride%32==4 word-banks -> conflict-free frag loads)
#define BM 128
#define BN 256
#define BK 32
#define STAGES 4
#define ARS 40                         // A smem row stride (halves)
#define BRS 40                         // B smem row stride (halves)
#define ASTGH (BM * ARS)               // 5120 halves / stage (10KB)
#define BSTGH (BN * BRS)               // 10240 halves / stage (20KB)
#define GEMM_SMEM (STAGES * (ASTGH + BSTGH) * 2)   // 122880 bytes

// MODE 0: C=acc            1: C=relu(acc)+1e-4     2: C=acc+bias
// MODE 3: g=sigmoid(acc+bias); Ch=half(g*ep+(1-g)*ex)
// MODE 4: o=acc+bias; C=o; Ch=half(o)
template <int MODE>
__global__ void __launch_bounds__(256, 1) gemm_h(
    const __half* __restrict__ A0, const __half* __restrict__ A1, int K0, int nkt,
    const __half* __restrict__ B, int ldb,
    const float* __restrict__ bias,
    const float* __restrict__ ep, const float* __restrict__ ex,
    float* __restrict__ C, __half* __restrict__ Ch, int N)
{
    extern __shared__ __half smh[];
    __half* As = smh;
    __half* Bs = smh + STAGES * ASTGH;
    const uint32_t asu = smem_u32(As);
    const uint32_t bsu = smem_u32(Bs);

    const int tid  = threadIdx.x;
    const int bm   = blockIdx.y * BM;
    const int bn   = blockIdx.x * BN;
    const int wid  = tid >> 5, lane = tid & 31;
    const int wm   = (wid >> 2) * 64;      // 2 warps along M
    const int wn   = (wid & 3) * 64;       // 4 warps along N
    const int lr   = lane >> 2;            // 0..7
    const int lc   = lane & 3;             // 0..3

    float acc[4][8][4];
#pragma unroll
    for (int mt = 0; mt < 4; mt++)
#pragma unroll
        for (int nt = 0; nt < 8; nt++)
#pragma unroll
            for (int e = 0; e < 4; e++) acc[mt][nt][e] = 0.0f;

    auto issue = [&](int kt) {
        const int s = kt % STAGES;
        const int kbase = kt * BK;
        const __half* Aptr;
        int kc;
        if (kbase < K0) { Aptr = A0; kc = kbase; }
        else            { Aptr = A1; kc = kbase - K0; }
        // A tile 128 x 32 halves : 512 x 8-half groups, 2 per thread
#pragma unroll
        for (int i = 0; i < 2; i++) {
            int idx = tid + i * 256;
            int r = idx >> 2, g = idx & 3;
            uint32_t dst = asu + (uint32_t)(s * ASTGH + r * ARS + g * 8) * 2u;
            cp16(dst, Aptr + (size_t)(bm + r) * DIN + kc + g * 8);
        }
        // B tile 256 x 32 halves : 1024 groups, 4 per thread ([n][k] layout)
#pragma unroll
        for (int i = 0; i < 4; i++) {
            int idx = tid + i * 256;
            int r = idx >> 2, g = idx & 3;
            uint32_t dst = bsu + (uint32_t)(s * BSTGH + r * BRS + g * 8) * 2u;
            cp16(dst, B + (size_t)(bn + r) * ldb + kbase + g * 8);
        }
    };

#pragma unroll
    for (int kt = 0; kt < STAGES - 1; kt++) {
        if (kt < nkt) issue(kt);
        CP_COMMIT();
    }

    uint32_t a[2][4][4], b[2][8][2];

    for (int kt = 0; kt < nkt; kt++) {
        CP_WAIT(STAGES - 2);
        __syncthreads();

        if (kt + STAGES - 1 < nkt) issue(kt + STAGES - 1);
        CP_COMMIT();

        const int s = kt % STAGES;
        const __half* as = As + s * ASTGH;
        const __half* bs = Bs + s * BSTGH;

        // load kk=0 fragments (k16 chunk 0: halves [0,16) of the row)
#pragma unroll
        for (int mt = 0; mt < 4; mt++) {
            const int r = wm + mt * 16 + lr;
            a[0][mt][0] = *(const uint32_t*)&as[r * ARS + 2 * lc];
            a[0][mt][1] = *(const uint32_t*)&as[(r + 8) * ARS + 2 * lc];
            a[0][mt][2] = *(const uint32_t*)&as[r * ARS + 2 * lc + 8];
            a[0][mt][3] = *(const uint32_t*)&as[(r + 8) * ARS + 2 * lc + 8];
        }
#pragma unroll
        for (int nt = 0; nt < 8; nt++) {
            const int c = wn + nt * 8 + lr;
            b[0][nt][0] = *(const uint32_t*)&bs[c * BRS + 2 * lc];
            b[0][nt][1] = *(const uint32_t*)&bs[c * BRS + 2 * lc + 8];
        }

#pragma unroll
        for (int kk = 0; kk < 2; kk++) {
            const int cur = kk & 1, nxt = cur ^ 1;
            if (kk < 1) {
                const int ko = 16;     // chunk 1 base (halves)
#pragma unroll
                for (int mt = 0; mt < 4; mt++) {
                    const int r = wm + mt * 16 + lr;
                    a[nxt][mt][0] = *(const uint32_t*)&as[r * ARS + ko + 2 * lc];
                    a[nxt][mt][1] = *(const uint32_t*)&as[(r + 8) * ARS + ko + 2 * lc];
                    a[nxt][mt][2] = *(const uint32_t*)&as[r * ARS + ko + 2 * lc + 8];
                    a[nxt][mt][3] = *(const uint32_t*)&as[(r + 8) * ARS + ko + 2 * lc + 8];
                }
#pragma unroll
                for (int nt = 0; nt < 8; nt++) {
                    const int c = wn + nt * 8 + lr;
                    b[nxt][nt][0] = *(const uint32_t*)&bs[c * BRS + ko + 2 * lc];
                    b[nxt][nt][1] = *(const uint32_t*)&bs[c * BRS + ko + 2 * lc + 8];
                }
            }
#pragma unroll
            for (int mt = 0; mt < 4; mt++)
#pragma unroll
                for (int nt = 0; nt < 8; nt++)
                    MMA_F16(acc[mt][nt], a[cur][mt], b[cur][nt]);
        }
    }

    // ---- epilogue: direct register writes ----
#pragma unroll
    for (int mt = 0; mt < 4; mt++) {
#pragma unroll
        for (int nt = 0; nt < 8; nt++) {
#pragma unroll
            for (int h = 0; h < 2; h++) {
                const int gr = bm + wm + mt * 16 + lr + h * 8;
                const int gc = bn + wn + nt * 8 + 2 * lc;
                const size_t gi = (size_t)gr * N + gc;
                float v0 = acc[mt][nt][h * 2 + 0];
                float v1 = acc[mt][nt][h * 2 + 1];
                if constexpr (MODE == 1) {
                    v0 = fmaxf(v0, 0.f) + 1e-4f;
                    v1 = fmaxf(v1, 0.f) + 1e-4f;
                    *(float2*)&C[gi] = make_float2(v0, v1);
                } else if constexpr (MODE == 0) {
                    *(float2*)&C[gi] = make_float2(v0, v1);
                } else if constexpr (MODE == 2) {
                    v0 += bias[gc]; v1 += bias[gc + 1];
                    *(float2*)&C[gi] = make_float2(v0, v1);
                } else if constexpr (MODE == 3) {
                    v0 += bias[gc]; v1 += bias[gc + 1];
                    const float g0 = 1.f / (1.f + expf(-v0));
                    const float g1 = 1.f / (1.f + expf(-v1));
                    const float2 e2 = *(const float2*)&ep[gi];
                    const float2 x2 = *(const float2*)&ex[gi];
                    const float r0 = g0 * e2.x + (1.f - g0) * x2.x;
                    const float r1 = g1 * e2.y + (1.f - g1) * x2.y;
                    *(__half2*)&Ch[gi] = __floats2half2_rn(r0, r1);
                } else {  // MODE 4
                    v0 += bias[gc]; v1 += bias[gc + 1];
                    *(float2*)&C[gi] = make_float2(v0, v1);
                    *(__half2*)&Ch[gi] = __floats2half2_rn(v0, v1);
                }
            }
        }
    }
}

// ---------------- fp32 -> half copy ----------------------------------------------
__global__ void half_copy(const float4* __restrict__ s, __half2* __restrict__ d)
{
    const int i = blockIdx.x * 256 + threadIdx.x;
    float4 v = s[i];
    d[2 * i]     = __floats2half2_rn(v.x, v.y);
    d[2 * i + 1] = __floats2half2_rn(v.z, v.w);
}

// ---------------- transpose + convert: WT[n][k] = half(W[k][n]) -------------------
__global__ void transpose_half(const float* __restrict__ S, __half* __restrict__ D,
                               int K, int N)
{
    __shared__ float t[32][33];
    const int bn = blockIdx.x * 32, bk = blockIdx.y * 32;
    const int tx = threadIdx.x, ty = threadIdx.y;
#pragma unroll
    for (int i = 0; i < 32; i += 8)
        t[ty + i][tx] = S[(size_t)(bk + ty + i) * N + bn + tx];
    __syncthreads();
#pragma unroll
    for (int i = 0; i < 32; i += 8)
        D[(size_t)(bn + ty + i) * K + bk + tx] = __float2half_rn(t[tx][ty + i]);
}

// ---------------- KV partial reduction (fp32) -------------------------------------
__global__ void __launch_bounds__(256) kv_reduce(const float* __restrict__ k,
                                                 const float* __restrict__ v)
{
    const int h = blockIdx.x;
    const int chunk = blockIdx.y;
    const int b0 = chunk * (BATCH / KV_SPLIT);
    __shared__ float ks[8][128];
    __shared__ float vs[8][128];
    const int tid = threadIdx.x;
    const int d0 = (tid >> 4) * 8;
    const int e0 = (tid & 15) * 8;
    float acc[8][8] = {};

    for (int bb = 0; bb < (BATCH / KV_SPLIT); bb += 8) {
        {
            int r = tid >> 5;
            int c4 = (tid & 31) << 2;
            *reinterpret_cast<float4*>(&ks[r][c4]) = *reinterpret_cast<const float4*>(
                k + (size_t)(b0 + bb + r) * DIN + h * DHEAD + c4);
            *reinterpret_cast<float4*>(&vs[r][c4]) = *reinterpret_cast<const float4*>(
                v + (size_t)(b0 + bb + r) * DIN + h * DHEAD + c4);
        }
        __syncthreads();
#pragma unroll
        for (int r = 0; r < 8; r++) {
            float kr[8], vr[8];
#pragma unroll
            for (int i = 0; i < 8; i++) { kr[i] = ks[r][d0 + i]; vr[i] = vs[r][e0 + i]; }
#pragma unroll
            for (int i = 0; i < 8; i++)
#pragma unroll
                for (int j = 0; j < 8; j++) acc[i][j] += kr[i] * vr[j];
        }
        __syncthreads();
    }
    float* dst = g_kvpart + (size_t)chunk * (HEADS * DHEAD * DHEAD) + h * DHEAD * DHEAD;
#pragma unroll
    for (int i = 0; i < 8; i++)
#pragma unroll
        for (int j = 0; j < 8; j++) dst[(d0 + i) * DHEAD + e0 + j] = acc[i][j];
}

__global__ void ksum_part(const float* __restrict__ k)
{
    int c = blockIdx.x * 256 + threadIdx.x;
    int r0 = blockIdx.y * (BATCH / KS_SPLIT);
    float s = 0.0f;
    for (int r = 0; r < BATCH / KS_SPLIT; r++) s += k[(size_t)(r0 + r) * DIN + c];
    g_ksumpart[blockIdx.y * DIN + c] = s;
}

__global__ void kv_final()
{
    int i = blockIdx.x * 256 + threadIdx.x;
    float s = 0.0f;
    for (int c = 0; c < KV_SPLIT; c++) s += g_kvpart[(size_t)c * (HEADS * DHEAD * DHEAD) + i];
    g_kv[i] = s;
    if (i < DIN) {
        float t = 0.0f;
        for (int c = 0; c < KS_SPLIT; c++) t += g_ksumpart[c * DIN + i];
        g_ksum[i] = t;
    }
}

// ---------------- attention (fp32 compute; half output) ---------------------------
__global__ void __launch_bounds__(256) attn_kernel(const float* __restrict__ q,
                                                   __half* __restrict__ att)
{
    extern __shared__ float smx[];
    float* kv_s   = smx;
    float* q_s    = smx + 128 * 132;
    float* ksum_s = q_s + 128 * 132;
    float* z_s    = ksum_s + 128;

    const int h  = blockIdx.y;
    const int b0 = blockIdx.x * 128;
    const int tid = threadIdx.x;

    const float* kvh = g_kv + h * DHEAD * DHEAD;
    for (int i = tid; i < DHEAD * DHEAD; i += 256) {
        int d = i >> 7, e = i & 127;
        kv_s[d * 132 + e] = kvh[i];
    }
    for (int i = tid; i < 128 * 32; i += 256) {
        int r = i >> 5;
        int c4 = (i & 31) << 2;
        *reinterpret_cast<float4*>(&q_s[r * 132 + c4]) =
            *reinterpret_cast<const float4*>(q + (size_t)(b0 + r) * DIN + h * DHEAD + c4);
    }
    if (tid < 128) ksum_s[tid] = g_ksum[h * DHEAD + tid];
    __syncthreads();

    {
        int r = tid >> 1, half_ = tid & 1;
        float s = 0.0f;
        int dbase = half_ * 64;
        for (int d = 0; d < 64; d++) s += q_s[r * 132 + dbase + d] * ksum_s[dbase + d];
        s += __shfl_xor_sync(0xffffffffu, s, 1);
        if (half_ == 0) z_s[r] = 1.0f / (s + 1e-6f);
    }
    __syncthreads();

    const int rg = tid >> 3;
    const int e0 = (tid & 7) * 16;
    float acc[4][16] = {};
    for (int d = 0; d < 128; d++) {
        float kvrow[16];
#pragma unroll
        for (int j = 0; j < 16; j += 4) {
            float4 f = *reinterpret_cast<float4*>(&kv_s[d * 132 + e0 + j]);
            kvrow[j] = f.x; kvrow[j + 1] = f.y; kvrow[j + 2] = f.z; kvrow[j + 3] = f.w;
        }
#pragma unroll
        for (int rr = 0; rr < 4; rr++) {
            float qd = q_s[(rg + rr * 32) * 132 + d];
#pragma unroll
            for (int j = 0; j < 16; j++) acc[rr][j] += qd * kvrow[j];
        }
    }
#pragma unroll
    for (int rr = 0; rr < 4; rr++) {
        int r = rg + rr * 32;
        float z = z_s[r];
#pragma unroll
        for (int j = 0; j < 16; j += 2) {
            __half2 hv = __floats2half2_rn(acc[rr][j] * z, acc[rr][j + 1] * z);
            *(__half2*)&att[(size_t)(b0 + r) * DIN + h * DHEAD + e0 + j] = hv;
        }
    }
}

// ---------------- launch -----------------------------------------------------------
extern "C" void kernel_launch(void* const* d_in, const int* in_sizes, int n_in,
                              void* d_out, int out_size)
{
    const float* x    = (const float*)d_in[0];
    const float* Wq   = (const float*)d_in[1];
    const float* Wk   = (const float*)d_in[2];
    const float* Wv   = (const float*)d_in[3];
    const float* Wo   = (const float*)d_in[4];
    const float* bo   = (const float*)d_in[5];
    const float* Wg   = (const float*)d_in[6];
    const float* bg   = (const float*)d_in[7];
    const float* Wout = (const float*)d_in[8];
    const float* bout = (const float*)d_in[9];
    float* out = (float*)d_out;

    __half *xh_, *att_, *opr_, *gt_;
    float  *q_, *k_, *v_, *op_;
    __half *wqT_, *wkT_, *wvT_, *woT_, *wgT_, *woutT_;
    cudaGetSymbolAddress((void**)&xh_,  g_xh);
    cudaGetSymbolAddress((void**)&q_,   g_q);
    cudaGetSymbolAddress((void**)&k_,   g_k);
    cudaGetSymbolAddress((void**)&v_,   g_v);
    cudaGetSymbolAddress((void**)&att_, g_att);
    cudaGetSymbolAddress((void**)&op_,  g_op);
    cudaGetSymbolAddress((void**)&opr_, g_opr);
    cudaGetSymbolAddress((void**)&gt_,  g_gt);
    cudaGetSymbolAddress((void**)&wqT_, g_wqT);
    cudaGetSymbolAddress((void**)&wkT_, g_wkT);
    cudaGetSymbolAddress((void**)&wvT_, g_wvT);
    cudaGetSymbolAddress((void**)&woT_, g_woT);
    cudaGetSymbolAddress((void**)&wgT_, g_wgT);
    cudaGetSymbolAddress((void**)&woutT_, g_woutT);

    cudaFuncSetAttribute(gemm_h<0>, cudaFuncAttributeMaxDynamicSharedMemorySize, GEMM_SMEM);
    cudaFuncSetAttribute(gemm_h<1>, cudaFuncAttributeMaxDynamicSharedMemorySize, GEMM_SMEM);
    cudaFuncSetAttribute(gemm_h<2>, cudaFuncAttributeMaxDynamicSharedMemorySize, GEMM_SMEM);
    cudaFuncSetAttribute(gemm_h<3>, cudaFuncAttributeMaxDynamicSharedMemorySize, GEMM_SMEM);
    cudaFuncSetAttribute(gemm_h<4>, cudaFuncAttributeMaxDynamicSharedMemorySize, GEMM_SMEM);

    const dim3 blk(256);
    const dim3 gN2048(DIN / BN, BATCH / BM);   // (8, 128)
    const dim3 gN512(DOUT / BN, BATCH / BM);   // (2, 128)
    const dim3 tblk(32, 8);

    // 0) operand prep: half copy of x; transpose+convert weights to [N][K] half
    half_copy<<<(BATCH * DIN) / 1024, 256>>>((const float4*)x, (__half2*)xh_);
    transpose_half<<<dim3(DIN / 32, DIN / 32), tblk>>>(Wq, wqT_, DIN, DIN);
    transpose_half<<<dim3(DIN / 32, DIN / 32), tblk>>>(Wk, wkT_, DIN, DIN);
    transpose_half<<<dim3(DIN / 32, DIN / 32), tblk>>>(Wv, wvT_, DIN, DIN);
    transpose_half<<<dim3(DIN / 32, DIN / 32), tblk>>>(Wo, woT_, DIN, DIN);
    transpose_half<<<dim3(DIN / 32, (2 * DIN) / 32), tblk>>>(Wg, wgT_, 2 * DIN, DIN);
    transpose_half<<<dim3(DOUT / 32, DIN / 32), tblk>>>(Wout, woutT_, DIN, DOUT);

    // 1-3) Q = feat(x@Wq), K = feat(x@Wk), V = x@Wv   (fp32 outputs)
    gemm_h<1><<<gN2048, blk, GEMM_SMEM>>>(xh_, xh_, DIN, DIN / BK, wqT_, DIN,
                                          nullptr, nullptr, nullptr, q_, nullptr, DIN);
    gemm_h<1><<<gN2048, blk, GEMM_SMEM>>>(xh_, xh_, DIN, DIN / BK, wkT_, DIN,
                                          nullptr, nullptr, nullptr, k_, nullptr, DIN);
    gemm_h<0><<<gN2048, blk, GEMM_SMEM>>>(xh_, xh_, DIN, DIN / BK, wvT_, DIN,
                                          nullptr, nullptr, nullptr, v_, nullptr, DIN);

    // 4-6) kv / ksum reductions (deterministic two-stage, fp32)
    kv_reduce<<<dim3(HEADS, KV_SPLIT), 256>>>(k_, v_);
    ksum_part<<<dim3(DIN / 256, KS_SPLIT), 256>>>(k_);
    kv_final<<<dim3((HEADS * DHEAD * DHEAD) / 256), 256>>>();

    // 7) attention (half output feeds Wo GEMM)
    size_t attn_smem = (size_t)(128 * 132 * 2 + 256) * sizeof(float);
    cudaFuncSetAttribute(attn_kernel, cudaFuncAttributeMaxDynamicSharedMemorySize,
                         (int)attn_smem);
    attn_kernel<<<dim3(BATCH / 128, HEADS), 256, attn_smem>>>(q_, att_);

    // 8) out_proj = att @ Wo + bo  (fp32 op + half opr)
    gemm_h<4><<<gN2048, blk, GEMM_SMEM>>>(att_, att_, DIN, DIN / BK, woT_, DIN,
                                          bo, nullptr, nullptr, op_, opr_, DIN);

    // 9) gate GEMM over concat [opr | xh]; blend exact op / x -> half gt
    gemm_h<3><<<gN2048, blk, GEMM_SMEM>>>(opr_, xh_, DIN, (2 * DIN) / BK, wgT_, 2 * DIN,
                                          bg, op_, x, nullptr, gt_, DIN);

    // 10) out = gt @ Wout + bout (fp32)
    gemm_h<2><<<gN512, blk, GEMM_SMEM>>>(gt_, gt_, DIN, DIN / BK, woutT_, DIN,
                                         bout, nullptr, nullptr, out, nullptr, DOUT);
}

// round 6
// speedup vs baseline: 3.6096x; 1.0171x over previous
#include <cuda_runtime.h>
#include <cuda_fp16.h>
#include <math.h>
#include <stdint.h>

// ---------------- problem dims (fixed) ----------------------------------------
#define BATCH 16384
#define DIN   2048
#define HEADS 16
#define DHEAD 128
#define DOUT  512

// ---------------- scratch (static device memory) ------------------------------
__device__ __half g_xh  [BATCH * DIN];          // half copy of x
__device__ float  g_q   [BATCH * DIN];
__device__ float  g_k   [BATCH * DIN];
__device__ float  g_v   [BATCH * DIN];
__device__ __half g_att [BATCH * DIN];          // half at write
__device__ float  g_op  [BATCH * DIN];          // exact fp32 (for blend)
__device__ __half g_opr [BATCH * DIN];          // half copy (gate GEMM A)
__device__ __half g_gt  [BATCH * DIN];          // half at write
__device__ float  g_kv  [HEADS * DHEAD * DHEAD];
__device__ float  g_ksum[HEADS * DHEAD];
#define KV_SPLIT 64
__device__ float g_kvpart[KV_SPLIT * HEADS * DHEAD * DHEAD];
#define KS_SPLIT 32
__device__ float g_ksumpart[KS_SPLIT * DIN];
// transposed half weights [N][K]
__device__ __half g_wqT  [DIN * DIN];
__device__ __half g_wkT  [DIN * DIN];
__device__ __half g_wvT  [DIN * DIN];
__device__ __half g_woT  [DIN * DIN];
__device__ __half g_wgT  [DIN * 2 * DIN];
__device__ __half g_woutT[DOUT * DIN];

// ---------------- helpers -------------------------------------------------------
__device__ __forceinline__ uint32_t smem_u32(const void* p) {
    uint32_t a;
    asm("{ .reg .u64 t; cvta.to.shared.u64 t, %1; cvt.u32.u64 %0, t; }" : "=r"(a) : "l"(p));
    return a;
}
__device__ __forceinline__ void cp16(uint32_t dst, const void* src) {
    asm volatile("cp.async.cg.shared.global [%0], [%1], 16;" :: "r"(dst), "l"(src));
}
#define CP_COMMIT() asm volatile("cp.async.commit_group;" ::: "memory")
#define CP_WAIT(n)  asm volatile("cp.async.wait_group %0;" :: "n"(n) : "memory")

#define MMA_F16(d, A4, B2) \
    asm volatile("mma.sync.aligned.m16n8k16.row.col.f32.f16.f16.f32 " \
        "{%0,%1,%2,%3},{%4,%5,%6,%7},{%8,%9},{%0,%1,%2,%3};" \
        : "+f"((d)[0]), "+f"((d)[1]), "+f"((d)[2]), "+f"((d)[3]) \
        : "r"((A4)[0]), "r"((A4)[1]), "r"((A4)[2]), "r"((A4)[3]), \
          "r"((B2)[0]), "r"((B2)[1]))

#define LDSM_X4(r0, r1, r2, r3, addr) \
    asm volatile("ldmatrix.sync.aligned.m8n8.x4.shared.b16 {%0,%1,%2,%3}, [%4];" \
        : "=r"(r0), "=r"(r1), "=r"(r2), "=r"(r3) : "r"(addr))

// ---------------- GEMM config ----------------------------------------------------
// block 128x256, 8 warps (2M x 4N), warp tile 64x64. BK = 32 halves.
// smem row stride 40 halves (80B): ldmatrix rows hit banks 20r%32 - conflict-free.
#define BM 128
#define BN 256
#define BK 32
#define STAGES 4
#define ARS 40
#define BRS 40
#define ASTGH (BM * ARS)               // 5120 halves / stage
#define BSTGH (BN * BRS)               // 10240 halves / stage
#define GEMM_SMEM (STAGES * (ASTGH + BSTGH) * 2)   // 122880 bytes

// MODE 0: C=acc            1: C=relu(acc)+1e-4     2: C=acc+bias
// MODE 3: g=sigmoid(acc+bias); Ch=half(g*ep+(1-g)*ex)
// MODE 4: o=acc+bias; C=o; Ch=half(o)
template <int MODE>
__global__ void __launch_bounds__(256, 1) gemm_h(
    const __half* __restrict__ A0, const __half* __restrict__ A1, int K0, int nkt,
    const __half* __restrict__ B, int ldb,
    const float* __restrict__ bias,
    const float* __restrict__ ep, const float* __restrict__ ex,
    float* __restrict__ C, __half* __restrict__ Ch, int N)
{
    extern __shared__ __half smh[];
    __half* As = smh;
    __half* Bs = smh + STAGES * ASTGH;
    const uint32_t asu = smem_u32(As);
    const uint32_t bsu = smem_u32(Bs);

    const int tid  = threadIdx.x;
    const int bm   = blockIdx.y * BM;
    const int bn   = blockIdx.x * BN;
    const int wid  = tid >> 5, lane = tid & 31;
    const int wm   = (wid >> 2) * 64;      // 2 warps along M
    const int wn   = (wid & 3) * 64;       // 4 warps along N

    // ldmatrix lane-address offsets (bytes)
    const uint32_t a_lane = (uint32_t)(((lane & 15) * ARS + (lane >> 4) * 8) * 2);
    const uint32_t b_lane = (uint32_t)(((((lane >> 4) << 3) + (lane & 7)) * BRS
                                        + ((lane >> 3) & 1) * 8) * 2);

    float acc[4][8][4];
#pragma unroll
    for (int mt = 0; mt < 4; mt++)
#pragma unroll
        for (int nt = 0; nt < 8; nt++)
#pragma unroll
            for (int e = 0; e < 4; e++) acc[mt][nt][e] = 0.0f;

    auto issue = [&](int kt) {
        const int s = kt % STAGES;
        const int kbase = kt * BK;
        const __half* Aptr;
        int kc;
        if (kbase < K0) { Aptr = A0; kc = kbase; }
        else            { Aptr = A1; kc = kbase - K0; }
#pragma unroll
        for (int i = 0; i < 2; i++) {          // A tile 128 x 32 halves
            int idx = tid + i * 256;
            int r = idx >> 2, g = idx & 3;
            uint32_t dst = asu + (uint32_t)(s * ASTGH + r * ARS + g * 8) * 2u;
            cp16(dst, Aptr + (size_t)(bm + r) * DIN + kc + g * 8);
        }
#pragma unroll
        for (int i = 0; i < 4; i++) {          // B tile 256 x 32 halves ([n][k])
            int idx = tid + i * 256;
            int r = idx >> 2, g = idx & 3;
            uint32_t dst = bsu + (uint32_t)(s * BSTGH + r * BRS + g * 8) * 2u;
            cp16(dst, B + (size_t)(bn + r) * ldb + kbase + g * 8);
        }
    };

#pragma unroll
    for (int kt = 0; kt < STAGES - 1; kt++) {
        if (kt < nkt) issue(kt);
        CP_COMMIT();
    }

    uint32_t a[2][4][4], b[2][8][2];

    for (int kt = 0; kt < nkt; kt++) {
        CP_WAIT(STAGES - 2);
        __syncthreads();

        if (kt + STAGES - 1 < nkt) issue(kt + STAGES - 1);
        CP_COMMIT();

        const int s = kt % STAGES;
        const uint32_t abase = asu + (uint32_t)(s * ASTGH + wm * ARS) * 2u + a_lane;
        const uint32_t bbase = bsu + (uint32_t)(s * BSTGH + wn * BRS) * 2u + b_lane;

        // kk=0 fragments via ldmatrix.x4
#pragma unroll
        for (int mt = 0; mt < 4; mt++)
            LDSM_X4(a[0][mt][0], a[0][mt][1], a[0][mt][2], a[0][mt][3],
                    abase + (uint32_t)(mt * 16 * ARS * 2));
#pragma unroll
        for (int p = 0; p < 4; p++)
            LDSM_X4(b[0][2 * p][0], b[0][2 * p][1], b[0][2 * p + 1][0], b[0][2 * p + 1][1],
                    bbase + (uint32_t)(p * 16 * BRS * 2));

#pragma unroll
        for (int kk = 0; kk < 2; kk++) {
            const int cur = kk & 1, nxt = cur ^ 1;
            if (kk < 1) {
                // kk=1 fragments (k offset 16 halves = 32 bytes)
#pragma unroll
                for (int mt = 0; mt < 4; mt++)
                    LDSM_X4(a[nxt][mt][0], a[nxt][mt][1], a[nxt][mt][2], a[nxt][mt][3],
                            abase + (uint32_t)(mt * 16 * ARS * 2) + 32u);
#pragma unroll
                for (int p = 0; p < 4; p++)
                    LDSM_X4(b[nxt][2 * p][0], b[nxt][2 * p][1],
                            b[nxt][2 * p + 1][0], b[nxt][2 * p + 1][1],
                            bbase + (uint32_t)(p * 16 * BRS * 2) + 32u);
            }
#pragma unroll
            for (int mt = 0; mt < 4; mt++)
#pragma unroll
                for (int nt = 0; nt < 8; nt++)
                    MMA_F16(acc[mt][nt], a[cur][mt], b[cur][nt]);
        }
    }

    // ---- epilogue: direct register writes ----
    const int lr = lane >> 2, lc = lane & 3;
#pragma unroll
    for (int mt = 0; mt < 4; mt++) {
#pragma unroll
        for (int nt = 0; nt < 8; nt++) {
#pragma unroll
            for (int h = 0; h < 2; h++) {
                const int gr = bm + wm + mt * 16 + lr + h * 8;
                const int gc = bn + wn + nt * 8 + 2 * lc;
                const size_t gi = (size_t)gr * N + gc;
                float v0 = acc[mt][nt][h * 2 + 0];
                float v1 = acc[mt][nt][h * 2 + 1];
                if constexpr (MODE == 1) {
                    v0 = fmaxf(v0, 0.f) + 1e-4f;
                    v1 = fmaxf(v1, 0.f) + 1e-4f;
                    *(float2*)&C[gi] = make_float2(v0, v1);
                } else if constexpr (MODE == 0) {
                    *(float2*)&C[gi] = make_float2(v0, v1);
                } else if constexpr (MODE == 2) {
                    v0 += bias[gc]; v1 += bias[gc + 1];
                    *(float2*)&C[gi] = make_float2(v0, v1);
                } else if constexpr (MODE == 3) {
                    v0 += bias[gc]; v1 += bias[gc + 1];
                    const float g0 = 1.f / (1.f + expf(-v0));
                    const float g1 = 1.f / (1.f + expf(-v1));
                    const float2 e2 = *(const float2*)&ep[gi];
                    const float2 x2 = *(const float2*)&ex[gi];
                    const float r0 = g0 * e2.x + (1.f - g0) * x2.x;
                    const float r1 = g1 * e2.y + (1.f - g1) * x2.y;
                    *(__half2*)&Ch[gi] = __floats2half2_rn(r0, r1);
                } else {  // MODE 4
                    v0 += bias[gc]; v1 += bias[gc + 1];
                    *(float2*)&C[gi] = make_float2(v0, v1);
                    *(__half2*)&Ch[gi] = __floats2half2_rn(v0, v1);
                }
            }
        }
    }
}

// ---------------- fp32 -> half copy ----------------------------------------------
__global__ void half_copy(const float4* __restrict__ s, __half2* __restrict__ d)
{
    const int i = blockIdx.x * 256 + threadIdx.x;
    float4 v = s[i];
    d[2 * i]     = __floats2half2_rn(v.x, v.y);
    d[2 * i + 1] = __floats2half2_rn(v.z, v.w);
}

// ---------------- transpose + convert: WT[n][k] = half(W[k][n]) -------------------
__global__ void transpose_half(const float* __restrict__ S, __half* __restrict__ D,
                               int K, int N)
{
    __shared__ float t[32][33];
    const int bn = blockIdx.x * 32, bk = blockIdx.y * 32;
    const int tx = threadIdx.x, ty = threadIdx.y;
#pragma unroll
    for (int i = 0; i < 32; i += 8)
        t[ty + i][tx] = S[(size_t)(bk + ty + i) * N + bn + tx];
    __syncthreads();
#pragma unroll
    for (int i = 0; i < 32; i += 8)
        D[(size_t)(bn + ty + i) * K + bk + tx] = __float2half_rn(t[tx][ty + i]);
}

// ---------------- KV partial reduction (fp32) -------------------------------------
__global__ void __launch_bounds__(256) kv_reduce(const float* __restrict__ k,
                                                 const float* __restrict__ v)
{
    const int h = blockIdx.x;
    const int chunk = blockIdx.y;
    const int b0 = chunk * (BATCH / KV_SPLIT);
    __shared__ float ks[8][128];
    __shared__ float vs[8][128];
    const int tid = threadIdx.x;
    const int d0 = (tid >> 4) * 8;
    const int e0 = (tid & 15) * 8;
    float acc[8][8] = {};

    for (int bb = 0; bb < (BATCH / KV_SPLIT); bb += 8) {
        {
            int r = tid >> 5;
            int c4 = (tid & 31) << 2;
            *reinterpret_cast<float4*>(&ks[r][c4]) = *reinterpret_cast<const float4*>(
                k + (size_t)(b0 + bb + r) * DIN + h * DHEAD + c4);
            *reinterpret_cast<float4*>(&vs[r][c4]) = *reinterpret_cast<const float4*>(
                v + (size_t)(b0 + bb + r) * DIN + h * DHEAD + c4);
        }
        __syncthreads();
#pragma unroll
        for (int r = 0; r < 8; r++) {
            float kr[8], vr[8];
#pragma unroll
            for (int i = 0; i < 8; i++) { kr[i] = ks[r][d0 + i]; vr[i] = vs[r][e0 + i]; }
#pragma unroll
            for (int i = 0; i < 8; i++)
#pragma unroll
                for (int j = 0; j < 8; j++) acc[i][j] += kr[i] * vr[j];
        }
        __syncthreads();
    }
    float* dst = g_kvpart + (size_t)chunk * (HEADS * DHEAD * DHEAD) + h * DHEAD * DHEAD;
#pragma unroll
    for (int i = 0; i < 8; i++)
#pragma unroll
        for (int j = 0; j < 8; j++) dst[(d0 + i) * DHEAD + e0 + j] = acc[i][j];
}

__global__ void ksum_part(const float* __restrict__ k)
{
    int c = blockIdx.x * 256 + threadIdx.x;
    int r0 = blockIdx.y * (BATCH / KS_SPLIT);
    float s = 0.0f;
    for (int r = 0; r < BATCH / KS_SPLIT; r++) s += k[(size_t)(r0 + r) * DIN + c];
    g_ksumpart[blockIdx.y * DIN + c] = s;
}

__global__ void kv_final()
{
    int i = blockIdx.x * 256 + threadIdx.x;
    float s = 0.0f;
    for (int c = 0; c < KV_SPLIT; c++) s += g_kvpart[(size_t)c * (HEADS * DHEAD * DHEAD) + i];
    g_kv[i] = s;
    if (i < DIN) {
        float t = 0.0f;
        for (int c = 0; c < KS_SPLIT; c++) t += g_ksumpart[c * DIN + i];
        g_ksum[i] = t;
    }
}

// ---------------- attention (fp32 compute; half output) ---------------------------
__global__ void __launch_bounds__(256) attn_kernel(const float* __restrict__ q,
                                                   __half* __restrict__ att)
{
    extern __shared__ float smx[];
    float* kv_s   = smx;
    float* q_s    = smx + 128 * 132;
    float* ksum_s = q_s + 128 * 132;
    float* z_s    = ksum_s + 128;

    const int h  = blockIdx.y;
    const int b0 = blockIdx.x * 128;
    const int tid = threadIdx.x;

    const float* kvh = g_kv + h * DHEAD * DHEAD;
    for (int i = tid; i < DHEAD * DHEAD; i += 256) {
        int d = i >> 7, e = i & 127;
        kv_s[d * 132 + e] = kvh[i];
    }
    for (int i = tid; i < 128 * 32; i += 256) {
        int r = i >> 5;
        int c4 = (i & 31) << 2;
        *reinterpret_cast<float4*>(&q_s[r * 132 + c4]) =
            *reinterpret_cast<const float4*>(q + (size_t)(b0 + r) * DIN + h * DHEAD + c4);
    }
    if (tid < 128) ksum_s[tid] = g_ksum[h * DHEAD + tid];
    __syncthreads();

    {
        int r = tid >> 1, half_ = tid & 1;
        float s = 0.0f;
        int dbase = half_ * 64;
        for (int d = 0; d < 64; d++) s += q_s[r * 132 + dbase + d] * ksum_s[dbase + d];
        s += __shfl_xor_sync(0xffffffffu, s, 1);
        if (half_ == 0) z_s[r] = 1.0f / (s + 1e-6f);
    }
    __syncthreads();

    const int rg = tid >> 3;
    const int e0 = (tid & 7) * 16;
    float acc[4][16] = {};
    for (int d = 0; d < 128; d++) {
        float kvrow[16];
#pragma unroll
        for (int j = 0; j < 16; j += 4) {
            float4 f = *reinterpret_cast<float4*>(&kv_s[d * 132 + e0 + j]);
            kvrow[j] = f.x; kvrow[j + 1] = f.y; kvrow[j + 2] = f.z; kvrow[j + 3] = f.w;
        }
#pragma unroll
        for (int rr = 0; rr < 4; rr++) {
            float qd = q_s[(rg + rr * 32) * 132 + d];
#pragma unroll
            for (int j = 0; j < 16; j++) acc[rr][j] += qd * kvrow[j];
        }
    }
#pragma unroll
    for (int rr = 0; rr < 4; rr++) {
        int r = rg + rr * 32;
        float z = z_s[r];
#pragma unroll
        for (int j = 0; j < 16; j += 2) {
            __half2 hv = __floats2half2_rn(acc[rr][j] * z, acc[rr][j + 1] * z);
            *(__half2*)&att[(size_t)(b0 + r) * DIN + h * DHEAD + e0 + j] = hv;
        }
    }
}

// ---------------- launch -----------------------------------------------------------
extern "C" void kernel_launch(void* const* d_in, const int* in_sizes, int n_in,
                              void* d_out, int out_size)
{
    const float* x    = (const float*)d_in[0];
    const float* Wq   = (const float*)d_in[1];
    const float* Wk   = (const float*)d_in[2];
    const float* Wv   = (const float*)d_in[3];
    const float* Wo   = (const float*)d_in[4];
    const float* bo   = (const float*)d_in[5];
    const float* Wg   = (const float*)d_in[6];
    const float* bg   = (const float*)d_in[7];
    const float* Wout = (const float*)d_in[8];
    const float* bout = (const float*)d_in[9];
    float* out = (float*)d_out;

    __half *xh_, *att_, *opr_, *gt_;
    float  *q_, *k_, *v_, *op_;
    __half *wqT_, *wkT_, *wvT_, *woT_, *wgT_, *woutT_;
    cudaGetSymbolAddress((void**)&xh_,  g_xh);
    cudaGetSymbolAddress((void**)&q_,   g_q);
    cudaGetSymbolAddress((void**)&k_,   g_k);
    cudaGetSymbolAddress((void**)&v_,   g_v);
    cudaGetSymbolAddress((void**)&att_, g_att);
    cudaGetSymbolAddress((void**)&op_,  g_op);
    cudaGetSymbolAddress((void**)&opr_, g_opr);
    cudaGetSymbolAddress((void**)&gt_,  g_gt);
    cudaGetSymbolAddress((void**)&wqT_, g_wqT);
    cudaGetSymbolAddress((void**)&wkT_, g_wkT);
    cudaGetSymbolAddress((void**)&wvT_, g_wvT);
    cudaGetSymbolAddress((void**)&woT_, g_woT);
    cudaGetSymbolAddress((void**)&wgT_, g_wgT);
    cudaGetSymbolAddress((void**)&woutT_, g_woutT);

    cudaFuncSetAttribute(gemm_h<0>, cudaFuncAttributeMaxDynamicSharedMemorySize, GEMM_SMEM);
    cudaFuncSetAttribute(gemm_h<1>, cudaFuncAttributeMaxDynamicSharedMemorySize, GEMM_SMEM);
    cudaFuncSetAttribute(gemm_h<2>, cudaFuncAttributeMaxDynamicSharedMemorySize, GEMM_SMEM);
    cudaFuncSetAttribute(gemm_h<3>, cudaFuncAttributeMaxDynamicSharedMemorySize, GEMM_SMEM);
    cudaFuncSetAttribute(gemm_h<4>, cudaFuncAttributeMaxDynamicSharedMemorySize, GEMM_SMEM);

    const dim3 blk(256);
    const dim3 gN2048(DIN / BN, BATCH / BM);   // (8, 128)
    const dim3 gN512(DOUT / BN, BATCH / BM);   // (2, 128)
    const dim3 tblk(32, 8);

    // 0) operand prep
    half_copy<<<(BATCH * DIN) / 1024, 256>>>((const float4*)x, (__half2*)xh_);
    transpose_half<<<dim3(DIN / 32, DIN / 32), tblk>>>(Wq, wqT_, DIN, DIN);
    transpose_half<<<dim3(DIN / 32, DIN / 32), tblk>>>(Wk, wkT_, DIN, DIN);
    transpose_half<<<dim3(DIN / 32, DIN / 32), tblk>>>(Wv, wvT_, DIN, DIN);
    transpose_half<<<dim3(DIN / 32, DIN / 32), tblk>>>(Wo, woT_, DIN, DIN);
    transpose_half<<<dim3(DIN / 32, (2 * DIN) / 32), tblk>>>(Wg, wgT_, 2 * DIN, DIN);
    transpose_half<<<dim3(DOUT / 32, DIN / 32), tblk>>>(Wout, woutT_, DIN, DOUT);

    // 1-3) Q = feat(x@Wq), K = feat(x@Wk), V = x@Wv   (fp32 outputs)
    gemm_h<1><<<gN2048, blk, GEMM_SMEM>>>(xh_, xh_, DIN, DIN / BK, wqT_, DIN,
                                          nullptr, nullptr, nullptr, q_, nullptr, DIN);
    gemm_h<1><<<gN2048, blk, GEMM_SMEM>>>(xh_, xh_, DIN, DIN / BK, wkT_, DIN,
                                          nullptr, nullptr, nullptr, k_, nullptr, DIN);
    gemm_h<0><<<gN2048, blk, GEMM_SMEM>>>(xh_, xh_, DIN, DIN / BK, wvT_, DIN,
                                          nullptr, nullptr, nullptr, v_, nullptr, DIN);

    // 4-6) kv / ksum reductions (deterministic two-stage, fp32)
    kv_reduce<<<dim3(HEADS, KV_SPLIT), 256>>>(k_, v_);
    ksum_part<<<dim3(DIN / 256, KS_SPLIT), 256>>>(k_);
    kv_final<<<dim3((HEADS * DHEAD * DHEAD) / 256), 256>>>();

    // 7) attention (half output feeds Wo GEMM)
    size_t attn_smem = (size_t)(128 * 132 * 2 + 256) * sizeof(float);
    cudaFuncSetAttribute(attn_kernel, cudaFuncAttributeMaxDynamicSharedMemorySize,
                         (int)attn_smem);
    attn_kernel<<<dim3(BATCH / 128, HEADS), 256, attn_smem>>>(q_, att_);

    // 8) out_proj = att @ Wo + bo  (fp32 op + half opr)
    gemm_h<4><<<gN2048, blk, GEMM_SMEM>>>(att_, att_, DIN, DIN / BK, woT_, DIN,
                                          bo, nullptr, nullptr, op_, opr_, DIN);

    // 9) gate GEMM over concat [opr | xh]; blend exact op / x -> half gt
    gemm_h<3><<<gN2048, blk, GEMM_SMEM>>>(opr_, xh_, DIN, (2 * DIN) / BK, wgT_, 2 * DIN,
                                          bg, op_, x, nullptr, gt_, DIN);

    // 10) out = gt @ Wout + bout (fp32)
    gemm_h<2><<<gN512, blk, GEMM_SMEM>>>(gt_, gt_, DIN, DIN / BK, woutT_, DIN,
                                         bout, nullptr, nullptr, out, nullptr, DOUT);
}

// round 7
// speedup vs baseline: 4.4294x; 1.2271x over previous
#include <cuda_runtime.h>
#include <cuda_fp16.h>
#include <math.h>
#include <stdint.h>

// ---------------- problem dims (fixed) ----------------------------------------
#define BATCH 16384
#define DIN   2048
#define HEADS 16
#define DHEAD 128
#define DOUT  512
#define NQKV  (3 * DIN)                 // 6144

// ---------------- scratch (static device memory) ------------------------------
__device__ __half g_xh  [BATCH * DIN];           // half copy of x
__device__ float  g_qkv [(size_t)BATCH * NQKV];  // q|k|v fp32, row stride 6144
__device__ __half g_att [BATCH * DIN];
__device__ float  g_op  [BATCH * DIN];           // exact fp32 (for blend)
__device__ __half g_opr [BATCH * DIN];           // half copy (gate GEMM A)
__device__ __half g_gt  [BATCH * DIN];
__device__ float  g_kv  [HEADS * DHEAD * DHEAD];
__device__ float  g_ksum[HEADS * DHEAD];
#define KV_SPLIT 64
__device__ float g_kvpart[KV_SPLIT * HEADS * DHEAD * DHEAD];
__device__ float g_ksumpart[KV_SPLIT * DIN];
// transposed half weights [N][K]
__device__ __half g_wqkvT[NQKV * DIN];
__device__ __half g_woT  [DIN * DIN];
__device__ __half g_wgT  [DIN * 2 * DIN];
__device__ __half g_woutT[DOUT * DIN];

// ---------------- helpers -------------------------------------------------------
__device__ __forceinline__ uint32_t smem_u32(const void* p) {
    uint32_t a;
    asm("{ .reg .u64 t; cvta.to.shared.u64 t, %1; cvt.u32.u64 %0, t; }" : "=r"(a) : "l"(p));
    return a;
}
__device__ __forceinline__ void cp16(uint32_t dst, const void* src) {
    asm volatile("cp.async.cg.shared.global [%0], [%1], 16;" :: "r"(dst), "l"(src));
}
#define CP_COMMIT() asm volatile("cp.async.commit_group;" ::: "memory")
#define CP_WAIT(n)  asm volatile("cp.async.wait_group %0;" :: "n"(n) : "memory")

#define MMA_F16(d, A4, B2) \
    asm volatile("mma.sync.aligned.m16n8k16.row.col.f32.f16.f16.f32 " \
        "{%0,%1,%2,%3},{%4,%5,%6,%7},{%8,%9},{%0,%1,%2,%3};" \
        : "+f"((d)[0]), "+f"((d)[1]), "+f"((d)[2]), "+f"((d)[3]) \
        : "r"((A4)[0]), "r"((A4)[1]), "r"((A4)[2]), "r"((A4)[3]), \
          "r"((B2)[0]), "r"((B2)[1]))

#define LDSM_X4(r0, r1, r2, r3, addr) \
    asm volatile("ldmatrix.sync.aligned.m8n8.x4.shared.b16 {%0,%1,%2,%3}, [%4];" \
        : "=r"(r0), "=r"(r1), "=r"(r2), "=r"(r3) : "r"(addr))

// ---------------- GEMM config ----------------------------------------------------
// block 128x128, 8 warps (2M x 4N), warp tile 64x32, BK=64, 3 stages, 2 CTAs/SM.
// smem row stride 72 halves (144B): ldmatrix rows -> banks 4r%32, conflict-free.
#define BM 128
#define BN 128
#define BK 64
#define STAGES 3
#define ARS 72
#define BRS 72
#define ASTGH (BM * ARS)               // 9216 halves / stage (18KB)
#define BSTGH (BN * BRS)               // 9216 halves / stage (18KB)
#define GEMM_SMEM (STAGES * (ASTGH + BSTGH) * 2)   // 110592 bytes

// MODE 0: C=acc   1: C=relu(acc)+1e-4   2: C=acc+bias
// MODE 3: g=sigmoid(acc+bias); Ch=half(g*ep+(1-g)*ex)
// MODE 4: o=acc+bias; C=o; Ch=half(o)
// MODE 5: QKV fused: col<2*DIN -> relu(acc)+1e-4, else acc (fp32 C only)
template <int MODE>
__global__ void __launch_bounds__(256, 2) gemm_h(
    const __half* __restrict__ A0, const __half* __restrict__ A1, int K0, int nkt,
    const __half* __restrict__ B, int ldb,
    const float* __restrict__ bias,
    const float* __restrict__ ep, const float* __restrict__ ex,
    float* __restrict__ C, __half* __restrict__ Ch, int N)
{
    extern __shared__ __half smh[];
    __half* As = smh;
    __half* Bs = smh + STAGES * ASTGH;
    const uint32_t asu = smem_u32(As);
    const uint32_t bsu = smem_u32(Bs);

    const int tid  = threadIdx.x;
    const int bm   = blockIdx.y * BM;
    const int bn   = blockIdx.x * BN;
    const int wid  = tid >> 5, lane = tid & 31;
    const int wm   = (wid >> 2) * 64;      // 2 warps along M
    const int wn   = (wid & 3) * 32;       // 4 warps along N

    const uint32_t a_lane = (uint32_t)(((lane & 15) * ARS + (lane >> 4) * 8) * 2);
    const uint32_t b_lane = (uint32_t)(((((lane >> 4) << 3) + (lane & 7)) * BRS
                                        + ((lane >> 3) & 1) * 8) * 2);

    float acc[4][4][4];
#pragma unroll
    for (int mt = 0; mt < 4; mt++)
#pragma unroll
        for (int nt = 0; nt < 4; nt++)
#pragma unroll
            for (int e = 0; e < 4; e++) acc[mt][nt][e] = 0.0f;

    auto issue = [&](int kt) {
        const int s = kt % STAGES;
        const int kbase = kt * BK;
        const __half* Aptr;
        int kc;
        if (kbase < K0) { Aptr = A0; kc = kbase; }
        else            { Aptr = A1; kc = kbase - K0; }
        // A tile 128 x 64 halves : 1024 groups of 8 halves, 4 per thread
#pragma unroll
        for (int i = 0; i < 4; i++) {
            int idx = tid + i * 256;
            int r = idx >> 3, g = idx & 7;
            uint32_t dst = asu + (uint32_t)(s * ASTGH + r * ARS + g * 8) * 2u;
            cp16(dst, Aptr + (size_t)(bm + r) * DIN + kc + g * 8);
        }
        // B tile 128 x 64 halves ([n][k]), 4 per thread
#pragma unroll
        for (int i = 0; i < 4; i++) {
            int idx = tid + i * 256;
            int r = idx >> 3, g = idx & 7;
            uint32_t dst = bsu + (uint32_t)(s * BSTGH + r * BRS + g * 8) * 2u;
            cp16(dst, B + (size_t)(bn + r) * ldb + kbase + g * 8);
        }
    };

#pragma unroll
    for (int kt = 0; kt < STAGES - 1; kt++) {
        if (kt < nkt) issue(kt);
        CP_COMMIT();
    }

    for (int kt = 0; kt < nkt; kt++) {
        CP_WAIT(STAGES - 2);
        __syncthreads();

        if (kt + STAGES - 1 < nkt) issue(kt + STAGES - 1);
        CP_COMMIT();

        const int s = kt % STAGES;
        const uint32_t abase = asu + (uint32_t)(s * ASTGH + wm * ARS) * 2u + a_lane;
        const uint32_t bbase = bsu + (uint32_t)(s * BSTGH + wn * BRS) * 2u + b_lane;

#pragma unroll
        for (int kc = 0; kc < 4; kc++) {
            uint32_t a[4][4], b[4][2];
            const uint32_t ko = (uint32_t)(kc * 32);   // 16 halves = 32 bytes
#pragma unroll
            for (int mt = 0; mt < 4; mt++)
                LDSM_X4(a[mt][0], a[mt][1], a[mt][2], a[mt][3],
                        abase + (uint32_t)(mt * 16 * ARS * 2) + ko);
#pragma unroll
            for (int p = 0; p < 2; p++)
                LDSM_X4(b[2 * p][0], b[2 * p][1], b[2 * p + 1][0], b[2 * p + 1][1],
                        bbase + (uint32_t)(p * 16 * BRS * 2) + ko);
#pragma unroll
            for (int mt = 0; mt < 4; mt++)
#pragma unroll
                for (int nt = 0; nt < 4; nt++)
                    MMA_F16(acc[mt][nt], a[mt], b[nt]);
        }
    }

    // ---- epilogue: direct register writes ----
    const int lr = lane >> 2, lc = lane & 3;
#pragma unroll
    for (int mt = 0; mt < 4; mt++) {
#pragma unroll
        for (int nt = 0; nt < 4; nt++) {
#pragma unroll
            for (int h = 0; h < 2; h++) {
                const int gr = bm + wm + mt * 16 + lr + h * 8;
                const int gc = bn + wn + nt * 8 + 2 * lc;
                const size_t gi = (size_t)gr * N + gc;
                float v0 = acc[mt][nt][h * 2 + 0];
                float v1 = acc[mt][nt][h * 2 + 1];
                if constexpr (MODE == 1) {
                    v0 = fmaxf(v0, 0.f) + 1e-4f;
                    v1 = fmaxf(v1, 0.f) + 1e-4f;
                    *(float2*)&C[gi] = make_float2(v0, v1);
                } else if constexpr (MODE == 0) {
                    *(float2*)&C[gi] = make_float2(v0, v1);
                } else if constexpr (MODE == 2) {
                    v0 += bias[gc]; v1 += bias[gc + 1];
                    *(float2*)&C[gi] = make_float2(v0, v1);
                } else if constexpr (MODE == 3) {
                    v0 += bias[gc]; v1 += bias[gc + 1];
                    const float g0 = 1.f / (1.f + expf(-v0));
                    const float g1 = 1.f / (1.f + expf(-v1));
                    const float2 e2 = *(const float2*)&ep[gi];
                    const float2 x2 = *(const float2*)&ex[gi];
                    const float r0 = g0 * e2.x + (1.f - g0) * x2.x;
                    const float r1 = g1 * e2.y + (1.f - g1) * x2.y;
                    *(__half2*)&Ch[gi] = __floats2half2_rn(r0, r1);
                } else if constexpr (MODE == 4) {
                    v0 += bias[gc]; v1 += bias[gc + 1];
                    *(float2*)&C[gi] = make_float2(v0, v1);
                    *(__half2*)&Ch[gi] = __floats2half2_rn(v0, v1);
                } else {  // MODE 5: fused QKV
                    if (gc < 2 * DIN) {
                        v0 = fmaxf(v0, 0.f) + 1e-4f;
                        v1 = fmaxf(v1, 0.f) + 1e-4f;
                    }
                    *(float2*)&C[gi] = make_float2(v0, v1);
                }
            }
        }
    }
}

// ---------------- fp32 -> half copy ----------------------------------------------
__global__ void half_copy(const float4* __restrict__ s, __half2* __restrict__ d)
{
    const int i = blockIdx.x * 256 + threadIdx.x;
    float4 v = s[i];
    d[2 * i]     = __floats2half2_rn(v.x, v.y);
    d[2 * i + 1] = __floats2half2_rn(v.z, v.w);
}

// ---------------- transpose + convert: WT[n][k] = half(W[k][n]) -------------------
__global__ void transpose_half(const float* __restrict__ S, __half* __restrict__ D,
                               int K, int N)
{
    __shared__ float t[32][33];
    const int bn = blockIdx.x * 32, bk = blockIdx.y * 32;
    const int tx = threadIdx.x, ty = threadIdx.y;
#pragma unroll
    for (int i = 0; i < 32; i += 8)
        t[ty + i][tx] = S[(size_t)(bk + ty + i) * N + bn + tx];
    __syncthreads();
#pragma unroll
    for (int i = 0; i < 32; i += 8)
        D[(size_t)(bn + ty + i) * K + bk + tx] = __float2half_rn(t[tx][ty + i]);
}

// ---------------- KV + ksum partial reduction (fp32, cp.async double-buffered) ----
__global__ void __launch_bounds__(256) kv_reduce(const float* __restrict__ qkv)
{
    __shared__ float ks[2][8][128];
    __shared__ float vs[2][8][128];
    __shared__ float ksum_s[2][128];

    const int h = blockIdx.x;
    const int chunk = blockIdx.y;
    const int b0 = chunk * (BATCH / KV_SPLIT);     // 256 rows
    const int tid = threadIdx.x;
    const int d0 = (tid >> 4) * 8;
    const int e0 = (tid & 15) * 8;
    const int kc = tid & 127;                      // ksum column
    const int rb = tid >> 7;                       // 0/1: ksum row-block

    const float* kbase = qkv + 2048 + h * DHEAD;   // k columns
    const float* vbase = qkv + 4096 + h * DHEAD;   // v columns

    const uint32_t ksu = smem_u32(&ks[0][0][0]);
    const uint32_t vsu = smem_u32(&vs[0][0][0]);

    auto load = [&](int buf, int bb) {
        int r = tid >> 5, c4 = (tid & 31) << 2;
        size_t row = (size_t)(b0 + bb + r) * NQKV;
        cp16(ksu + (uint32_t)(buf * 1024 + r * 128 + c4) * 4u, kbase + row + c4);
        cp16(vsu + (uint32_t)(buf * 1024 + r * 128 + c4) * 4u, vbase + row + c4);
    };

    float acc[8][8] = {};
    float ksacc = 0.0f;

    load(0, 0);
    CP_COMMIT();

    for (int bb = 0; bb < (BATCH / KV_SPLIT); bb += 8) {
        const int buf = (bb >> 3) & 1;
        if (bb + 8 < (BATCH / KV_SPLIT)) load(buf ^ 1, bb + 8);
        CP_COMMIT();
        CP_WAIT(1);
        __syncthreads();
#pragma unroll
        for (int r = 0; r < 8; r++) {
            float kr[8], vr[8];
#pragma unroll
            for (int i = 0; i < 8; i++) { kr[i] = ks[buf][r][d0 + i]; vr[i] = vs[buf][r][e0 + i]; }
#pragma unroll
            for (int i = 0; i < 8; i++)
#pragma unroll
                for (int j = 0; j < 8; j++) acc[i][j] += kr[i] * vr[j];
        }
#pragma unroll
        for (int rr = 0; rr < 4; rr++) ksacc += ks[buf][rb * 4 + rr][kc];
        __syncthreads();
    }

    float* dst = g_kvpart + (size_t)chunk * (HEADS * DHEAD * DHEAD) + h * DHEAD * DHEAD;
#pragma unroll
    for (int i = 0; i < 8; i++)
#pragma unroll
        for (int j = 0; j < 8; j++) dst[(d0 + i) * DHEAD + e0 + j] = acc[i][j];

    ksum_s[rb][kc] = ksacc;
    __syncthreads();
    if (tid < 128)
        g_ksumpart[chunk * DIN + h * DHEAD + tid] = ksum_s[0][tid] + ksum_s[1][tid];
}

// ---------------- final reductions (deterministic) ---------------------------------
__global__ void kv_final()
{
    int i = blockIdx.x * 256 + threadIdx.x;
    float s = 0.0f;
    for (int c = 0; c < KV_SPLIT; c++) s += g_kvpart[(size_t)c * (HEADS * DHEAD * DHEAD) + i];
    g_kv[i] = s;
    if (i < DIN) {
        float t = 0.0f;
        for (int c = 0; c < KV_SPLIT; c++) t += g_ksumpart[c * DIN + i];
        g_ksum[i] = t;
    }
}

// ---------------- attention (fp32 compute; half output) ---------------------------
__global__ void __launch_bounds__(256) attn_kernel(const float* __restrict__ qkv,
                                                   __half* __restrict__ att)
{
    extern __shared__ float smx[];
    float* kv_s   = smx;
    float* q_s    = smx + 128 * 132;
    float* ksum_s = q_s + 128 * 132;
    float* z_s    = ksum_s + 128;

    const int h  = blockIdx.y;
    const int b0 = blockIdx.x * 128;
    const int tid = threadIdx.x;
    const float* q = qkv + h * DHEAD;              // q columns, row stride NQKV

    const float* kvh = g_kv + h * DHEAD * DHEAD;
    for (int i = tid; i < DHEAD * DHEAD; i += 256) {
        int d = i >> 7, e = i & 127;
        kv_s[d * 132 + e] = kvh[i];
    }
    for (int i = tid; i < 128 * 32; i += 256) {
        int r = i >> 5;
        int c4 = (i & 31) << 2;
        *reinterpret_cast<float4*>(&q_s[r * 132 + c4]) =
            *reinterpret_cast<const float4*>(q + (size_t)(b0 + r) * NQKV + c4);
    }
    if (tid < 128) ksum_s[tid] = g_ksum[h * DHEAD + tid];
    __syncthreads();

    {
        int r = tid >> 1, half_ = tid & 1;
        float s = 0.0f;
        int dbase = half_ * 64;
        for (int d = 0; d < 64; d++) s += q_s[r * 132 + dbase + d] * ksum_s[dbase + d];
        s += __shfl_xor_sync(0xffffffffu, s, 1);
        if (half_ == 0) z_s[r] = 1.0f / (s + 1e-6f);
    }
    __syncthreads();

    const int rg = tid >> 3;
    const int e0 = (tid & 7) * 16;
    float acc[4][16] = {};
    for (int d = 0; d < 128; d++) {
        float kvrow[16];
#pragma unroll
        for (int j = 0; j < 16; j += 4) {
            float4 f = *reinterpret_cast<float4*>(&kv_s[d * 132 + e0 + j]);
            kvrow[j] = f.x; kvrow[j + 1] = f.y; kvrow[j + 2] = f.z; kvrow[j + 3] = f.w;
        }
#pragma unroll
        for (int rr = 0; rr < 4; rr++) {
            float qd = q_s[(rg + rr * 32) * 132 + d];
#pragma unroll
            for (int j = 0; j < 16; j++) acc[rr][j] += qd * kvrow[j];
        }
    }
#pragma unroll
    for (int rr = 0; rr < 4; rr++) {
        int r = rg + rr * 32;
        float z = z_s[r];
#pragma unroll
        for (int j = 0; j < 16; j += 2) {
            __half2 hv = __floats2half2_rn(acc[rr][j] * z, acc[rr][j + 1] * z);
            *(__half2*)&att[(size_t)(b0 + r) * DIN + h * DHEAD + e0 + j] = hv;
        }
    }
}

// ---------------- launch -----------------------------------------------------------
extern "C" void kernel_launch(void* const* d_in, const int* in_sizes, int n_in,
                              void* d_out, int out_size)
{
    const float* x    = (const float*)d_in[0];
    const float* Wq   = (const float*)d_in[1];
    const float* Wk   = (const float*)d_in[2];
    const float* Wv   = (const float*)d_in[3];
    const float* Wo   = (const float*)d_in[4];
    const float* bo   = (const float*)d_in[5];
    const float* Wg   = (const float*)d_in[6];
    const float* bg   = (const float*)d_in[7];
    const float* Wout = (const float*)d_in[8];
    const float* bout = (const float*)d_in[9];
    float* out = (float*)d_out;

    __half *xh_, *att_, *opr_, *gt_;
    float  *qkv_, *op_;
    __half *wqkvT_, *woT_, *wgT_, *woutT_;
    cudaGetSymbolAddress((void**)&xh_,    g_xh);
    cudaGetSymbolAddress((void**)&qkv_,   g_qkv);
    cudaGetSymbolAddress((void**)&att_,   g_att);
    cudaGetSymbolAddress((void**)&op_,    g_op);
    cudaGetSymbolAddress((void**)&opr_,   g_opr);
    cudaGetSymbolAddress((void**)&gt_,    g_gt);
    cudaGetSymbolAddress((void**)&wqkvT_, g_wqkvT);
    cudaGetSymbolAddress((void**)&woT_,   g_woT);
    cudaGetSymbolAddress((void**)&wgT_,   g_wgT);
    cudaGetSymbolAddress((void**)&woutT_, g_woutT);

    cudaFuncSetAttribute(gemm_h<2>, cudaFuncAttributeMaxDynamicSharedMemorySize, GEMM_SMEM);
    cudaFuncSetAttribute(gemm_h<3>, cudaFuncAttributeMaxDynamicSharedMemorySize, GEMM_SMEM);
    cudaFuncSetAttribute(gemm_h<4>, cudaFuncAttributeMaxDynamicSharedMemorySize, GEMM_SMEM);
    cudaFuncSetAttribute(gemm_h<5>, cudaFuncAttributeMaxDynamicSharedMemorySize, GEMM_SMEM);

    const dim3 blk(256);
    const dim3 tblk(32, 8);

    // launches 0-4: prep (order chosen so launch #5 = fused QKV GEMM for ncu -s 5)
    half_copy<<<(BATCH * DIN) / 1024, 256>>>((const float4*)x, (__half2*)xh_);         // 0
    transpose_half<<<dim3(DIN / 32, DIN / 32), tblk>>>(Wq, wqkvT_, DIN, DIN);          // 1
    transpose_half<<<dim3(DIN / 32, DIN / 32), tblk>>>(Wk, wqkvT_ + (size_t)DIN * DIN, DIN, DIN);       // 2
    transpose_half<<<dim3(DIN / 32, DIN / 32), tblk>>>(Wv, wqkvT_ + (size_t)2 * DIN * DIN, DIN, DIN);   // 3
    transpose_half<<<dim3(DIN / 32, DIN / 32), tblk>>>(Wo, woT_, DIN, DIN);            // 4

    // 5: fused QKV GEMM: qkv = x @ [Wq|Wk|Wv], relu-feature on q,k columns
    gemm_h<5><<<dim3(NQKV / BN, BATCH / BM), blk, GEMM_SMEM>>>(
        xh_, xh_, DIN, DIN / BK, wqkvT_, DIN,
        nullptr, nullptr, nullptr, qkv_, nullptr, NQKV);

    transpose_half<<<dim3(DIN / 32, (2 * DIN) / 32), tblk>>>(Wg, wgT_, 2 * DIN, DIN);  // 6
    transpose_half<<<dim3(DOUT / 32, DIN / 32), tblk>>>(Wout, woutT_, DIN, DOUT);      // 7

    // kv + ksum partials, then final reduce (deterministic)
    kv_reduce<<<dim3(HEADS, KV_SPLIT), 256>>>(qkv_);
    kv_final<<<dim3((HEADS * DHEAD * DHEAD) / 256), 256>>>();

    // attention (half output feeds Wo GEMM)
    size_t attn_smem = (size_t)(128 * 132 * 2 + 256) * sizeof(float);
    cudaFuncSetAttribute(attn_kernel, cudaFuncAttributeMaxDynamicSharedMemorySize,
                         (int)attn_smem);
    attn_kernel<<<dim3(BATCH / 128, HEADS), 256, attn_smem>>>(qkv_, att_);

    // out_proj = att @ Wo + bo (fp32 op + half opr)
    gemm_h<4><<<dim3(DIN / BN, BATCH / BM), blk, GEMM_SMEM>>>(
        att_, att_, DIN, DIN / BK, woT_, DIN,
        bo, nullptr, nullptr, op_, opr_, DIN);

    // gate GEMM over concat [opr | xh]; blend exact op / x -> half gt
    gemm_h<3><<<dim3(DIN / BN, BATCH / BM), blk, GEMM_SMEM>>>(
        opr_, xh_, DIN, (2 * DIN) / BK, wgT_, 2 * DIN,
        bg, op_, x, nullptr, gt_, DIN);

    // out = gt @ Wout + bout (fp32)
    gemm_h<2><<<dim3(DOUT / BN, BATCH / BM), blk, GEMM_SMEM>>>(
        gt_, gt_, DIN, DIN / BK, woutT_, DIN,
        bout, nullptr, nullptr, out, nullptr, DOUT);
}

// round 8
// speedup vs baseline: 4.4379x; 1.0019x over previous
#include <cuda_runtime.h>
#include <cuda_fp16.h>
#include <math.h>
#include <stdint.h>

// ---------------- problem dims (fixed) ----------------------------------------
#define BATCH 16384
#define DIN   2048
#define HEADS 16
#define DHEAD 128
#define DOUT  512
#define NQKV  (3 * DIN)                 // 6144

// ---------------- scratch (static device memory) ------------------------------
__device__ __half g_xh  [BATCH * DIN];            // half copy of x
__device__ __half g_qkvh[(size_t)BATCH * NQKV];   // q|k|v half, row stride 6144
__device__ __half g_att [BATCH * DIN];
__device__ float  g_op  [BATCH * DIN];            // exact fp32 (for blend)
__device__ __half g_opr [BATCH * DIN];            // half copy (gate GEMM A)
__device__ __half g_gt  [BATCH * DIN];
__device__ float  g_kv  [HEADS * DHEAD * DHEAD];
__device__ float  g_ksum[HEADS * DHEAD];
#define KV_SPLIT 64
__device__ float g_kvpart[KV_SPLIT * HEADS * DHEAD * DHEAD];
__device__ float g_ksumpart[KV_SPLIT * DIN];
// transposed half weights [N][K]
__device__ __half g_wqkvT[NQKV * DIN];
__device__ __half g_woT  [DIN * DIN];
__device__ __half g_wgT  [DIN * 2 * DIN];
__device__ __half g_woutT[DOUT * DIN];

// ---------------- helpers -------------------------------------------------------
__device__ __forceinline__ uint32_t smem_u32(const void* p) {
    uint32_t a;
    asm("{ .reg .u64 t; cvta.to.shared.u64 t, %1; cvt.u32.u64 %0, t; }" : "=r"(a) : "l"(p));
    return a;
}
__device__ __forceinline__ void cp16(uint32_t dst, const void* src) {
    asm volatile("cp.async.cg.shared.global [%0], [%1], 16;" :: "r"(dst), "l"(src));
}
#define CP_COMMIT() asm volatile("cp.async.commit_group;" ::: "memory")
#define CP_WAIT(n)  asm volatile("cp.async.wait_group %0;" :: "n"(n) : "memory")

#define MMA_F16(d, A4, B2) \
    asm volatile("mma.sync.aligned.m16n8k16.row.col.f32.f16.f16.f32 " \
        "{%0,%1,%2,%3},{%4,%5,%6,%7},{%8,%9},{%0,%1,%2,%3};" \
        : "+f"((d)[0]), "+f"((d)[1]), "+f"((d)[2]), "+f"((d)[3]) \
        : "r"((A4)[0]), "r"((A4)[1]), "r"((A4)[2]), "r"((A4)[3]), \
          "r"((B2)[0]), "r"((B2)[1]))

#define LDSM_X4(r0, r1, r2, r3, addr) \
    asm volatile("ldmatrix.sync.aligned.m8n8.x4.shared.b16 {%0,%1,%2,%3}, [%4];" \
        : "=r"(r0), "=r"(r1), "=r"(r2), "=r"(r3) : "r"(addr))

// ---------------- GEMM config ----------------------------------------------------
// block 128x128, 8 warps (2M x 4N), warp tile 64x32, BK=64, 3 stages, 2 CTAs/SM.
#define BM 128
#define BN 128
#define BK 64
#define STAGES 3
#define ARS 72
#define BRS 72
#define ASTGH (BM * ARS)
#define BSTGH (BN * BRS)
#define GEMM_SMEM (STAGES * (ASTGH + BSTGH) * 2)   // 110592 bytes

// MODE 2: C=acc+bias (fp32)
// MODE 3: g=sigmoid(acc+bias); Ch=half(g*ep+(1-g)*ex)
// MODE 4: o=acc+bias; C=o; Ch=half(o)
// MODE 5: QKV fused: col<2*DIN -> relu(acc)+1e-4, else acc; Ch=half
template <int MODE>
__global__ void __launch_bounds__(256, 2) gemm_h(
    const __half* __restrict__ A0, const __half* __restrict__ A1, int K0, int nkt,
    const __half* __restrict__ B, int ldb,
    const float* __restrict__ bias,
    const float* __restrict__ ep, const float* __restrict__ ex,
    float* __restrict__ C, __half* __restrict__ Ch, int N)
{
    extern __shared__ __half smh[];
    __half* As = smh;
    __half* Bs = smh + STAGES * ASTGH;
    const uint32_t asu = smem_u32(As);
    const uint32_t bsu = smem_u32(Bs);

    const int tid  = threadIdx.x;
    const int bm   = blockIdx.y * BM;
    const int bn   = blockIdx.x * BN;
    const int wid  = tid >> 5, lane = tid & 31;
    const int wm   = (wid >> 2) * 64;
    const int wn   = (wid & 3) * 32;

    const uint32_t a_lane = (uint32_t)(((lane & 15) * ARS + (lane >> 4) * 8) * 2);
    const uint32_t b_lane = (uint32_t)(((((lane >> 4) << 3) + (lane & 7)) * BRS
                                        + ((lane >> 3) & 1) * 8) * 2);

    float acc[4][4][4];
#pragma unroll
    for (int mt = 0; mt < 4; mt++)
#pragma unroll
        for (int nt = 0; nt < 4; nt++)
#pragma unroll
            for (int e = 0; e < 4; e++) acc[mt][nt][e] = 0.0f;

    auto issue = [&](int kt) {
        const int s = kt % STAGES;
        const int kbase = kt * BK;
        const __half* Aptr;
        int kc;
        if (kbase < K0) { Aptr = A0; kc = kbase; }
        else            { Aptr = A1; kc = kbase - K0; }
#pragma unroll
        for (int i = 0; i < 4; i++) {
            int idx = tid + i * 256;
            int r = idx >> 3, g = idx & 7;
            uint32_t dst = asu + (uint32_t)(s * ASTGH + r * ARS + g * 8) * 2u;
            cp16(dst, Aptr + (size_t)(bm + r) * DIN + kc + g * 8);
        }
#pragma unroll
        for (int i = 0; i < 4; i++) {
            int idx = tid + i * 256;
            int r = idx >> 3, g = idx & 7;
            uint32_t dst = bsu + (uint32_t)(s * BSTGH + r * BRS + g * 8) * 2u;
            cp16(dst, B + (size_t)(bn + r) * ldb + kbase + g * 8);
        }
    };

#pragma unroll
    for (int kt = 0; kt < STAGES - 1; kt++) {
        if (kt < nkt) issue(kt);
        CP_COMMIT();
    }

    for (int kt = 0; kt < nkt; kt++) {
        CP_WAIT(STAGES - 2);
        __syncthreads();

        if (kt + STAGES - 1 < nkt) issue(kt + STAGES - 1);
        CP_COMMIT();

        const int s = kt % STAGES;
        const uint32_t abase = asu + (uint32_t)(s * ASTGH + wm * ARS) * 2u + a_lane;
        const uint32_t bbase = bsu + (uint32_t)(s * BSTGH + wn * BRS) * 2u + b_lane;

#pragma unroll
        for (int kc = 0; kc < 4; kc++) {
            uint32_t a[4][4], b[4][2];
            const uint32_t ko = (uint32_t)(kc * 32);
#pragma unroll
            for (int mt = 0; mt < 4; mt++)
                LDSM_X4(a[mt][0], a[mt][1], a[mt][2], a[mt][3],
                        abase + (uint32_t)(mt * 16 * ARS * 2) + ko);
#pragma unroll
            for (int p = 0; p < 2; p++)
                LDSM_X4(b[2 * p][0], b[2 * p][1], b[2 * p + 1][0], b[2 * p + 1][1],
                        bbase + (uint32_t)(p * 16 * BRS * 2) + ko);
#pragma unroll
            for (int mt = 0; mt < 4; mt++)
#pragma unroll
                for (int nt = 0; nt < 4; nt++)
                    MMA_F16(acc[mt][nt], a[mt], b[nt]);
        }
    }

    // ---- epilogue ----
    const int lr = lane >> 2, lc = lane & 3;
#pragma unroll
    for (int mt = 0; mt < 4; mt++) {
#pragma unroll
        for (int nt = 0; nt < 4; nt++) {
#pragma unroll
            for (int h = 0; h < 2; h++) {
                const int gr = bm + wm + mt * 16 + lr + h * 8;
                const int gc = bn + wn + nt * 8 + 2 * lc;
                const size_t gi = (size_t)gr * N + gc;
                float v0 = acc[mt][nt][h * 2 + 0];
                float v1 = acc[mt][nt][h * 2 + 1];
                if constexpr (MODE == 2) {
                    v0 += bias[gc]; v1 += bias[gc + 1];
                    *(float2*)&C[gi] = make_float2(v0, v1);
                } else if constexpr (MODE == 3) {
                    v0 += bias[gc]; v1 += bias[gc + 1];
                    const float g0 = 1.f / (1.f + expf(-v0));
                    const float g1 = 1.f / (1.f + expf(-v1));
                    const float2 e2 = *(const float2*)&ep[gi];
                    const float2 x2 = *(const float2*)&ex[gi];
                    const float r0 = g0 * e2.x + (1.f - g0) * x2.x;
                    const float r1 = g1 * e2.y + (1.f - g1) * x2.y;
                    *(__half2*)&Ch[gi] = __floats2half2_rn(r0, r1);
                } else if constexpr (MODE == 4) {
                    v0 += bias[gc]; v1 += bias[gc + 1];
                    *(float2*)&C[gi] = make_float2(v0, v1);
                    *(__half2*)&Ch[gi] = __floats2half2_rn(v0, v1);
                } else {  // MODE 5: fused QKV -> half
                    if (gc < 2 * DIN) {
                        v0 = fmaxf(v0, 0.f) + 1e-4f;
                        v1 = fmaxf(v1, 0.f) + 1e-4f;
                    }
                    *(__half2*)&Ch[gi] = __floats2half2_rn(v0, v1);
                }
            }
        }
    }
}

// ---------------- fp32 -> half copy ----------------------------------------------
__global__ void half_copy(const float4* __restrict__ s, __half2* __restrict__ d)
{
    const int i = blockIdx.x * 256 + threadIdx.x;
    float4 v = s[i];
    d[2 * i]     = __floats2half2_rn(v.x, v.y);
    d[2 * i + 1] = __floats2half2_rn(v.z, v.w);
}

// ---------------- transpose + convert: WT[n][k] = half(W[k][n]) -------------------
__global__ void transpose_half(const float* __restrict__ S, __half* __restrict__ D,
                               int K, int N)
{
    __shared__ float t[32][33];
    const int bn = blockIdx.x * 32, bk = blockIdx.y * 32;
    const int tx = threadIdx.x, ty = threadIdx.y;
#pragma unroll
    for (int i = 0; i < 32; i += 8)
        t[ty + i][tx] = S[(size_t)(bk + ty + i) * N + bn + tx];
    __syncthreads();
#pragma unroll
    for (int i = 0; i < 32; i += 8)
        D[(size_t)(bn + ty + i) * K + bk + tx] = __float2half_rn(t[tx][ty + i]);
}

// ---------------- KV + ksum partial reduction (half in, fp32 accum) ----------------
__global__ void __launch_bounds__(256) kv_reduce(const __half* __restrict__ qkv)
{
    __shared__ __half ks[2][8][128];
    __shared__ __half vs[2][8][128];
    __shared__ float ksum_s[2][128];

    const int h = blockIdx.x;
    const int chunk = blockIdx.y;
    const int b0 = chunk * (BATCH / KV_SPLIT);     // 256 rows
    const int tid = threadIdx.x;
    const int d0 = (tid >> 4) * 8;
    const int e0 = (tid & 15) * 8;
    const int kc = tid & 127;
    const int rb = tid >> 7;

    const __half* kbase = qkv + 2048 + h * DHEAD;
    const __half* vbase = qkv + 4096 + h * DHEAD;

    const uint32_t ksu = smem_u32(&ks[0][0][0]);
    const uint32_t vsu = smem_u32(&vs[0][0][0]);

    // threads 0-127 load k (8 rows x 16 chunks of 8 halves), 128-255 load v
    auto load = [&](int buf, int bb) {
        const int t = tid & 127;
        const int r = t >> 4, g = t & 15;
        const size_t row = (size_t)(b0 + bb + r) * NQKV;
        if (tid < 128)
            cp16(ksu + (uint32_t)(buf * 2048 + r * 256 + g * 16), kbase + row + g * 8);
        else
            cp16(vsu + (uint32_t)(buf * 2048 + r * 256 + g * 16), vbase + row + g * 8);
    };

    float acc[8][8] = {};
    float ksacc = 0.0f;

    load(0, 0);
    CP_COMMIT();

    for (int bb = 0; bb < (BATCH / KV_SPLIT); bb += 8) {
        const int buf = (bb >> 3) & 1;
        if (bb + 8 < (BATCH / KV_SPLIT)) load(buf ^ 1, bb + 8);
        CP_COMMIT();
        CP_WAIT(1);
        __syncthreads();
#pragma unroll
        for (int r = 0; r < 8; r++) {
            float kr[8], vr[8];
#pragma unroll
            for (int i = 0; i < 8; i += 2) {
                float2 kf = __half22float2(*(const __half2*)&ks[buf][r][d0 + i]);
                float2 vf = __half22float2(*(const __half2*)&vs[buf][r][e0 + i]);
                kr[i] = kf.x; kr[i + 1] = kf.y;
                vr[i] = vf.x; vr[i + 1] = vf.y;
            }
#pragma unroll
            for (int i = 0; i < 8; i++)
#pragma unroll
                for (int j = 0; j < 8; j++) acc[i][j] += kr[i] * vr[j];
        }
#pragma unroll
        for (int rr = 0; rr < 4; rr++) ksacc += __half2float(ks[buf][rb * 4 + rr][kc]);
        __syncthreads();
    }

    float* dst = g_kvpart + (size_t)chunk * (HEADS * DHEAD * DHEAD) + h * DHEAD * DHEAD;
#pragma unroll
    for (int i = 0; i < 8; i++)
#pragma unroll
        for (int j = 0; j < 8; j++) dst[(d0 + i) * DHEAD + e0 + j] = acc[i][j];

    ksum_s[rb][kc] = ksacc;
    __syncthreads();
    if (tid < 128)
        g_ksumpart[chunk * DIN + h * DHEAD + tid] = ksum_s[0][tid] + ksum_s[1][tid];
}

// ---------------- final reductions (deterministic) ---------------------------------
__global__ void kv_final()
{
    int i = blockIdx.x * 256 + threadIdx.x;
    float s = 0.0f;
    for (int c = 0; c < KV_SPLIT; c++) s += g_kvpart[(size_t)c * (HEADS * DHEAD * DHEAD) + i];
    g_kv[i] = s;
    if (i < DIN) {
        float t = 0.0f;
        for (int c = 0; c < KV_SPLIT; c++) t += g_ksumpart[c * DIN + i];
        g_ksum[i] = t;
    }
}

// ---------------- attention (half q in; fp32 compute; half out) --------------------
__global__ void __launch_bounds__(256) attn_kernel(const __half* __restrict__ qkv,
                                                   __half* __restrict__ att)
{
    extern __shared__ float smx[];
    float* kv_s   = smx;
    float* q_s    = smx + 128 * 132;
    float* ksum_s = q_s + 128 * 132;
    float* z_s    = ksum_s + 128;

    const int h  = blockIdx.y;
    const int b0 = blockIdx.x * 128;
    const int tid = threadIdx.x;
    const __half* q = qkv + h * DHEAD;             // q columns, row stride NQKV

    const float* kvh = g_kv + h * DHEAD * DHEAD;
    for (int i = tid; i < DHEAD * DHEAD; i += 256) {
        int d = i >> 7, e = i & 127;
        kv_s[d * 132 + e] = kvh[i];
    }
    for (int i = tid; i < 128 * 16; i += 256) {    // 128 rows x 16 chunks of 8 halves
        int r = i >> 4, g = i & 15;
        uint4 raw = *(const uint4*)(q + (size_t)(b0 + r) * NQKV + g * 8);
        const __half2* hp = (const __half2*)&raw;
        float* dstq = &q_s[r * 132 + g * 8];
#pragma unroll
        for (int j = 0; j < 4; j++) {
            float2 f = __half22float2(hp[j]);
            dstq[2 * j] = f.x; dstq[2 * j + 1] = f.y;
        }
    }
    if (tid < 128) ksum_s[tid] = g_ksum[h * DHEAD + tid];
    __syncthreads();

    {
        int r = tid >> 1, half_ = tid & 1;
        float s = 0.0f;
        int dbase = half_ * 64;
        for (int d = 0; d < 64; d++) s += q_s[r * 132 + dbase + d] * ksum_s[dbase + d];
        s += __shfl_xor_sync(0xffffffffu, s, 1);
        if (half_ == 0) z_s[r] = 1.0f / (s + 1e-6f);
    }
    __syncthreads();

    const int rg = tid >> 3;
    const int e0 = (tid & 7) * 16;
    float acc[4][16] = {};
    for (int d = 0; d < 128; d++) {
        float kvrow[16];
#pragma unroll
        for (int j = 0; j < 16; j += 4) {
            float4 f = *reinterpret_cast<float4*>(&kv_s[d * 132 + e0 + j]);
            kvrow[j] = f.x; kvrow[j + 1] = f.y; kvrow[j + 2] = f.z; kvrow[j + 3] = f.w;
        }
#pragma unroll
        for (int rr = 0; rr < 4; rr++) {
            float qd = q_s[(rg + rr * 32) * 132 + d];
#pragma unroll
            for (int j = 0; j < 16; j++) acc[rr][j] += qd * kvrow[j];
        }
    }
#pragma unroll
    for (int rr = 0; rr < 4; rr++) {
        int r = rg + rr * 32;
        float z = z_s[r];
#pragma unroll
        for (int j = 0; j < 16; j += 2) {
            __half2 hv = __floats2half2_rn(acc[rr][j] * z, acc[rr][j + 1] * z);
            *(__half2*)&att[(size_t)(b0 + r) * DIN + h * DHEAD + e0 + j] = hv;
        }
    }
}

// ---------------- launch -----------------------------------------------------------
extern "C" void kernel_launch(void* const* d_in, const int* in_sizes, int n_in,
                              void* d_out, int out_size)
{
    const float* x    = (const float*)d_in[0];
    const float* Wq   = (const float*)d_in[1];
    const float* Wk   = (const float*)d_in[2];
    const float* Wv   = (const float*)d_in[3];
    const float* Wo   = (const float*)d_in[4];
    const float* bo   = (const float*)d_in[5];
    const float* Wg   = (const float*)d_in[6];
    const float* bg   = (const float*)d_in[7];
    const float* Wout = (const float*)d_in[8];
    const float* bout = (const float*)d_in[9];
    float* out = (float*)d_out;

    __half *xh_, *qkvh_, *att_, *opr_, *gt_;
    float  *op_;
    __half *wqkvT_, *woT_, *wgT_, *woutT_;
    cudaGetSymbolAddress((void**)&xh_,    g_xh);
    cudaGetSymbolAddress((void**)&qkvh_,  g_qkvh);
    cudaGetSymbolAddress((void**)&att_,   g_att);
    cudaGetSymbolAddress((void**)&op_,    g_op);
    cudaGetSymbolAddress((void**)&opr_,   g_opr);
    cudaGetSymbolAddress((void**)&gt_,    g_gt);
    cudaGetSymbolAddress((void**)&wqkvT_, g_wqkvT);
    cudaGetSymbolAddress((void**)&woT_,   g_woT);
    cudaGetSymbolAddress((void**)&wgT_,   g_wgT);
    cudaGetSymbolAddress((void**)&woutT_, g_woutT);

    cudaFuncSetAttribute(gemm_h<2>, cudaFuncAttributeMaxDynamicSharedMemorySize, GEMM_SMEM);
    cudaFuncSetAttribute(gemm_h<3>, cudaFuncAttributeMaxDynamicSharedMemorySize, GEMM_SMEM);
    cudaFuncSetAttribute(gemm_h<4>, cudaFuncAttributeMaxDynamicSharedMemorySize, GEMM_SMEM);
    cudaFuncSetAttribute(gemm_h<5>, cudaFuncAttributeMaxDynamicSharedMemorySize, GEMM_SMEM);

    const dim3 blk(256);
    const dim3 tblk(32, 8);

    // idx 0-3: prep; idx 4 = QKV GEMM (harness pre-launch shifts ncu -s 5 onto it)
    half_copy<<<(BATCH * DIN) / 1024, 256>>>((const float4*)x, (__half2*)xh_);        // 0
    transpose_half<<<dim3(DIN / 32, DIN / 32), tblk>>>(Wq, wqkvT_, DIN, DIN);         // 1
    transpose_half<<<dim3(DIN / 32, DIN / 32), tblk>>>(Wk, wqkvT_ + (size_t)DIN * DIN, DIN, DIN);      // 2
    transpose_half<<<dim3(DIN / 32, DIN / 32), tblk>>>(Wv, wqkvT_ + (size_t)2 * DIN * DIN, DIN, DIN);  // 3

    // 4: fused QKV GEMM -> half qkv, relu-feature on q,k columns
    gemm_h<5><<<dim3(NQKV / BN, BATCH / BM), blk, GEMM_SMEM>>>(
        xh_, xh_, DIN, DIN / BK, wqkvT_, DIN,
        nullptr, nullptr, nullptr, nullptr, qkvh_, NQKV);

    transpose_half<<<dim3(DIN / 32, DIN / 32), tblk>>>(Wo, woT_, DIN, DIN);           // 5
    transpose_half<<<dim3(DIN / 32, (2 * DIN) / 32), tblk>>>(Wg, wgT_, 2 * DIN, DIN); // 6
    transpose_half<<<dim3(DOUT / 32, DIN / 32), tblk>>>(Wout, woutT_, DIN, DOUT);     // 7

    // kv + ksum partials, then final reduce (deterministic)
    kv_reduce<<<dim3(HEADS, KV_SPLIT), 256>>>(qkvh_);
    kv_final<<<dim3((HEADS * DHEAD * DHEAD) / 256), 256>>>();

    // attention
    size_t attn_smem = (size_t)(128 * 132 * 2 + 256) * sizeof(float);
    cudaFuncSetAttribute(attn_kernel, cudaFuncAttributeMaxDynamicSharedMemorySize,
                         (int)attn_smem);
    attn_kernel<<<dim3(BATCH / 128, HEADS), 256, attn_smem>>>(qkvh_, att_);

    // out_proj = att @ Wo + bo (fp32 op + half opr)
    gemm_h<4><<<dim3(DIN / BN, BATCH / BM), blk, GEMM_SMEM>>>(
        att_, att_, DIN, DIN / BK, woT_, DIN,
        bo, nullptr, nullptr, op_, opr_, DIN);

    // gate GEMM over concat [opr | xh]; blend exact op / x -> half gt
    gemm_h<3><<<dim3(DIN / BN, BATCH / BM), blk, GEMM_SMEM>>>(
        opr_, xh_, DIN, (2 * DIN) / BK, wgT_, 2 * DIN,
        bg, op_, x, nullptr, gt_, DIN);

    // out = gt @ Wout + bout (fp32)
    gemm_h<2><<<dim3(DOUT / BN, BATCH / BM), blk, GEMM_SMEM>>>(
        gt_, gt_, DIN, DIN / BK, woutT_, DIN,
        bout, nullptr, nullptr, out, nullptr, DOUT);
}

// round 9
// speedup vs baseline: 4.4871x; 1.0111x over previous
#include <cuda_runtime.h>
#include <cuda_fp16.h>
#include <math.h>
#include <stdint.h>

// ---------------- problem dims (fixed) ----------------------------------------
#define BATCH 16384
#define DIN   2048
#define HEADS 16
#define DHEAD 128
#define DOUT  512
#define NQKV  (3 * DIN)                 // 6144

// ---------------- scratch (static device memory) ------------------------------
__device__ __half g_xh  [BATCH * DIN];            // half copy of x
__device__ __half g_qkvh[(size_t)BATCH * NQKV];   // q|k|v half, row stride 6144
__device__ __half g_att [BATCH * DIN];
__device__ __half g_opr [BATCH * DIN];            // half out_proj (blend + gate A)
__device__ __half g_gt  [BATCH * DIN];
__device__ float  g_kv  [HEADS * DHEAD * DHEAD];
__device__ float  g_ksum[HEADS * DHEAD];
#define KV_SPLIT 32
__device__ float g_kvpart[KV_SPLIT * HEADS * DHEAD * DHEAD];
__device__ float g_ksumpart[KV_SPLIT * DIN];
// transposed half weights [N][K]
__device__ __half g_wqkvT[NQKV * DIN];
__device__ __half g_woT  [DIN * DIN];
__device__ __half g_wgT  [DIN * 2 * DIN];
__device__ __half g_woutT[DOUT * DIN];

// ---------------- helpers -------------------------------------------------------
__device__ __forceinline__ uint32_t smem_u32(const void* p) {
    uint32_t a;
    asm("{ .reg .u64 t; cvta.to.shared.u64 t, %1; cvt.u32.u64 %0, t; }" : "=r"(a) : "l"(p));
    return a;
}
__device__ __forceinline__ void cp16(uint32_t dst, const void* src) {
    asm volatile("cp.async.cg.shared.global [%0], [%1], 16;" :: "r"(dst), "l"(src));
}
#define CP_COMMIT() asm volatile("cp.async.commit_group;" ::: "memory")
#define CP_WAIT(n)  asm volatile("cp.async.wait_group %0;" :: "n"(n) : "memory")

#define MMA_F16(d, A4, B2) \
    asm volatile("mma.sync.aligned.m16n8k16.row.col.f32.f16.f16.f32 " \
        "{%0,%1,%2,%3},{%4,%5,%6,%7},{%8,%9},{%0,%1,%2,%3};" \
        : "+f"((d)[0]), "+f"((d)[1]), "+f"((d)[2]), "+f"((d)[3]) \
        : "r"((A4)[0]), "r"((A4)[1]), "r"((A4)[2]), "r"((A4)[3]), \
          "r"((B2)[0]), "r"((B2)[1]))

#define LDSM_X4(r0, r1, r2, r3, addr) \
    asm volatile("ldmatrix.sync.aligned.m8n8.x4.shared.b16 {%0,%1,%2,%3}, [%4];" \
        : "=r"(r0), "=r"(r1), "=r"(r2), "=r"(r3) : "r"(addr))

// ---------------- GEMM config ----------------------------------------------------
// block 128x128, 8 warps (2M x 4N), warp tile 64x32, BK=64, 3 stages, 2 CTAs/SM.
#define BM 128
#define BN 128
#define BK 64
#define STAGES 3
#define ARS 72
#define BRS 72
#define ASTGH (BM * ARS)
#define BSTGH (BN * BRS)
#define GEMM_SMEM (STAGES * (ASTGH + BSTGH) * 2)   // 110592 bytes

// MODE 2: C=acc+bias (fp32 out)
// MODE 3: g=sigmoid(acc+bias); Ch=half(g*hep+(1-g)*hex)  (hep,hex half)
// MODE 4: Ch=half(acc+bias)
// MODE 5: QKV fused: col<2*DIN -> relu(acc)+1e-4, else acc; Ch=half
template <int MODE>
__global__ void __launch_bounds__(256, 2) gemm_h(
    const __half* __restrict__ A0, const __half* __restrict__ A1, int K0, int nkt,
    const __half* __restrict__ B, int ldb,
    const float* __restrict__ bias,
    const __half* __restrict__ hep, const __half* __restrict__ hex,
    float* __restrict__ C, __half* __restrict__ Ch, int N)
{
    extern __shared__ __half smh[];
    __half* As = smh;
    __half* Bs = smh + STAGES * ASTGH;
    const uint32_t asu = smem_u32(As);
    const uint32_t bsu = smem_u32(Bs);

    const int tid  = threadIdx.x;
    const int bm   = blockIdx.y * BM;
    const int bn   = blockIdx.x * BN;
    const int wid  = tid >> 5, lane = tid & 31;
    const int wm   = (wid >> 2) * 64;
    const int wn   = (wid & 3) * 32;

    const uint32_t a_lane = (uint32_t)(((lane & 15) * ARS + (lane >> 4) * 8) * 2);
    const uint32_t b_lane = (uint32_t)(((((lane >> 4) << 3) + (lane & 7)) * BRS
                                        + ((lane >> 3) & 1) * 8) * 2);

    float acc[4][4][4];
#pragma unroll
    for (int mt = 0; mt < 4; mt++)
#pragma unroll
        for (int nt = 0; nt < 4; nt++)
#pragma unroll
            for (int e = 0; e < 4; e++) acc[mt][nt][e] = 0.0f;

    auto issue = [&](int kt) {
        const int s = kt % STAGES;
        const int kbase = kt * BK;
        const __half* Aptr;
        int kc;
        if (kbase < K0) { Aptr = A0; kc = kbase; }
        else            { Aptr = A1; kc = kbase - K0; }
#pragma unroll
        for (int i = 0; i < 4; i++) {
            int idx = tid + i * 256;
            int r = idx >> 3, g = idx & 7;
            uint32_t dst = asu + (uint32_t)(s * ASTGH + r * ARS + g * 8) * 2u;
            cp16(dst, Aptr + (size_t)(bm + r) * DIN + kc + g * 8);
        }
#pragma unroll
        for (int i = 0; i < 4; i++) {
            int idx = tid + i * 256;
            int r = idx >> 3, g = idx & 7;
            uint32_t dst = bsu + (uint32_t)(s * BSTGH + r * BRS + g * 8) * 2u;
            cp16(dst, B + (size_t)(bn + r) * ldb + kbase + g * 8);
        }
    };

#pragma unroll
    for (int kt = 0; kt < STAGES - 1; kt++) {
        if (kt < nkt) issue(kt);
        CP_COMMIT();
    }

    for (int kt = 0; kt < nkt; kt++) {
        CP_WAIT(STAGES - 2);
        __syncthreads();

        if (kt + STAGES - 1 < nkt) issue(kt + STAGES - 1);
        CP_COMMIT();

        const int s = kt % STAGES;
        const uint32_t abase = asu + (uint32_t)(s * ASTGH + wm * ARS) * 2u + a_lane;
        const uint32_t bbase = bsu + (uint32_t)(s * BSTGH + wn * BRS) * 2u + b_lane;

#pragma unroll
        for (int kc = 0; kc < 4; kc++) {
            uint32_t a[4][4], b[4][2];
            const uint32_t ko = (uint32_t)(kc * 32);
#pragma unroll
            for (int mt = 0; mt < 4; mt++)
                LDSM_X4(a[mt][0], a[mt][1], a[mt][2], a[mt][3],
                        abase + (uint32_t)(mt * 16 * ARS * 2) + ko);
#pragma unroll
            for (int p = 0; p < 2; p++)
                LDSM_X4(b[2 * p][0], b[2 * p][1], b[2 * p + 1][0], b[2 * p + 1][1],
                        bbase + (uint32_t)(p * 16 * BRS * 2) + ko);
#pragma unroll
            for (int mt = 0; mt < 4; mt++)
#pragma unroll
                for (int nt = 0; nt < 4; nt++)
                    MMA_F16(acc[mt][nt], a[mt], b[nt]);
        }
    }

    // ---- epilogue ----
    const int lr = lane >> 2, lc = lane & 3;
#pragma unroll
    for (int mt = 0; mt < 4; mt++) {
#pragma unroll
        for (int nt = 0; nt < 4; nt++) {
#pragma unroll
            for (int h = 0; h < 2; h++) {
                const int gr = bm + wm + mt * 16 + lr + h * 8;
                const int gc = bn + wn + nt * 8 + 2 * lc;
                const size_t gi = (size_t)gr * N + gc;
                float v0 = acc[mt][nt][h * 2 + 0];
                float v1 = acc[mt][nt][h * 2 + 1];
                if constexpr (MODE == 2) {
                    v0 += bias[gc]; v1 += bias[gc + 1];
                    *(float2*)&C[gi] = make_float2(v0, v1);
                } else if constexpr (MODE == 3) {
                    v0 += bias[gc]; v1 += bias[gc + 1];
                    const float g0 = 1.f / (1.f + expf(-v0));
                    const float g1 = 1.f / (1.f + expf(-v1));
                    const float2 e2 = __half22float2(*(const __half2*)&hep[gi]);
                    const float2 x2 = __half22float2(*(const __half2*)&hex[gi]);
                    const float r0 = g0 * e2.x + (1.f - g0) * x2.x;
                    const float r1 = g1 * e2.y + (1.f - g1) * x2.y;
                    *(__half2*)&Ch[gi] = __floats2half2_rn(r0, r1);
                } else if constexpr (MODE == 4) {
                    v0 += bias[gc]; v1 += bias[gc + 1];
                    *(__half2*)&Ch[gi] = __floats2half2_rn(v0, v1);
                } else {  // MODE 5: fused QKV -> half
                    if (gc < 2 * DIN) {
                        v0 = fmaxf(v0, 0.f) + 1e-4f;
                        v1 = fmaxf(v1, 0.f) + 1e-4f;
                    }
                    *(__half2*)&Ch[gi] = __floats2half2_rn(v0, v1);
                }
            }
        }
    }
}

// ---------------- fp32 -> half copy ----------------------------------------------
__global__ void half_copy(const float4* __restrict__ s, __half2* __restrict__ d)
{
    const int i = blockIdx.x * 256 + threadIdx.x;
    float4 v = s[i];
    d[2 * i]     = __floats2half2_rn(v.x, v.y);
    d[2 * i + 1] = __floats2half2_rn(v.z, v.w);
}

// ---------------- transpose + convert: WT[n][k] = half(W[k][n]) -------------------
__global__ void transpose_half(const float* __restrict__ S, __half* __restrict__ D,
                               int K, int N)
{
    __shared__ float t[32][33];
    const int bn = blockIdx.x * 32, bk = blockIdx.y * 32;
    const int tx = threadIdx.x, ty = threadIdx.y;
#pragma unroll
    for (int i = 0; i < 32; i += 8)
        t[ty + i][tx] = S[(size_t)(bk + ty + i) * N + bn + tx];
    __syncthreads();
#pragma unroll
    for (int i = 0; i < 32; i += 8)
        D[(size_t)(bn + ty + i) * K + bk + tx] = __float2half_rn(t[tx][ty + i]);
}

// fused 3-way transpose for Wq/Wk/Wv (blockIdx.z selects source)
__global__ void transpose_qkv(const float* __restrict__ Wq, const float* __restrict__ Wk,
                              const float* __restrict__ Wv, __half* __restrict__ D)
{
    __shared__ float t[32][33];
    const float* S = (blockIdx.z == 0) ? Wq : (blockIdx.z == 1) ? Wk : Wv;
    __half* Dz = D + (size_t)blockIdx.z * DIN * DIN;
    const int bn = blockIdx.x * 32, bk = blockIdx.y * 32;
    const int tx = threadIdx.x, ty = threadIdx.y;
#pragma unroll
    for (int i = 0; i < 32; i += 8)
        t[ty + i][tx] = S[(size_t)(bk + ty + i) * DIN + bn + tx];
    __syncthreads();
#pragma unroll
    for (int i = 0; i < 32; i += 8)
        Dz[(size_t)(bn + ty + i) * DIN + bk + tx] = __float2half_rn(t[tx][ty + i]);
}

// ---------------- KV + ksum partial reduction (half in, fp32 accum) ----------------
__global__ void __launch_bounds__(256) kv_reduce(const __half* __restrict__ qkv)
{
    __shared__ __half ks[2][8][128];
    __shared__ __half vs[2][8][128];
    __shared__ float ksum_s[2][128];

    const int h = blockIdx.x;
    const int chunk = blockIdx.y;
    const int b0 = chunk * (BATCH / KV_SPLIT);     // 512 rows
    const int tid = threadIdx.x;
    const int d0 = (tid >> 4) * 8;
    const int e0 = (tid & 15) * 8;
    const int kc = tid & 127;
    const int rb = tid >> 7;

    const __half* kbase = qkv + 2048 + h * DHEAD;
    const __half* vbase = qkv + 4096 + h * DHEAD;

    const uint32_t ksu = smem_u32(&ks[0][0][0]);
    const uint32_t vsu = smem_u32(&vs[0][0][0]);

    auto load = [&](int buf, int bb) {
        const int t = tid & 127;
        const int r = t >> 4, g = t & 15;
        const size_t row = (size_t)(b0 + bb + r) * NQKV;
        if (tid < 128)
            cp16(ksu + (uint32_t)(buf * 2048 + r * 256 + g * 16), kbase + row + g * 8);
        else
            cp16(vsu + (uint32_t)(buf * 2048 + r * 256 + g * 16), vbase + row + g * 8);
    };

    float acc[8][8] = {};
    float ksacc = 0.0f;

    load(0, 0);
    CP_COMMIT();

    for (int bb = 0; bb < (BATCH / KV_SPLIT); bb += 8) {
        const int buf = (bb >> 3) & 1;
        if (bb + 8 < (BATCH / KV_SPLIT)) load(buf ^ 1, bb + 8);
        CP_COMMIT();
        CP_WAIT(1);
        __syncthreads();
#pragma unroll
        for (int r = 0; r < 8; r++) {
            float kr[8], vr[8];
#pragma unroll
            for (int i = 0; i < 8; i += 2) {
                float2 kf = __half22float2(*(const __half2*)&ks[buf][r][d0 + i]);
                float2 vf = __half22float2(*(const __half2*)&vs[buf][r][e0 + i]);
                kr[i] = kf.x; kr[i + 1] = kf.y;
                vr[i] = vf.x; vr[i + 1] = vf.y;
            }
#pragma unroll
            for (int i = 0; i < 8; i++)
#pragma unroll
                for (int j = 0; j < 8; j++) acc[i][j] += kr[i] * vr[j];
        }
#pragma unroll
        for (int rr = 0; rr < 4; rr++) ksacc += __half2float(ks[buf][rb * 4 + rr][kc]);
        __syncthreads();
    }

    float* dst = g_kvpart + (size_t)chunk * (HEADS * DHEAD * DHEAD) + h * DHEAD * DHEAD;
#pragma unroll
    for (int i = 0; i < 8; i++)
#pragma unroll
        for (int j = 0; j < 8; j++) dst[(d0 + i) * DHEAD + e0 + j] = acc[i][j];

    ksum_s[rb][kc] = ksacc;
    __syncthreads();
    if (tid < 128)
        g_ksumpart[chunk * DIN + h * DHEAD + tid] = ksum_s[0][tid] + ksum_s[1][tid];
}

// ---------------- final reductions (deterministic) ---------------------------------
__global__ void kv_final()
{
    int i = blockIdx.x * 256 + threadIdx.x;
    float s = 0.0f;
    for (int c = 0; c < KV_SPLIT; c++) s += g_kvpart[(size_t)c * (HEADS * DHEAD * DHEAD) + i];
    g_kv[i] = s;
    if (i < DIN) {
        float t = 0.0f;
        for (int c = 0; c < KV_SPLIT; c++) t += g_ksumpart[c * DIN + i];
        g_ksum[i] = t;
    }
}

// ---------------- attention (half q in; fp32 compute; half out) --------------------
__global__ void __launch_bounds__(256) attn_kernel(const __half* __restrict__ qkv,
                                                   __half* __restrict__ att)
{
    extern __shared__ float smx[];
    float* kv_s   = smx;
    float* q_s    = smx + 128 * 132;
    float* ksum_s = q_s + 128 * 132;
    float* z_s    = ksum_s + 128;

    const int h  = blockIdx.y;
    const int b0 = blockIdx.x * 128;
    const int tid = threadIdx.x;
    const __half* q = qkv + h * DHEAD;

    const float* kvh = g_kv + h * DHEAD * DHEAD;
    for (int i = tid; i < DHEAD * DHEAD; i += 256) {
        int d = i >> 7, e = i & 127;
        kv_s[d * 132 + e] = kvh[i];
    }
    for (int i = tid; i < 128 * 16; i += 256) {
        int r = i >> 4, g = i & 15;
        uint4 raw = *(const uint4*)(q + (size_t)(b0 + r) * NQKV + g * 8);
        const __half2* hp = (const __half2*)&raw;
        float* dstq = &q_s[r * 132 + g * 8];
#pragma unroll
        for (int j = 0; j < 4; j++) {
            float2 f = __half22float2(hp[j]);
            dstq[2 * j] = f.x; dstq[2 * j + 1] = f.y;
        }
    }
    if (tid < 128) ksum_s[tid] = g_ksum[h * DHEAD + tid];
    __syncthreads();

    {
        int r = tid >> 1, half_ = tid & 1;
        float s = 0.0f;
        int dbase = half_ * 64;
        for (int d = 0; d < 64; d++) s += q_s[r * 132 + dbase + d] * ksum_s[dbase + d];
        s += __shfl_xor_sync(0xffffffffu, s, 1);
        if (half_ == 0) z_s[r] = 1.0f / (s + 1e-6f);
    }
    __syncthreads();

    const int rg = tid >> 3;
    const int e0 = (tid & 7) * 16;
    float acc[4][16] = {};
    for (int d = 0; d < 128; d++) {
        float kvrow[16];
#pragma unroll
        for (int j = 0; j < 16; j += 4) {
            float4 f = *reinterpret_cast<float4*>(&kv_s[d * 132 + e0 + j]);
            kvrow[j] = f.x; kvrow[j + 1] = f.y; kvrow[j + 2] = f.z; kvrow[j + 3] = f.w;
        }
#pragma unroll
        for (int rr = 0; rr < 4; rr++) {
            float qd = q_s[(rg + rr * 32) * 132 + d];
#pragma unroll
            for (int j = 0; j < 16; j++) acc[rr][j] += qd * kvrow[j];
        }
    }
#pragma unroll
    for (int rr = 0; rr < 4; rr++) {
        int r = rg + rr * 32;
        float z = z_s[r];
#pragma unroll
        for (int j = 0; j < 16; j += 2) {
            __half2 hv = __floats2half2_rn(acc[rr][j] * z, acc[rr][j + 1] * z);
            *(__half2*)&att[(size_t)(b0 + r) * DIN + h * DHEAD + e0 + j] = hv;
        }
    }
}

// ---------------- launch -----------------------------------------------------------
extern "C" void kernel_launch(void* const* d_in, const int* in_sizes, int n_in,
                              void* d_out, int out_size)
{
    const float* x    = (const float*)d_in[0];
    const float* Wq   = (const float*)d_in[1];
    const float* Wk   = (const float*)d_in[2];
    const float* Wv   = (const float*)d_in[3];
    const float* Wo   = (const float*)d_in[4];
    const float* bo   = (const float*)d_in[5];
    const float* Wg   = (const float*)d_in[6];
    const float* bg   = (const float*)d_in[7];
    const float* Wout = (const float*)d_in[8];
    const float* bout = (const float*)d_in[9];
    float* out = (float*)d_out;

    __half *xh_, *qkvh_, *att_, *opr_, *gt_;
    __half *wqkvT_, *woT_, *wgT_, *woutT_;
    cudaGetSymbolAddress((void**)&xh_,    g_xh);
    cudaGetSymbolAddress((void**)&qkvh_,  g_qkvh);
    cudaGetSymbolAddress((void**)&att_,   g_att);
    cudaGetSymbolAddress((void**)&opr_,   g_opr);
    cudaGetSymbolAddress((void**)&gt_,    g_gt);
    cudaGetSymbolAddress((void**)&wqkvT_, g_wqkvT);
    cudaGetSymbolAddress((void**)&woT_,   g_woT);
    cudaGetSymbolAddress((void**)&wgT_,   g_wgT);
    cudaGetSymbolAddress((void**)&woutT_, g_woutT);

    cudaFuncSetAttribute(gemm_h<2>, cudaFuncAttributeMaxDynamicSharedMemorySize, GEMM_SMEM);
    cudaFuncSetAttribute(gemm_h<3>, cudaFuncAttributeMaxDynamicSharedMemorySize, GEMM_SMEM);
    cudaFuncSetAttribute(gemm_h<4>, cudaFuncAttributeMaxDynamicSharedMemorySize, GEMM_SMEM);
    cudaFuncSetAttribute(gemm_h<5>, cudaFuncAttributeMaxDynamicSharedMemorySize, GEMM_SMEM);

    const dim3 blk(256);
    const dim3 tblk(32, 8);

    // idx 0-2: prep; idx 3 = QKV GEMM (2 harness pre-launches + ncu -s 5 -> lands here)
    half_copy<<<(BATCH * DIN) / 1024, 256>>>((const float4*)x, (__half2*)xh_);        // 0
    transpose_qkv<<<dim3(DIN / 32, DIN / 32, 3), tblk>>>(Wq, Wk, Wv, wqkvT_);         // 1
    transpose_half<<<dim3(DIN / 32, DIN / 32), tblk>>>(Wo, woT_, DIN, DIN);           // 2

    // 3: fused QKV GEMM -> half qkv, relu-feature on q,k columns
    gemm_h<5><<<dim3(NQKV / BN, BATCH / BM), blk, GEMM_SMEM>>>(
        xh_, xh_, DIN, DIN / BK, wqkvT_, DIN,
        nullptr, nullptr, nullptr, nullptr, qkvh_, NQKV);

    transpose_half<<<dim3(DIN / 32, (2 * DIN) / 32), tblk>>>(Wg, wgT_, 2 * DIN, DIN); // 4
    transpose_half<<<dim3(DOUT / 32, DIN / 32), tblk>>>(Wout, woutT_, DIN, DOUT);     // 5

    // kv + ksum partials, then final reduce (deterministic)
    kv_reduce<<<dim3(HEADS, KV_SPLIT), 256>>>(qkvh_);
    kv_final<<<dim3((HEADS * DHEAD * DHEAD) / 256), 256>>>();

    // attention
    size_t attn_smem = (size_t)(128 * 132 * 2 + 256) * sizeof(float);
    cudaFuncSetAttribute(attn_kernel, cudaFuncAttributeMaxDynamicSharedMemorySize,
                         (int)attn_smem);
    attn_kernel<<<dim3(BATCH / 128, HEADS), 256, attn_smem>>>(qkvh_, att_);

    // out_proj = att @ Wo + bo -> half opr only
    gemm_h<4><<<dim3(DIN / BN, BATCH / BM), blk, GEMM_SMEM>>>(
        att_, att_, DIN, DIN / BK, woT_, DIN,
        bo, nullptr, nullptr, nullptr, opr_, DIN);

    // gate GEMM over concat [opr | xh]; blend half opr / xh -> half gt
    gemm_h<3><<<dim3(DIN / BN, BATCH / BM), blk, GEMM_SMEM>>>(
        opr_, xh_, DIN, (2 * DIN) / BK, wgT_, 2 * DIN,
        bg, opr_, xh_, nullptr, gt_, DIN);

    // out = gt @ Wout + bout (fp32)
    gemm_h<2><<<dim3(DOUT / BN, BATCH / BM), blk, GEMM_SMEM>>>(
        gt_, gt_, DIN, DIN / BK, woutT_, DIN,
        bout, nullptr, nullptr, out, nullptr, DOUT);
}

// round 10
// speedup vs baseline: 4.4997x; 1.0028x over previous
#include <cuda_runtime.h>
#include <cuda_fp16.h>
#include <math.h>
#include <stdint.h>

// ---------------- problem dims (fixed) ----------------------------------------
#define BATCH 16384
#define DIN   2048
#define HEADS 16
#define DHEAD 128
#define DOUT  512
#define NQKV  (3 * DIN)                 // 6144

// ---------------- scratch (static device memory) ------------------------------
__device__ __half g_xh  [BATCH * DIN];            // half copy of x
__device__ __half g_qkvh[(size_t)BATCH * NQKV];   // q|k|v half, row stride 6144
__device__ __half g_att [BATCH * DIN];
__device__ __half g_opr [BATCH * DIN];            // half out_proj (blend + gate A)
__device__ __half g_gt  [BATCH * DIN];
__device__ float  g_kv  [HEADS * DHEAD * DHEAD];
__device__ float  g_ksum[HEADS * DHEAD];
#define KV_SPLIT 32
__device__ float g_kvpart[KV_SPLIT * HEADS * DHEAD * DHEAD];
__device__ float g_ksumpart[KV_SPLIT * DIN];
// transposed half weights [N][K]
__device__ __half g_wqkvT[NQKV * DIN];
__device__ __half g_woT  [DIN * DIN];
__device__ __half g_wgT  [DIN * 2 * DIN];
__device__ __half g_woutT[DOUT * DIN];

// ---------------- helpers -------------------------------------------------------
__device__ __forceinline__ uint32_t smem_u32(const void* p) {
    uint32_t a;
    asm("{ .reg .u64 t; cvta.to.shared.u64 t, %1; cvt.u32.u64 %0, t; }" : "=r"(a) : "l"(p));
    return a;
}
__device__ __forceinline__ void cp16(uint32_t dst, const void* src) {
    asm volatile("cp.async.cg.shared.global [%0], [%1], 16;" :: "r"(dst), "l"(src));
}
#define CP_COMMIT() asm volatile("cp.async.commit_group;" ::: "memory")
#define CP_WAIT(n)  asm volatile("cp.async.wait_group %0;" :: "n"(n) : "memory")

#define MMA_F16(d, A4, B2) \
    asm volatile("mma.sync.aligned.m16n8k16.row.col.f32.f16.f16.f32 " \
        "{%0,%1,%2,%3},{%4,%5,%6,%7},{%8,%9},{%0,%1,%2,%3};" \
        : "+f"((d)[0]), "+f"((d)[1]), "+f"((d)[2]), "+f"((d)[3]) \
        : "r"((A4)[0]), "r"((A4)[1]), "r"((A4)[2]), "r"((A4)[3]), \
          "r"((B2)[0]), "r"((B2)[1]))

#define LDSM_X4(r0, r1, r2, r3, addr) \
    asm volatile("ldmatrix.sync.aligned.m8n8.x4.shared.b16 {%0,%1,%2,%3}, [%4];" \
        : "=r"(r0), "=r"(r1), "=r"(r2), "=r"(r3) : "r"(addr))

// ---------------- GEMM config ----------------------------------------------------
// block 128x128, 8 warps (2M x 4N), warp tile 64x32, BK=64, 3 stages, 2 CTAs/SM.
// Fragment double-buffering across kc chunks hides LDSM latency under MMAs.
#define BM 128
#define BN 128
#define BK 64
#define STAGES 3
#define ARS 72
#define BRS 72
#define ASTGH (BM * ARS)
#define BSTGH (BN * BRS)
#define GEMM_SMEM (STAGES * (ASTGH + BSTGH) * 2)   // 110592 bytes

// MODE 2: C=acc+bias (fp32 out)
// MODE 3: g=sigmoid(acc+bias); Ch=half(g*hep+(1-g)*hex)
// MODE 4: Ch=half(acc+bias)
// MODE 5: QKV fused: col<2*DIN -> relu(acc)+1e-4, else acc; Ch=half
template <int MODE>
__global__ void __launch_bounds__(256, 2) gemm_h(
    const __half* __restrict__ A0, const __half* __restrict__ A1, int K0, int nkt,
    const __half* __restrict__ B, int ldb,
    const float* __restrict__ bias,
    const __half* __restrict__ hep, const __half* __restrict__ hex,
    float* __restrict__ C, __half* __restrict__ Ch, int N)
{
    extern __shared__ __half smh[];
    __half* As = smh;
    __half* Bs = smh + STAGES * ASTGH;
    const uint32_t asu = smem_u32(As);
    const uint32_t bsu = smem_u32(Bs);

    const int tid  = threadIdx.x;
    const int bm   = blockIdx.y * BM;
    const int bn   = blockIdx.x * BN;
    const int wid  = tid >> 5, lane = tid & 31;
    const int wm   = (wid >> 2) * 64;
    const int wn   = (wid & 3) * 32;

    const uint32_t a_lane = (uint32_t)(((lane & 15) * ARS + (lane >> 4) * 8) * 2);
    const uint32_t b_lane = (uint32_t)(((((lane >> 4) << 3) + (lane & 7)) * BRS
                                        + ((lane >> 3) & 1) * 8) * 2);

    float acc[4][4][4];
#pragma unroll
    for (int mt = 0; mt < 4; mt++)
#pragma unroll
        for (int nt = 0; nt < 4; nt++)
#pragma unroll
            for (int e = 0; e < 4; e++) acc[mt][nt][e] = 0.0f;

    auto issue = [&](int kt) {
        const int s = kt % STAGES;
        const int kbase = kt * BK;
        const __half* Aptr;
        int kc;
        if (kbase < K0) { Aptr = A0; kc = kbase; }
        else            { Aptr = A1; kc = kbase - K0; }
#pragma unroll
        for (int i = 0; i < 4; i++) {
            int idx = tid + i * 256;
            int r = idx >> 3, g = idx & 7;
            uint32_t dst = asu + (uint32_t)(s * ASTGH + r * ARS + g * 8) * 2u;
            cp16(dst, Aptr + (size_t)(bm + r) * DIN + kc + g * 8);
        }
#pragma unroll
        for (int i = 0; i < 4; i++) {
            int idx = tid + i * 256;
            int r = idx >> 3, g = idx & 7;
            uint32_t dst = bsu + (uint32_t)(s * BSTGH + r * BRS + g * 8) * 2u;
            cp16(dst, B + (size_t)(bn + r) * ldb + kbase + g * 8);
        }
    };

#pragma unroll
    for (int kt = 0; kt < STAGES - 1; kt++) {
        if (kt < nkt) issue(kt);
        CP_COMMIT();
    }

    for (int kt = 0; kt < nkt; kt++) {
        CP_WAIT(STAGES - 2);
        __syncthreads();

        if (kt + STAGES - 1 < nkt) issue(kt + STAGES - 1);
        CP_COMMIT();

        const int s = kt % STAGES;
        const uint32_t abase = asu + (uint32_t)(s * ASTGH + wm * ARS) * 2u + a_lane;
        const uint32_t bbase = bsu + (uint32_t)(s * BSTGH + wn * BRS) * 2u + b_lane;

        uint32_t a[2][4][4], b[2][4][2];
        // preload kc=0 fragments
#pragma unroll
        for (int mt = 0; mt < 4; mt++)
            LDSM_X4(a[0][mt][0], a[0][mt][1], a[0][mt][2], a[0][mt][3],
                    abase + (uint32_t)(mt * 16 * ARS * 2));
#pragma unroll
        for (int p = 0; p < 2; p++)
            LDSM_X4(b[0][2 * p][0], b[0][2 * p][1], b[0][2 * p + 1][0], b[0][2 * p + 1][1],
                    bbase + (uint32_t)(p * 16 * BRS * 2));

#pragma unroll
        for (int kc = 0; kc < 4; kc++) {
            const int cur = kc & 1, nxt = cur ^ 1;
            if (kc < 3) {
                const uint32_t ko = (uint32_t)((kc + 1) * 32);
#pragma unroll
                for (int mt = 0; mt < 4; mt++)
                    LDSM_X4(a[nxt][mt][0], a[nxt][mt][1], a[nxt][mt][2], a[nxt][mt][3],
                            abase + (uint32_t)(mt * 16 * ARS * 2) + ko);
#pragma unroll
                for (int p = 0; p < 2; p++)
                    LDSM_X4(b[nxt][2 * p][0], b[nxt][2 * p][1],
                            b[nxt][2 * p + 1][0], b[nxt][2 * p + 1][1],
                            bbase + (uint32_t)(p * 16 * BRS * 2) + ko);
            }
#pragma unroll
            for (int mt = 0; mt < 4; mt++)
#pragma unroll
                for (int nt = 0; nt < 4; nt++)
                    MMA_F16(acc[mt][nt], a[cur][mt], b[cur][nt]);
        }
    }

    // ---- epilogue ----
    const int lr = lane >> 2, lc = lane & 3;
#pragma unroll
    for (int mt = 0; mt < 4; mt++) {
#pragma unroll
        for (int nt = 0; nt < 4; nt++) {
#pragma unroll
            for (int h = 0; h < 2; h++) {
                const int gr = bm + wm + mt * 16 + lr + h * 8;
                const int gc = bn + wn + nt * 8 + 2 * lc;
                const size_t gi = (size_t)gr * N + gc;
                float v0 = acc[mt][nt][h * 2 + 0];
                float v1 = acc[mt][nt][h * 2 + 1];
                if constexpr (MODE == 2) {
                    v0 += bias[gc]; v1 += bias[gc + 1];
                    *(float2*)&C[gi] = make_float2(v0, v1);
                } else if constexpr (MODE == 3) {
                    v0 += bias[gc]; v1 += bias[gc + 1];
                    const float g0 = 1.f / (1.f + expf(-v0));
                    const float g1 = 1.f / (1.f + expf(-v1));
                    const float2 e2 = __half22float2(*(const __half2*)&hep[gi]);
                    const float2 x2 = __half22float2(*(const __half2*)&hex[gi]);
                    const float r0 = g0 * e2.x + (1.f - g0) * x2.x;
                    const float r1 = g1 * e2.y + (1.f - g1) * x2.y;
                    *(__half2*)&Ch[gi] = __floats2half2_rn(r0, r1);
                } else if constexpr (MODE == 4) {
                    v0 += bias[gc]; v1 += bias[gc + 1];
                    *(__half2*)&Ch[gi] = __floats2half2_rn(v0, v1);
                } else {  // MODE 5: fused QKV -> half
                    if (gc < 2 * DIN) {
                        v0 = fmaxf(v0, 0.f) + 1e-4f;
                        v1 = fmaxf(v1, 0.f) + 1e-4f;
                    }
                    *(__half2*)&Ch[gi] = __floats2half2_rn(v0, v1);
                }
            }
        }
    }
}

// ---------------- fp32 -> half copy ----------------------------------------------
__global__ void half_copy(const float4* __restrict__ s, __half2* __restrict__ d)
{
    const int i = blockIdx.x * 256 + threadIdx.x;
    float4 v = s[i];
    d[2 * i]     = __floats2half2_rn(v.x, v.y);
    d[2 * i + 1] = __floats2half2_rn(v.z, v.w);
}

// ---------------- transpose + convert: WT[n][k] = half(W[k][n]) -------------------
__global__ void transpose_half(const float* __restrict__ S, __half* __restrict__ D,
                               int K, int N)
{
    __shared__ float t[32][33];
    const int bn = blockIdx.x * 32, bk = blockIdx.y * 32;
    const int tx = threadIdx.x, ty = threadIdx.y;
#pragma unroll
    for (int i = 0; i < 32; i += 8)
        t[ty + i][tx] = S[(size_t)(bk + ty + i) * N + bn + tx];
    __syncthreads();
#pragma unroll
    for (int i = 0; i < 32; i += 8)
        D[(size_t)(bn + ty + i) * K + bk + tx] = __float2half_rn(t[tx][ty + i]);
}

// fused 3-way transpose for Wq/Wk/Wv
__global__ void transpose_qkv(const float* __restrict__ Wq, const float* __restrict__ Wk,
                              const float* __restrict__ Wv, __half* __restrict__ D)
{
    __shared__ float t[32][33];
    const float* S = (blockIdx.z == 0) ? Wq : (blockIdx.z == 1) ? Wk : Wv;
    __half* Dz = D + (size_t)blockIdx.z * DIN * DIN;
    const int bn = blockIdx.x * 32, bk = blockIdx.y * 32;
    const int tx = threadIdx.x, ty = threadIdx.y;
#pragma unroll
    for (int i = 0; i < 32; i += 8)
        t[ty + i][tx] = S[(size_t)(bk + ty + i) * DIN + bn + tx];
    __syncthreads();
#pragma unroll
    for (int i = 0; i < 32; i += 8)
        Dz[(size_t)(bn + ty + i) * DIN + bk + tx] = __float2half_rn(t[tx][ty + i]);
}

// ---------------- KV + ksum partial reduction (half in, fp32 accum) ----------------
__global__ void __launch_bounds__(256) kv_reduce(const __half* __restrict__ qkv)
{
    __shared__ __half ks[2][8][128];
    __shared__ __half vs[2][8][128];
    __shared__ float ksum_s[2][128];

    const int h = blockIdx.x;
    const int chunk = blockIdx.y;
    const int b0 = chunk * (BATCH / KV_SPLIT);     // 512 rows
    const int tid = threadIdx.x;
    const int d0 = (tid >> 4) * 8;
    const int e0 = (tid & 15) * 8;
    const int kc = tid & 127;
    const int rb = tid >> 7;

    const __half* kbase = qkv + 2048 + h * DHEAD;
    const __half* vbase = qkv + 4096 + h * DHEAD;

    const uint32_t ksu = smem_u32(&ks[0][0][0]);
    const uint32_t vsu = smem_u32(&vs[0][0][0]);

    auto load = [&](int buf, int bb) {
        const int t = tid & 127;
        const int r = t >> 4, g = t & 15;
        const size_t row = (size_t)(b0 + bb + r) * NQKV;
        if (tid < 128)
            cp16(ksu + (uint32_t)(buf * 2048 + r * 256 + g * 16), kbase + row + g * 8);
        else
            cp16(vsu + (uint32_t)(buf * 2048 + r * 256 + g * 16), vbase + row + g * 8);
    };

    float acc[8][8] = {};
    float ksacc = 0.0f;

    load(0, 0);
    CP_COMMIT();

    for (int bb = 0; bb < (BATCH / KV_SPLIT); bb += 8) {
        const int buf = (bb >> 3) & 1;
        if (bb + 8 < (BATCH / KV_SPLIT)) load(buf ^ 1, bb + 8);
        CP_COMMIT();
        CP_WAIT(1);
        __syncthreads();
#pragma unroll
        for (int r = 0; r < 8; r++) {
            float kr[8], vr[8];
#pragma unroll
            for (int i = 0; i < 8; i += 2) {
                float2 kf = __half22float2(*(const __half2*)&ks[buf][r][d0 + i]);
                float2 vf = __half22float2(*(const __half2*)&vs[buf][r][e0 + i]);
                kr[i] = kf.x; kr[i + 1] = kf.y;
                vr[i] = vf.x; vr[i + 1] = vf.y;
            }
#pragma unroll
            for (int i = 0; i < 8; i++)
#pragma unroll
                for (int j = 0; j < 8; j++) acc[i][j] += kr[i] * vr[j];
        }
#pragma unroll
        for (int rr = 0; rr < 4; rr++) ksacc += __half2float(ks[buf][rb * 4 + rr][kc]);
        __syncthreads();
    }

    float* dst = g_kvpart + (size_t)chunk * (HEADS * DHEAD * DHEAD) + h * DHEAD * DHEAD;
#pragma unroll
    for (int i = 0; i < 8; i++)
#pragma unroll
        for (int j = 0; j < 8; j++) dst[(d0 + i) * DHEAD + e0 + j] = acc[i][j];

    ksum_s[rb][kc] = ksacc;
    __syncthreads();
    if (tid < 128)
        g_ksumpart[chunk * DIN + h * DHEAD + tid] = ksum_s[0][tid] + ksum_s[1][tid];
}

// ---------------- final reductions (deterministic) ---------------------------------
__global__ void kv_final()
{
    int i = blockIdx.x * 256 + threadIdx.x;
    float s = 0.0f;
    for (int c = 0; c < KV_SPLIT; c++) s += g_kvpart[(size_t)c * (HEADS * DHEAD * DHEAD) + i];
    g_kv[i] = s;
    if (i < DIN) {
        float t = 0.0f;
        for (int c = 0; c < KV_SPLIT; c++) t += g_ksumpart[c * DIN + i];
        g_ksum[i] = t;
    }
}

// ---------------- attention (half q in; fp32 compute; half out) --------------------
__global__ void __launch_bounds__(256) attn_kernel(const __half* __restrict__ qkv,
                                                   __half* __restrict__ att)
{
    extern __shared__ float smx[];
    float* kv_s   = smx;
    float* q_s    = smx + 128 * 132;
    float* ksum_s = q_s + 128 * 132;
    float* z_s    = ksum_s + 128;

    const int h  = blockIdx.y;
    const int b0 = blockIdx.x * 128;
    const int tid = threadIdx.x;
    const __half* q = qkv + h * DHEAD;

    const float* kvh = g_kv + h * DHEAD * DHEAD;
    for (int i = tid; i < DHEAD * DHEAD; i += 256) {
        int d = i >> 7, e = i & 127;
        kv_s[d * 132 + e] = kvh[i];
    }
    for (int i = tid; i < 128 * 16; i += 256) {
        int r = i >> 4, g = i & 15;
        uint4 raw = *(const uint4*)(q + (size_t)(b0 + r) * NQKV + g * 8);
        const __half2* hp = (const __half2*)&raw;
        float* dstq = &q_s[r * 132 + g * 8];
#pragma unroll
        for (int j = 0; j < 4; j++) {
            float2 f = __half22float2(hp[j]);
            dstq[2 * j] = f.x; dstq[2 * j + 1] = f.y;
        }
    }
    if (tid < 128) ksum_s[tid] = g_ksum[h * DHEAD + tid];
    __syncthreads();

    {
        int r = tid >> 1, half_ = tid & 1;
        float s = 0.0f;
        int dbase = half_ * 64;
        for (int d = 0; d < 64; d++) s += q_s[r * 132 + dbase + d] * ksum_s[dbase + d];
        s += __shfl_xor_sync(0xffffffffu, s, 1);
        if (half_ == 0) z_s[r] = 1.0f / (s + 1e-6f);
    }
    __syncthreads();

    const int rg = tid >> 3;
    const int e0 = (tid & 7) * 16;
    float acc[4][16] = {};
    for (int d = 0; d < 128; d++) {
        float kvrow[16];
#pragma unroll
        for (int j = 0; j < 16; j += 4) {
            float4 f = *reinterpret_cast<float4*>(&kv_s[d * 132 + e0 + j]);
            kvrow[j] = f.x; kvrow[j + 1] = f.y; kvrow[j + 2] = f.z; kvrow[j + 3] = f.w;
        }
#pragma unroll
        for (int rr = 0; rr < 4; rr++) {
            float qd = q_s[(rg + rr * 32) * 132 + d];
#pragma unroll
            for (int j = 0; j < 16; j++) acc[rr][j] += qd * kvrow[j];
        }
    }
#pragma unroll
    for (int rr = 0; rr < 4; rr++) {
        int r = rg + rr * 32;
        float z = z_s[r];
#pragma unroll
        for (int j = 0; j < 16; j += 2) {
            __half2 hv = __floats2half2_rn(acc[rr][j] * z, acc[rr][j + 1] * z);
            *(__half2*)&att[(size_t)(b0 + r) * DIN + h * DHEAD + e0 + j] = hv;
        }
    }
}

// ---------------- launch -----------------------------------------------------------
extern "C" void kernel_launch(void* const* d_in, const int* in_sizes, int n_in,
                              void* d_out, int out_size)
{
    const float* x    = (const float*)d_in[0];
    const float* Wq   = (const float*)d_in[1];
    const float* Wk   = (const float*)d_in[2];
    const float* Wv   = (const float*)d_in[3];
    const float* Wo   = (const float*)d_in[4];
    const float* bo   = (const float*)d_in[5];
    const float* Wg   = (const float*)d_in[6];
    const float* bg   = (const float*)d_in[7];
    const float* Wout = (const float*)d_in[8];
    const float* bout = (const float*)d_in[9];
    float* out = (float*)d_out;

    __half *xh_, *qkvh_, *att_, *opr_, *gt_;
    __half *wqkvT_, *woT_, *wgT_, *woutT_;
    cudaGetSymbolAddress((void**)&xh_,    g_xh);
    cudaGetSymbolAddress((void**)&qkvh_,  g_qkvh);
    cudaGetSymbolAddress((void**)&att_,   g_att);
    cudaGetSymbolAddress((void**)&opr_,   g_opr);
    cudaGetSymbolAddress((void**)&gt_,    g_gt);
    cudaGetSymbolAddress((void**)&wqkvT_, g_wqkvT);
    cudaGetSymbolAddress((void**)&woT_,   g_woT);
    cudaGetSymbolAddress((void**)&wgT_,   g_wgT);
    cudaGetSymbolAddress((void**)&woutT_, g_woutT);

    cudaFuncSetAttribute(gemm_h<2>, cudaFuncAttributeMaxDynamicSharedMemorySize, GEMM_SMEM);
    cudaFuncSetAttribute(gemm_h<3>, cudaFuncAttributeMaxDynamicSharedMemorySize, GEMM_SMEM);
    cudaFuncSetAttribute(gemm_h<4>, cudaFuncAttributeMaxDynamicSharedMemorySize, GEMM_SMEM);
    cudaFuncSetAttribute(gemm_h<5>, cudaFuncAttributeMaxDynamicSharedMemorySize, GEMM_SMEM);

    const dim3 blk(256);
    const dim3 tblk(32, 8);

    // idx 0-2: prep; idx 3 = QKV GEMM (ncu lands here)
    half_copy<<<(BATCH * DIN) / 1024, 256>>>((const float4*)x, (__half2*)xh_);        // 0
    transpose_qkv<<<dim3(DIN / 32, DIN / 32, 3), tblk>>>(Wq, Wk, Wv, wqkvT_);         // 1
    transpose_half<<<dim3(DIN / 32, DIN / 32), tblk>>>(Wo, woT_, DIN, DIN);           // 2

    // 3: fused QKV GEMM -> half qkv, relu-feature on q,k columns
    gemm_h<5><<<dim3(NQKV / BN, BATCH / BM), blk, GEMM_SMEM>>>(
        xh_, xh_, DIN, DIN / BK, wqkvT_, DIN,
        nullptr, nullptr, nullptr, nullptr, qkvh_, NQKV);

    transpose_half<<<dim3(DIN / 32, (2 * DIN) / 32), tblk>>>(Wg, wgT_, 2 * DIN, DIN); // 4
    transpose_half<<<dim3(DOUT / 32, DIN / 32), tblk>>>(Wout, woutT_, DIN, DOUT);     // 5

    // kv + ksum partials, then final reduce (deterministic)
    kv_reduce<<<dim3(HEADS, KV_SPLIT), 256>>>(qkvh_);
    kv_final<<<dim3((HEADS * DHEAD * DHEAD) / 256), 256>>>();

    // attention
    size_t attn_smem = (size_t)(128 * 132 * 2 + 256) * sizeof(float);
    cudaFuncSetAttribute(attn_kernel, cudaFuncAttributeMaxDynamicSharedMemorySize,
                         (int)attn_smem);
    attn_kernel<<<dim3(BATCH / 128, HEADS), 256, attn_smem>>>(qkvh_, att_);

    // out_proj = att @ Wo + bo -> half opr
    gemm_h<4><<<dim3(DIN / BN, BATCH / BM), blk, GEMM_SMEM>>>(
        att_, att_, DIN, DIN / BK, woT_, DIN,
        bo, nullptr, nullptr, nullptr, opr_, DIN);

    // gate GEMM over concat [opr | xh]; blend half opr / xh -> half gt
    gemm_h<3><<<dim3(DIN / BN, BATCH / BM), blk, GEMM_SMEM>>>(
        opr_, xh_, DIN, (2 * DIN) / BK, wgT_, 2 * DIN,
        bg, opr_, xh_, nullptr, gt_, DIN);

    // out = gt @ Wout + bout (fp32)
    gemm_h<2><<<dim3(DOUT / BN, BATCH / BM), blk, GEMM_SMEM>>>(
        gt_, gt_, DIN, DIN / BK, woutT_, DIN,
        bout, nullptr, nullptr, out, nullptr, DOUT);
}

// round 11
// speedup vs baseline: 5.4480x; 1.2108x over previous
#include <cuda_runtime.h>
#include <cuda_fp16.h>
#include <math.h>
#include <stdint.h>

// ---------------- problem dims (fixed) ----------------------------------------
#define BATCH 16384
#define DIN   2048
#define HEADS 16
#define DHEAD 128
#define DOUT  512
#define NQKV  (3 * DIN)                 // 6144

// ---------------- scratch (static device memory) ------------------------------
__device__ __half g_xh  [BATCH * DIN];            // half copy of x
__device__ __half g_qkvh[(size_t)BATCH * NQKV];   // q|k|v half, row stride 6144
__device__ __half g_att [BATCH * DIN];
__device__ __half g_opr [BATCH * DIN];            // half out_proj (blend + gate A)
__device__ __half g_gt  [BATCH * DIN];
__device__ __half g_kvT [HEADS * DHEAD * DHEAD];  // kv transposed [h][e][d], half
__device__ float  g_ksum[HEADS * DHEAD];
#define KV_SPLIT 32
__device__ float g_kvpart[KV_SPLIT * HEADS * DHEAD * DHEAD];   // [chunk][h][e][d]
__device__ float g_ksumpart[KV_SPLIT * DIN];
// transposed half weights [N][K]
__device__ __half g_wqkvT[NQKV * DIN];
__device__ __half g_woT  [DIN * DIN];
__device__ __half g_wgT  [DIN * 2 * DIN];
__device__ __half g_woutT[DOUT * DIN];

// ---------------- helpers -------------------------------------------------------
__device__ __forceinline__ uint32_t smem_u32(const void* p) {
    uint32_t a;
    asm("{ .reg .u64 t; cvta.to.shared.u64 t, %1; cvt.u32.u64 %0, t; }" : "=r"(a) : "l"(p));
    return a;
}
__device__ __forceinline__ void cp16(uint32_t dst, const void* src) {
    asm volatile("cp.async.cg.shared.global [%0], [%1], 16;" :: "r"(dst), "l"(src));
}
#define CP_COMMIT() asm volatile("cp.async.commit_group;" ::: "memory")
#define CP_WAIT(n)  asm volatile("cp.async.wait_group %0;" :: "n"(n) : "memory")

#define MMA_F16(d, A4, B2) \
    asm volatile("mma.sync.aligned.m16n8k16.row.col.f32.f16.f16.f32 " \
        "{%0,%1,%2,%3},{%4,%5,%6,%7},{%8,%9},{%0,%1,%2,%3};" \
        : "+f"((d)[0]), "+f"((d)[1]), "+f"((d)[2]), "+f"((d)[3]) \
        : "r"((A4)[0]), "r"((A4)[1]), "r"((A4)[2]), "r"((A4)[3]), \
          "r"((B2)[0]), "r"((B2)[1]))

#define LDSM_X4(r0, r1, r2, r3, addr) \
    asm volatile("ldmatrix.sync.aligned.m8n8.x4.shared.b16 {%0,%1,%2,%3}, [%4];" \
        : "=r"(r0), "=r"(r1), "=r"(r2), "=r"(r3) : "r"(addr))

// ---------------- GEMM config ----------------------------------------------------
#define BM 128
#define BN 128
#define BK 64
#define STAGES 3
#define ARS 72
#define BRS 72
#define ASTGH (BM * ARS)
#define BSTGH (BN * BRS)
#define GEMM_SMEM (STAGES * (ASTGH + BSTGH) * 2)   // 110592 bytes

// MODE 2: C=acc+bias (fp32 out)
// MODE 3: g=sigmoid(acc+bias); Ch=half(g*hep+(1-g)*hex)
// MODE 4: Ch=half(acc+bias)
// MODE 5: QKV fused: col<2*DIN -> relu(acc)+1e-4, else acc; Ch=half
template <int MODE>
__global__ void __launch_bounds__(256, 2) gemm_h(
    const __half* __restrict__ A0, const __half* __restrict__ A1, int K0, int nkt,
    const __half* __restrict__ B, int ldb,
    const float* __restrict__ bias,
    const __half* __restrict__ hep, const __half* __restrict__ hex,
    float* __restrict__ C, __half* __restrict__ Ch, int N)
{
    extern __shared__ __half smh[];
    __half* As = smh;
    __half* Bs = smh + STAGES * ASTGH;
    const uint32_t asu = smem_u32(As);
    const uint32_t bsu = smem_u32(Bs);

    const int tid  = threadIdx.x;
    const int bm   = blockIdx.y * BM;
    const int bn   = blockIdx.x * BN;
    const int wid  = tid >> 5, lane = tid & 31;
    const int wm   = (wid >> 2) * 64;
    const int wn   = (wid & 3) * 32;

    const uint32_t a_lane = (uint32_t)(((lane & 15) * ARS + (lane >> 4) * 8) * 2);
    const uint32_t b_lane = (uint32_t)(((((lane >> 4) << 3) + (lane & 7)) * BRS
                                        + ((lane >> 3) & 1) * 8) * 2);

    float acc[4][4][4];
#pragma unroll
    for (int mt = 0; mt < 4; mt++)
#pragma unroll
        for (int nt = 0; nt < 4; nt++)
#pragma unroll
            for (int e = 0; e < 4; e++) acc[mt][nt][e] = 0.0f;

    auto issue = [&](int kt) {
        const int s = kt % STAGES;
        const int kbase = kt * BK;
        const __half* Aptr;
        int kc;
        if (kbase < K0) { Aptr = A0; kc = kbase; }
        else            { Aptr = A1; kc = kbase - K0; }
#pragma unroll
        for (int i = 0; i < 4; i++) {
            int idx = tid + i * 256;
            int r = idx >> 3, g = idx & 7;
            uint32_t dst = asu + (uint32_t)(s * ASTGH + r * ARS + g * 8) * 2u;
            cp16(dst, Aptr + (size_t)(bm + r) * DIN + kc + g * 8);
        }
#pragma unroll
        for (int i = 0; i < 4; i++) {
            int idx = tid + i * 256;
            int r = idx >> 3, g = idx & 7;
            uint32_t dst = bsu + (uint32_t)(s * BSTGH + r * BRS + g * 8) * 2u;
            cp16(dst, B + (size_t)(bn + r) * ldb + kbase + g * 8);
        }
    };

#pragma unroll
    for (int kt = 0; kt < STAGES - 1; kt++) {
        if (kt < nkt) issue(kt);
        CP_COMMIT();
    }

    for (int kt = 0; kt < nkt; kt++) {
        CP_WAIT(STAGES - 2);
        __syncthreads();

        if (kt + STAGES - 1 < nkt) issue(kt + STAGES - 1);
        CP_COMMIT();

        const int s = kt % STAGES;
        const uint32_t abase = asu + (uint32_t)(s * ASTGH + wm * ARS) * 2u + a_lane;
        const uint32_t bbase = bsu + (uint32_t)(s * BSTGH + wn * BRS) * 2u + b_lane;

        uint32_t a[2][4][4], b[2][4][2];
#pragma unroll
        for (int mt = 0; mt < 4; mt++)
            LDSM_X4(a[0][mt][0], a[0][mt][1], a[0][mt][2], a[0][mt][3],
                    abase + (uint32_t)(mt * 16 * ARS * 2));
#pragma unroll
        for (int p = 0; p < 2; p++)
            LDSM_X4(b[0][2 * p][0], b[0][2 * p][1], b[0][2 * p + 1][0], b[0][2 * p + 1][1],
                    bbase + (uint32_t)(p * 16 * BRS * 2));

#pragma unroll
        for (int kc = 0; kc < 4; kc++) {
            const int cur = kc & 1, nxt = cur ^ 1;
            if (kc < 3) {
                const uint32_t ko = (uint32_t)((kc + 1) * 32);
#pragma unroll
                for (int mt = 0; mt < 4; mt++)
                    LDSM_X4(a[nxt][mt][0], a[nxt][mt][1], a[nxt][mt][2], a[nxt][mt][3],
                            abase + (uint32_t)(mt * 16 * ARS * 2) + ko);
#pragma unroll
                for (int p = 0; p < 2; p++)
                    LDSM_X4(b[nxt][2 * p][0], b[nxt][2 * p][1],
                            b[nxt][2 * p + 1][0], b[nxt][2 * p + 1][1],
                            bbase + (uint32_t)(p * 16 * BRS * 2) + ko);
            }
#pragma unroll
            for (int mt = 0; mt < 4; mt++)
#pragma unroll
                for (int nt = 0; nt < 4; nt++)
                    MMA_F16(acc[mt][nt], a[cur][mt], b[cur][nt]);
        }
    }

    // ---- epilogue ----
    const int lr = lane >> 2, lc = lane & 3;
#pragma unroll
    for (int mt = 0; mt < 4; mt++) {
#pragma unroll
        for (int nt = 0; nt < 4; nt++) {
#pragma unroll
            for (int h = 0; h < 2; h++) {
                const int gr = bm + wm + mt * 16 + lr + h * 8;
                const int gc = bn + wn + nt * 8 + 2 * lc;
                const size_t gi = (size_t)gr * N + gc;
                float v0 = acc[mt][nt][h * 2 + 0];
                float v1 = acc[mt][nt][h * 2 + 1];
                if constexpr (MODE == 2) {
                    v0 += bias[gc]; v1 += bias[gc + 1];
                    *(float2*)&C[gi] = make_float2(v0, v1);
                } else if constexpr (MODE == 3) {
                    v0 += bias[gc]; v1 += bias[gc + 1];
                    const float g0 = 1.f / (1.f + expf(-v0));
                    const float g1 = 1.f / (1.f + expf(-v1));
                    const float2 e2 = __half22float2(*(const __half2*)&hep[gi]);
                    const float2 x2 = __half22float2(*(const __half2*)&hex[gi]);
                    const float r0 = g0 * e2.x + (1.f - g0) * x2.x;
                    const float r1 = g1 * e2.y + (1.f - g1) * x2.y;
                    *(__half2*)&Ch[gi] = __floats2half2_rn(r0, r1);
                } else if constexpr (MODE == 4) {
                    v0 += bias[gc]; v1 += bias[gc + 1];
                    *(__half2*)&Ch[gi] = __floats2half2_rn(v0, v1);
                } else {  // MODE 5: fused QKV -> half
                    if (gc < 2 * DIN) {
                        v0 = fmaxf(v0, 0.f) + 1e-4f;
                        v1 = fmaxf(v1, 0.f) + 1e-4f;
                    }
                    *(__half2*)&Ch[gi] = __floats2half2_rn(v0, v1);
                }
            }
        }
    }
}

// ---------------- fp32 -> half copy ----------------------------------------------
__global__ void half_copy(const float4* __restrict__ s, __half2* __restrict__ d)
{
    const int i = blockIdx.x * 256 + threadIdx.x;
    float4 v = s[i];
    d[2 * i]     = __floats2half2_rn(v.x, v.y);
    d[2 * i + 1] = __floats2half2_rn(v.z, v.w);
}

// ---------------- transpose + convert: WT[n][k] = half(W[k][n]) -------------------
__global__ void transpose_half(const float* __restrict__ S, __half* __restrict__ D,
                               int K, int N)
{
    __shared__ float t[32][33];
    const int bn = blockIdx.x * 32, bk = blockIdx.y * 32;
    const int tx = threadIdx.x, ty = threadIdx.y;
#pragma unroll
    for (int i = 0; i < 32; i += 8)
        t[ty + i][tx] = S[(size_t)(bk + ty + i) * N + bn + tx];
    __syncthreads();
#pragma unroll
    for (int i = 0; i < 32; i += 8)
        D[(size_t)(bn + ty + i) * K + bk + tx] = __float2half_rn(t[tx][ty + i]);
}

// fused 3-way transpose for Wq/Wk/Wv
__global__ void transpose_qkv(const float* __restrict__ Wq, const float* __restrict__ Wk,
                              const float* __restrict__ Wv, __half* __restrict__ D)
{
    __shared__ float t[32][33];
    const float* S = (blockIdx.z == 0) ? Wq : (blockIdx.z == 1) ? Wk : Wv;
    __half* Dz = D + (size_t)blockIdx.z * DIN * DIN;
    const int bn = blockIdx.x * 32, bk = blockIdx.y * 32;
    const int tx = threadIdx.x, ty = threadIdx.y;
#pragma unroll
    for (int i = 0; i < 32; i += 8)
        t[ty + i][tx] = S[(size_t)(bk + ty + i) * DIN + bn + tx];
    __syncthreads();
#pragma unroll
    for (int i = 0; i < 32; i += 8)
        Dz[(size_t)(bn + ty + i) * DIN + bk + tx] = __float2half_rn(t[tx][ty + i]);
}

// ---------------- KV + ksum partial reduction (half in, fp32 accum) ----------------
// NOTE: stores kv partials TRANSPOSED: kvpart[chunk][h][e][d]
__global__ void __launch_bounds__(256) kv_reduce(const __half* __restrict__ qkv)
{
    __shared__ __half ks[2][8][128];
    __shared__ __half vs[2][8][128];
    __shared__ float ksum_s[2][128];

    const int h = blockIdx.x;
    const int chunk = blockIdx.y;
    const int b0 = chunk * (BATCH / KV_SPLIT);     // 512 rows
    const int tid = threadIdx.x;
    const int d0 = (tid >> 4) * 8;
    const int e0 = (tid & 15) * 8;
    const int kc = tid & 127;
    const int rb = tid >> 7;

    const __half* kbase = qkv + 2048 + h * DHEAD;
    const __half* vbase = qkv + 4096 + h * DHEAD;

    const uint32_t ksu = smem_u32(&ks[0][0][0]);
    const uint32_t vsu = smem_u32(&vs[0][0][0]);

    auto load = [&](int buf, int bb) {
        const int t = tid & 127;
        const int r = t >> 4, g = t & 15;
        const size_t row = (size_t)(b0 + bb + r) * NQKV;
        if (tid < 128)
            cp16(ksu + (uint32_t)(buf * 2048 + r * 256 + g * 16), kbase + row + g * 8);
        else
            cp16(vsu + (uint32_t)(buf * 2048 + r * 256 + g * 16), vbase + row + g * 8);
    };

    float acc[8][8] = {};
    float ksacc = 0.0f;

    load(0, 0);
    CP_COMMIT();

    for (int bb = 0; bb < (BATCH / KV_SPLIT); bb += 8) {
        const int buf = (bb >> 3) & 1;
        if (bb + 8 < (BATCH / KV_SPLIT)) load(buf ^ 1, bb + 8);
        CP_COMMIT();
        CP_WAIT(1);
        __syncthreads();
#pragma unroll
        for (int r = 0; r < 8; r++) {
            float kr[8], vr[8];
#pragma unroll
            for (int i = 0; i < 8; i += 2) {
                float2 kf = __half22float2(*(const __half2*)&ks[buf][r][d0 + i]);
                float2 vf = __half22float2(*(const __half2*)&vs[buf][r][e0 + i]);
                kr[i] = kf.x; kr[i + 1] = kf.y;
                vr[i] = vf.x; vr[i + 1] = vf.y;
            }
#pragma unroll
            for (int i = 0; i < 8; i++)
#pragma unroll
                for (int j = 0; j < 8; j++) acc[i][j] += kr[i] * vr[j];
        }
#pragma unroll
        for (int rr = 0; rr < 4; rr++) ksacc += __half2float(ks[buf][rb * 4 + rr][kc]);
        __syncthreads();
    }

    // transposed store: [e][d]
    float* dst = g_kvpart + (size_t)chunk * (HEADS * DHEAD * DHEAD) + h * DHEAD * DHEAD;
#pragma unroll
    for (int i = 0; i < 8; i++)
#pragma unroll
        for (int j = 0; j < 8; j++) dst[(e0 + j) * DHEAD + d0 + i] = acc[i][j];

    ksum_s[rb][kc] = ksacc;
    __syncthreads();
    if (tid < 128)
        g_ksumpart[chunk * DIN + h * DHEAD + tid] = ksum_s[0][tid] + ksum_s[1][tid];
}

// ---------------- final reductions: kvT (half) + ksum (fp32) -----------------------
__global__ void kv_final()
{
    int i = blockIdx.x * 256 + threadIdx.x;
    float s = 0.0f;
    for (int c = 0; c < KV_SPLIT; c++) s += g_kvpart[(size_t)c * (HEADS * DHEAD * DHEAD) + i];
    g_kvT[i] = __float2half_rn(s);
    if (i < DIN) {
        float t = 0.0f;
        for (int c = 0; c < KV_SPLIT; c++) t += g_ksumpart[c * DIN + i];
        g_ksum[i] = t;
    }
}

// ---------------- attention via HMMA: att = (q @ kvT^T) * z ------------------------
// block 256 thr, 8 warps (2M x 4N), warp tile 64x32; K=128 = 2 resident k-tiles.
#define ATT_SMEM (2 * 128 * 72 * 2 * 2 + 1024)
__global__ void __launch_bounds__(256) attn_mma(const __half* __restrict__ qkv,
                                                __half* __restrict__ att)
{
    extern __shared__ char smc[];
    __half* As = (__half*)smc;                         // [2][128*72]
    __half* Bs = (__half*)(smc + 2 * 128 * 72 * 2);    // [2][128*72]
    float* ksum_s = (float*)(smc + 4 * 128 * 72 * 2);  // 128
    float* z_s    = ksum_s + 128;                      // 128

    const int h  = blockIdx.y;
    const int b0 = blockIdx.x * 128;
    const int tid = threadIdx.x;
    const int wid = tid >> 5, lane = tid & 31;
    const int wm = (wid >> 2) * 64, wn = (wid & 3) * 32;
    const uint32_t asu = smem_u32(As), bsu = smem_u32(Bs);

    const __half* qb  = qkv + h * DHEAD;
    const __half* kvb = g_kvT + (size_t)h * DHEAD * DHEAD;

    // load both k-tiles of q (A) and kvT (B)
#pragma unroll
    for (int kt = 0; kt < 2; kt++) {
#pragma unroll
        for (int i = 0; i < 4; i++) {
            int idx = tid + i * 256;
            int r = idx >> 3, g = idx & 7;
            cp16(asu + (uint32_t)(kt * 128 * 72 + r * 72 + g * 8) * 2u,
                 qb + (size_t)(b0 + r) * NQKV + kt * 64 + g * 8);
            cp16(bsu + (uint32_t)(kt * 128 * 72 + r * 72 + g * 8) * 2u,
                 kvb + r * DHEAD + kt * 64 + g * 8);
        }
    }
    CP_COMMIT();
    if (tid < 128) ksum_s[tid] = g_ksum[h * DHEAD + tid];
    CP_WAIT(0);
    __syncthreads();

    // z per row (2 threads/row; thread half hf covers k-tile hf)
    {
        int r = tid >> 1, hf = tid & 1;
        const __half* qrow = As + hf * 128 * 72 + r * 72;
        float s = 0.0f;
        for (int d = 0; d < 64; d++) s += __half2float(qrow[d]) * ksum_s[hf * 64 + d];
        s += __shfl_xor_sync(0xffffffffu, s, 1);
        if (hf == 0) z_s[r] = 1.0f / (s + 1e-6f);
    }
    __syncthreads();

    const uint32_t a_lane = (uint32_t)(((lane & 15) * 72 + (lane >> 4) * 8) * 2);
    const uint32_t b_lane = (uint32_t)(((((lane >> 4) << 3) + (lane & 7)) * 72
                                        + ((lane >> 3) & 1) * 8) * 2);

    float acc[4][4][4];
#pragma unroll
    for (int mt = 0; mt < 4; mt++)
#pragma unroll
        for (int nt = 0; nt < 4; nt++)
#pragma unroll
            for (int e = 0; e < 4; e++) acc[mt][nt][e] = 0.0f;

#pragma unroll
    for (int kt = 0; kt < 2; kt++) {
        const uint32_t abase = asu + (uint32_t)(kt * 128 * 72 + wm * 72) * 2u + a_lane;
        const uint32_t bbase = bsu + (uint32_t)(kt * 128 * 72 + wn * 72) * 2u + b_lane;
#pragma unroll
        for (int kc = 0; kc < 4; kc++) {
            uint32_t a[4][4], b[4][2];
            const uint32_t ko = (uint32_t)(kc * 32);
#pragma unroll
            for (int mt = 0; mt < 4; mt++)
                LDSM_X4(a[mt][0], a[mt][1], a[mt][2], a[mt][3],
                        abase + (uint32_t)(mt * 16 * 72 * 2) + ko);
#pragma unroll
            for (int p = 0; p < 2; p++)
                LDSM_X4(b[2 * p][0], b[2 * p][1], b[2 * p + 1][0], b[2 * p + 1][1],
                        bbase + (uint32_t)(p * 16 * 72 * 2) + ko);
#pragma unroll
            for (int mt = 0; mt < 4; mt++)
#pragma unroll
                for (int nt = 0; nt < 4; nt++)
                    MMA_F16(acc[mt][nt], a[mt], b[nt]);
        }
    }

    // epilogue: scale by z, write half
    const int lr = lane >> 2, lc = lane & 3;
#pragma unroll
    for (int mt = 0; mt < 4; mt++) {
#pragma unroll
        for (int nt = 0; nt < 4; nt++) {
#pragma unroll
            for (int hh = 0; hh < 2; hh++) {
                const int rl = wm + mt * 16 + lr + hh * 8;      // local row
                const int gc = wn + nt * 8 + 2 * lc;            // e column
                const float z = z_s[rl];
                const float v0 = acc[mt][nt][hh * 2 + 0] * z;
                const float v1 = acc[mt][nt][hh * 2 + 1] * z;
                *(__half2*)&att[(size_t)(b0 + rl) * DIN + h * DHEAD + gc] =
                    __floats2half2_rn(v0, v1);
            }
        }
    }
}

// ---------------- launch -----------------------------------------------------------
extern "C" void kernel_launch(void* const* d_in, const int* in_sizes, int n_in,
                              void* d_out, int out_size)
{
    const float* x    = (const float*)d_in[0];
    const float* Wq   = (const float*)d_in[1];
    const float* Wk   = (const float*)d_in[2];
    const float* Wv   = (const float*)d_in[3];
    const float* Wo   = (const float*)d_in[4];
    const float* bo   = (const float*)d_in[5];
    const float* Wg   = (const float*)d_in[6];
    const float* bg   = (const float*)d_in[7];
    const float* Wout = (const float*)d_in[8];
    const float* bout = (const float*)d_in[9];
    float* out = (float*)d_out;

    __half *xh_, *qkvh_, *att_, *opr_, *gt_;
    __half *wqkvT_, *woT_, *wgT_, *woutT_;
    cudaGetSymbolAddress((void**)&xh_,    g_xh);
    cudaGetSymbolAddress((void**)&qkvh_,  g_qkvh);
    cudaGetSymbolAddress((void**)&att_,   g_att);
    cudaGetSymbolAddress((void**)&opr_,   g_opr);
    cudaGetSymbolAddress((void**)&gt_,    g_gt);
    cudaGetSymbolAddress((void**)&wqkvT_, g_wqkvT);
    cudaGetSymbolAddress((void**)&woT_,   g_woT);
    cudaGetSymbolAddress((void**)&wgT_,   g_wgT);
    cudaGetSymbolAddress((void**)&woutT_, g_woutT);

    cudaFuncSetAttribute(gemm_h<2>, cudaFuncAttributeMaxDynamicSharedMemorySize, GEMM_SMEM);
    cudaFuncSetAttribute(gemm_h<3>, cudaFuncAttributeMaxDynamicSharedMemorySize, GEMM_SMEM);
    cudaFuncSetAttribute(gemm_h<4>, cudaFuncAttributeMaxDynamicSharedMemorySize, GEMM_SMEM);
    cudaFuncSetAttribute(gemm_h<5>, cudaFuncAttributeMaxDynamicSharedMemorySize, GEMM_SMEM);
    cudaFuncSetAttribute(attn_mma, cudaFuncAttributeMaxDynamicSharedMemorySize, ATT_SMEM);

    const dim3 blk(256);
    const dim3 tblk(32, 8);

    // idx 0-2: prep; idx 3 = QKV GEMM (ncu lands here)
    half_copy<<<(BATCH * DIN) / 1024, 256>>>((const float4*)x, (__half2*)xh_);        // 0
    transpose_qkv<<<dim3(DIN / 32, DIN / 32, 3), tblk>>>(Wq, Wk, Wv, wqkvT_);         // 1
    transpose_half<<<dim3(DIN / 32, DIN / 32), tblk>>>(Wo, woT_, DIN, DIN);           // 2

    // 3: fused QKV GEMM -> half qkv, relu-feature on q,k columns
    gemm_h<5><<<dim3(NQKV / BN, BATCH / BM), blk, GEMM_SMEM>>>(
        xh_, xh_, DIN, DIN / BK, wqkvT_, DIN,
        nullptr, nullptr, nullptr, nullptr, qkvh_, NQKV);

    transpose_half<<<dim3(DIN / 32, (2 * DIN) / 32), tblk>>>(Wg, wgT_, 2 * DIN, DIN); // 4
    transpose_half<<<dim3(DOUT / 32, DIN / 32), tblk>>>(Wout, woutT_, DIN, DOUT);     // 5

    // kv + ksum partials (transposed), then final reduce -> half kvT + fp32 ksum
    kv_reduce<<<dim3(HEADS, KV_SPLIT), 256>>>(qkvh_);
    kv_final<<<dim3((HEADS * DHEAD * DHEAD) / 256), 256>>>();

    // attention via HMMA
    attn_mma<<<dim3(BATCH / 128, HEADS), 256, ATT_SMEM>>>(qkvh_, att_);

    // out_proj = att @ Wo + bo -> half opr
    gemm_h<4><<<dim3(DIN / BN, BATCH / BM), blk, GEMM_SMEM>>>(
        att_, att_, DIN, DIN / BK, woT_, DIN,
        bo, nullptr, nullptr, nullptr, opr_, DIN);

    // gate GEMM over concat [opr | xh]; blend half opr / xh -> half gt
    gemm_h<3><<<dim3(DIN / BN, BATCH / BM), blk, GEMM_SMEM>>>(
        opr_, xh_, DIN, (2 * DIN) / BK, wgT_, 2 * DIN,
        bg, opr_, xh_, nullptr, gt_, DIN);

    // out = gt @ Wout + bout (fp32)
    gemm_h<2><<<dim3(DOUT / BN, BATCH / BM), blk, GEMM_SMEM>>>(
        gt_, gt_, DIN, DIN / BK, woutT_, DIN,
        bout, nullptr, nullptr, out, nullptr, DOUT);
}